// round 1
// baseline (speedup 1.0000x reference)
#include <cuda_runtime.h>
#include <math_constants.h>

#define NN 10000
#define EE 160000
#define MULT 16
#define NL 2
#define DIM 4
#define EDIM 32
#define HID 128
#define RANK 8
#define NH 4
#define TE 32          // edges per block
#define KC 16          // k-chunk of GEMM

// ---------------- scratch (static device arrays; no allocation) ----------------
__device__ float g_q[NN * 64];
__device__ float g_v[EE * 64];
__device__ float g_scores[EE * NH];
__device__ float g_ex[EE * NH];
__device__ float g_m[NN * NH];
__device__ float g_den[NN * NH];

__device__ __forceinline__ void atomicMaxFloat(float* addr, float val) {
    if (val >= 0.f) atomicMax((int*)addr, __float_as_int(val));
    else            atomicMin((unsigned int*)addr, __float_as_uint(val));
}

// ---------------- kernel 1: Q equivariant linear + init ----------------
__global__ void qinit_kernel(const float* __restrict__ f,
                             const float* __restrict__ qw,
                             const float* __restrict__ qb,
                             float* __restrict__ dout) {
    int p = blockIdx.x * blockDim.x + threadIdx.x;
    if (p < NN * 64) {
        int n = p >> 6, j = p & 63;
        int o = j >> 2, d = j & 3;
        int l = (d == 0) ? 0 : 1;                    // IDX = [0,1,1,1]
        float acc = (d == 0) ? qb[o] : 0.f;
        const float* wrow = qw + (l * 16 + o) * 16;  // q_w.reshape(2,16,16)[l][o][:]
        const float* frow = f + n * 64 + d;
#pragma unroll
        for (int m = 0; m < 16; m++) acc += wrow[m] * frow[m * 4];
        g_q[p] = acc;
        dout[p] = 0.f;
    }
    if (p < NN * NH) { g_m[p] = -CUDART_INF_F; g_den[p] = 0.f; }
}

// ---------------- kernel 2: fused conv (K or V via blockIdx.y) ----------------
// smem layout (floats)
#define OFF_W   0        // 16*512 = 8192   (also stages w1 32*128=4096 in phase A)
#define OFF_H   8192     // 128*32 = 4096   h[j][e]
#define OFF_EF  12288    // 32*33  = 1056
#define OFF_T   13344    // 32*33  = 1056
#define OFF_RT  14400    // 32*8   = 256
#define OFF_T2  14656    // 32*32  = 1024
#define OFF_OUT 15680    // 32*64  = 2048
#define OFF_BL  17728    // 256
#define OFF_BR  17984    // 256
#define SMEM_FLOATS 18240
#define SMEM_BYTES (SMEM_FLOATS * 4)

__global__ void __launch_bounds__(256, 2)
conv_kernel(const float* __restrict__ basis1,   // (E,4,2)
            const float* __restrict__ basis2,   // (E,2,4)
            const float* __restrict__ ef,       // (E,32)
            const float* __restrict__ f,        // (N,16,4)
            const int*   __restrict__ src,
            const int*   __restrict__ dst,
            const float* __restrict__ k_w1, const float* __restrict__ k_b1,
            const float* __restrict__ k_wl, const float* __restrict__ k_bl,
            const float* __restrict__ k_wr, const float* __restrict__ k_br,
            const float* __restrict__ v_w1, const float* __restrict__ v_b1,
            const float* __restrict__ v_wl, const float* __restrict__ v_bl,
            const float* __restrict__ v_wr, const float* __restrict__ v_br) {
    extern __shared__ float sm[];
    float* sh_w   = sm + OFF_W;
    float* sh_h   = sm + OFF_H;
    float* sh_ef  = sm + OFF_EF;
    float* sh_t   = sm + OFF_T;
    float* sh_rt  = sm + OFF_RT;
    float* sh_t2  = sm + OFF_T2;
    float* sh_out = sm + OFF_OUT;
    float* sh_bl  = sm + OFF_BL;
    float* sh_br  = sm + OFF_BR;

    const int tid = threadIdx.x;
    const int e0 = blockIdx.x * TE;
    const int conv = blockIdx.y;                // 0 = K, 1 = V

    const float* w1 = conv ? v_w1 : k_w1;
    const float* hb = conv ? v_b1 : k_b1;
    const float* wl = conv ? v_wl : k_wl;
    const float* bl = conv ? v_bl : k_bl;
    const float* wr = conv ? v_wr : k_wr;
    const float* br = conv ? v_br : k_br;

    // ---- phase A: stage w1 (into sh_w), ef tile, biases; zero rt ----
#pragma unroll
    for (int r = 0; r < 16; r++) sh_w[r * 256 + tid] = w1[r * 256 + tid];       // 4096
#pragma unroll
    for (int r = 0; r < 4; r++) {
        int p = r * 256 + tid;                  // 0..1023
        int e = p >> 5, i = p & 31;
        sh_ef[e * 33 + i] = ef[(e0 + e) * EDIM + i];
    }
    sh_bl[tid & 255] = bl[tid];                 // 256 each
    sh_br[tid] = br[tid];
    sh_rt[tid & 255] = 0.f;
    if (tid < 256) {}                           // (all 256 threads covered above)

    // ---- phase B: t[e][c] = sum_d f[src][m][d]*basis1[e][d][l], c=m*2+l ----
#pragma unroll
    for (int r = 0; r < 4; r++) {
        int p = r * 256 + tid;                  // 0..1023
        int e = p >> 5, c = p & 31;
        int m = c >> 1, l = c & 1;
        int sn = __ldg(&src[e0 + e]);
        const float* fr = f + sn * 64 + m * 4;
        const float* b1r = basis1 + (e0 + e) * 8 + l;
        float a = 0.f;
#pragma unroll
        for (int d = 0; d < 4; d++) a += fr[d] * b1r[d * 2];
        sh_t[e * 33 + c] = a;
    }
    __syncthreads();

    // ---- phase A2: h[j][e] = gelu(ef . w1[:,j] + hb[j]) ----
#pragma unroll
    for (int rep = 0; rep < 16; rep++) {
        int p = rep * 256 + tid;                // 0..4095
        int e = p & 31, j = p >> 5;
        float a = __ldg(&hb[j]);
#pragma unroll
        for (int i = 0; i < 32; i++) a += sh_ef[e * 33 + i] * sh_w[i * 128 + j];
        sh_h[j * 32 + e] = a * normcdff(a);     // exact gelu
    }

    // ---- phase C: GEMM  C[32e x 512o] = h(32x128) @ [wl|wr](128x512) ----
    const int eg = tid >> 6;                    // 0..3  (8 edges each)
    const int og = tid & 63;                    // 0..63 (8 outputs each)
    float acc[8][8];
#pragma unroll
    for (int a = 0; a < 8; a++)
#pragma unroll
        for (int b = 0; b < 8; b++) acc[a][b] = 0.f;

    for (int k0 = 0; k0 < HID; k0 += KC) {
        __syncthreads();                        // protects sh_w reuse
#pragma unroll
        for (int r = 0; r < 8; r++) {
            int fi = r * 256 + tid;             // float4 index 0..2047
            int kk = fi >> 7;
            int o4 = (fi & 127) << 2;
            int j = k0 + kk;
            const float* sp = (o4 < 256) ? (wl + j * 256 + o4)
                                         : (wr + j * 256 + (o4 - 256));
            float4 vv = *reinterpret_cast<const float4*>(sp);
            *reinterpret_cast<float4*>(&sh_w[kk * 512 + o4]) = vv;
        }
        __syncthreads();
#pragma unroll
        for (int kk = 0; kk < KC; kk++) {
            float4 h0 = *reinterpret_cast<const float4*>(&sh_h[(k0 + kk) * 32 + eg * 8]);
            float4 h1 = *reinterpret_cast<const float4*>(&sh_h[(k0 + kk) * 32 + eg * 8 + 4]);
            float4 w0 = *reinterpret_cast<const float4*>(&sh_w[kk * 512 + og * 8]);
            float4 w1v = *reinterpret_cast<const float4*>(&sh_w[kk * 512 + og * 8 + 4]);
            float hv[8] = {h0.x, h0.y, h0.z, h0.w, h1.x, h1.y, h1.z, h1.w};
            float wv[8] = {w0.x, w0.y, w0.z, w0.w, w1v.x, w1v.y, w1v.z, w1v.w};
#pragma unroll
            for (int a = 0; a < 8; a++)
#pragma unroll
                for (int b = 0; b < 8; b++) acc[a][b] += hv[a] * wv[b];
        }
    }

    // ---- phase D: rt[e][r] = sum_c (right[r*32+c]+br) * t[e][c] ----
    if (og >= 32) {
        int ogr = og - 32;                      // right-half: o = 256 + ogr*8 + i
        int r = ogr >> 2;
        int cb = (ogr & 3) << 3;
#pragma unroll
        for (int a = 0; a < 8; a++) {
            int e = eg * 8 + a;
            float part = 0.f;
#pragma unroll
            for (int i = 0; i < 8; i++)
                part += (acc[a][i] + sh_br[ogr * 8 + i]) * sh_t[e * 33 + cb + i];
            atomicAdd(&sh_rt[e * 8 + r], part);
        }
    }
    __syncthreads();

    // ---- phase E: t2[e][p] = sum_r (left[p*8+r]+bl) * rt[e][r] ----
    if (og < 32) {
#pragma unroll
        for (int a = 0; a < 8; a++) {
            int e = eg * 8 + a;
            float s = 0.f;
#pragma unroll
            for (int r = 0; r < 8; r++)
                s += (acc[a][r] + sh_bl[og * 8 + r]) * sh_rt[e * 8 + r];
            sh_t2[e * 32 + og] = s;
        }
    }
    __syncthreads();

    // ---- phase F: out[e][m][d] = t2[e][2m]*b2[e][0][d] + t2[e][2m+1]*b2[e][1][d] ----
#pragma unroll
    for (int rep = 0; rep < 8; rep++) {
        int p = rep * 256 + tid;                // 0..2047
        int e = p >> 6, j = p & 63;
        int m = j >> 2, d = j & 3;
        float b2a = basis2[(e0 + e) * 8 + d];
        float b2b = basis2[(e0 + e) * 8 + 4 + d];
        float o = sh_t2[e * 32 + 2 * m] * b2a + sh_t2[e * 32 + 2 * m + 1] * b2b;
        sh_out[e * 64 + j] = o;
        if (conv == 1) g_v[(e0 + e) * 64 + j] = o;
    }
    __syncthreads();

    // ---- phase G (K conv only): attention scores + segment max ----
    if (conv == 0 && tid < TE * NH) {
        int e = tid >> 2, hh = tid & 3;
        int dn = __ldg(&dst[e0 + e]);
        const float* qr = g_q + dn * 64 + hh * 16;
        const float* kr = sh_out + e * 64 + hh * 16;
        float s = 0.f;
#pragma unroll
        for (int i = 0; i < 16; i++) s += qr[i] * kr[i];
        s *= 0.25f;                             // / sqrt(HM*DIM=16)
        g_scores[(e0 + e) * NH + hh] = s;
        atomicMaxFloat(&g_m[dn * NH + hh], s);
    }
}

// ---------------- kernel 3: exp + segment sum ----------------
__global__ void exden_kernel(const int* __restrict__ dst) {
    int p = blockIdx.x * blockDim.x + threadIdx.x;
    if (p >= EE * NH) return;
    int e = p >> 2, hh = p & 3;
    int d = __ldg(&dst[e]);
    float ex = expf(g_scores[p] - g_m[d * NH + hh]);
    g_ex[p] = ex;
    atomicAdd(&g_den[d * NH + hh], ex);
}

// ---------------- kernel 4: weighted scatter of V ----------------
__global__ void scatter_kernel(const int* __restrict__ dst, float* __restrict__ dout) {
    int p = blockIdx.x * blockDim.x + threadIdx.x;
    if (p >= EE * 64) return;
    int e = p >> 6, j = p & 63;
    int hh = j >> 4;
    int d = __ldg(&dst[e]);
    float den = fmaxf(g_den[d * NH + hh], 1e-9f);
    float alpha = g_ex[e * NH + hh] / den;
    atomicAdd(&dout[d * 64 + j], alpha * g_v[p]);
}

// ---------------- launch ----------------
extern "C" void kernel_launch(void* const* d_in, const int* in_sizes, int n_in,
                              void* d_out, int out_size) {
    const float* basis1 = (const float*)d_in[0];
    const float* basis2 = (const float*)d_in[1];
    const float* ef     = (const float*)d_in[2];
    const float* f      = (const float*)d_in[3];
    const int*   src    = (const int*)d_in[4];
    const int*   dst    = (const int*)d_in[5];
    const float* q_w    = (const float*)d_in[6];
    const float* q_b    = (const float*)d_in[7];
    const float* k_w1   = (const float*)d_in[8];
    const float* k_b1   = (const float*)d_in[9];
    const float* k_wl   = (const float*)d_in[10];
    const float* k_bl   = (const float*)d_in[11];
    const float* k_wr   = (const float*)d_in[12];
    const float* k_br   = (const float*)d_in[13];
    const float* v_w1   = (const float*)d_in[14];
    const float* v_b1   = (const float*)d_in[15];
    const float* v_wl   = (const float*)d_in[16];
    const float* v_bl   = (const float*)d_in[17];
    const float* v_wr   = (const float*)d_in[18];
    const float* v_br   = (const float*)d_in[19];
    float* dout = (float*)d_out;

    cudaFuncSetAttribute(conv_kernel, cudaFuncAttributeMaxDynamicSharedMemorySize, SMEM_BYTES);

    qinit_kernel<<<(NN * 64 + 255) / 256, 256>>>(f, q_w, q_b, dout);
    conv_kernel<<<dim3(EE / TE, 2), 256, SMEM_BYTES>>>(
        basis1, basis2, ef, f, src, dst,
        k_w1, k_b1, k_wl, k_bl, k_wr, k_br,
        v_w1, v_b1, v_wl, v_bl, v_wr, v_br);
    exden_kernel<<<(EE * NH + 255) / 256, 256>>>(dst);
    scatter_kernel<<<(EE * 64 + 255) / 256, 256>>>(dst, dout);
}

// round 2
// speedup vs baseline: 1.0184x; 1.0184x over previous
#include <cuda_runtime.h>
#include <math_constants.h>

#define NN 10000
#define EE 160000
#define MULT 16
#define NL 2
#define DIM 4
#define EDIM 32
#define HID 128
#define RANK 8
#define NH 4
#define TE 32          // edges per block
#define KC 16          // k-chunk of GEMM

// ---------------- scratch (static device arrays; no allocation) ----------------
__device__ float g_q[NN * 64];
__device__ float g_v[EE * 64];
__device__ float g_scores[EE * NH];
__device__ float g_ex[EE * NH];
__device__ float g_m[NN * NH];
__device__ float g_den[NN * NH];

__device__ __forceinline__ void atomicMaxFloat(float* addr, float val) {
    if (val >= 0.f) atomicMax((int*)addr, __float_as_int(val));
    else            atomicMin((unsigned int*)addr, __float_as_uint(val));
}

// packed fp32x2 FMA (Blackwell FFMA2 — PTX-only path)
#define FMA_F32X2(acc, a, b) \
    asm("fma.rn.f32x2 %0, %1, %2, %0;" : "+l"(acc) : "l"(a), "l"(b))
#define DUP_F32X2(dst, s) \
    asm("mov.b64 %0, {%1, %1};" : "=l"(dst) : "f"(s))
#define UNPACK_F32X2_(lo, hi, in) \
    asm("mov.b64 {%0, %1}, %2;" : "=f"(lo), "=f"(hi) : "l"(in))

// ---------------- kernel 1: Q equivariant linear + init ----------------
__global__ void qinit_kernel(const float* __restrict__ f,
                             const float* __restrict__ qw,
                             const float* __restrict__ qb,
                             float* __restrict__ dout) {
    int p = blockIdx.x * blockDim.x + threadIdx.x;
    if (p < NN * 64) {
        int n = p >> 6, j = p & 63;
        int o = j >> 2, d = j & 3;
        int l = (d == 0) ? 0 : 1;                    // IDX = [0,1,1,1]
        float acc = (d == 0) ? qb[o] : 0.f;
        const float* wrow = qw + (l * 16 + o) * 16;  // q_w.reshape(2,16,16)[l][o][:]
        const float* frow = f + n * 64 + d;
#pragma unroll
        for (int m = 0; m < 16; m++) acc += wrow[m] * frow[m * 4];
        g_q[p] = acc;
        dout[p] = 0.f;
    }
    if (p < NN * NH) { g_m[p] = -CUDART_INF_F; g_den[p] = 0.f; }
}

// ---------------- kernel 2: fused conv (K or V via blockIdx.y) ----------------
// smem layout (floats)
#define OFF_W   0        // 16*512 = 8192   (also stages w1 32*128=4096 in phase A)
#define OFF_H   8192     // 128*32 = 4096   h[j][e]
#define OFF_EF  12288    // 32*33  = 1056
#define OFF_T   13344    // 32*33  = 1056
#define OFF_RT  14400    // 32*8   = 256
#define OFF_T2  14656    // 32*32  = 1024
#define OFF_OUT 15680    // 32*64  = 2048
#define OFF_BL  17728    // 256
#define OFF_BR  17984    // 256
#define SMEM_FLOATS 18240
#define SMEM_BYTES (SMEM_FLOATS * 4)

__global__ void __launch_bounds__(256, 2)
conv_kernel(const float* __restrict__ basis1,   // (E,4,2)
            const float* __restrict__ basis2,   // (E,2,4)
            const float* __restrict__ ef,       // (E,32)
            const float* __restrict__ f,        // (N,16,4)
            const int*   __restrict__ src,
            const int*   __restrict__ dst,
            const float* __restrict__ k_w1, const float* __restrict__ k_b1,
            const float* __restrict__ k_wl, const float* __restrict__ k_bl,
            const float* __restrict__ k_wr, const float* __restrict__ k_br,
            const float* __restrict__ v_w1, const float* __restrict__ v_b1,
            const float* __restrict__ v_wl, const float* __restrict__ v_bl,
            const float* __restrict__ v_wr, const float* __restrict__ v_br) {
    extern __shared__ float sm[];
    float* sh_w   = sm + OFF_W;
    float* sh_h   = sm + OFF_H;
    float* sh_ef  = sm + OFF_EF;
    float* sh_t   = sm + OFF_T;
    float* sh_rt  = sm + OFF_RT;
    float* sh_t2  = sm + OFF_T2;
    float* sh_out = sm + OFF_OUT;
    float* sh_bl  = sm + OFF_BL;
    float* sh_br  = sm + OFF_BR;

    const int tid = threadIdx.x;
    const int e0 = blockIdx.x * TE;
    const int conv = blockIdx.y;                // 0 = K, 1 = V

    const float* w1 = conv ? v_w1 : k_w1;
    const float* hb = conv ? v_b1 : k_b1;
    const float* wl = conv ? v_wl : k_wl;
    const float* bl = conv ? v_bl : k_bl;
    const float* wr = conv ? v_wr : k_wr;
    const float* br = conv ? v_br : k_br;

    // ---- phase A: stage w1 (into sh_w), ef tile, biases; zero rt ----
#pragma unroll
    for (int r = 0; r < 16; r++) sh_w[r * 256 + tid] = w1[r * 256 + tid];       // 4096
#pragma unroll
    for (int r = 0; r < 4; r++) {
        int p = r * 256 + tid;                  // 0..1023
        int e = p >> 5, i = p & 31;
        sh_ef[e * 33 + i] = ef[(e0 + e) * EDIM + i];
    }
    sh_bl[tid & 255] = bl[tid];                 // 256 each
    sh_br[tid] = br[tid];
    sh_rt[tid & 255] = 0.f;

    // ---- phase B: t[e][c] = sum_d f[src][m][d]*basis1[e][d][l], c=m*2+l ----
#pragma unroll
    for (int r = 0; r < 4; r++) {
        int p = r * 256 + tid;                  // 0..1023
        int e = p >> 5, c = p & 31;
        int m = c >> 1, l = c & 1;
        int sn = __ldg(&src[e0 + e]);
        const float* fr = f + sn * 64 + m * 4;
        const float* b1r = basis1 + (e0 + e) * 8 + l;
        float a = 0.f;
#pragma unroll
        for (int d = 0; d < 4; d++) a += fr[d] * b1r[d * 2];
        sh_t[e * 33 + c] = a;
    }
    __syncthreads();

    // ---- phase A2: h[j][e] = gelu(ef . w1[:,j] + hb[j]) ----
#pragma unroll
    for (int rep = 0; rep < 16; rep++) {
        int p = rep * 256 + tid;                // 0..4095
        int e = p & 31, j = p >> 5;
        float a = __ldg(&hb[j]);
#pragma unroll
        for (int i = 0; i < 32; i++) a += sh_ef[e * 33 + i] * sh_w[i * 128 + j];
        sh_h[j * 32 + e] = a * normcdff(a);     // exact gelu
    }

    // ---- phase C: GEMM  C[32e x 512o] = h(32x128) @ [wl|wr](128x512) ----
    // packed f32x2 microkernel: acc pairs along the output (og) dimension
    const int eg = tid >> 6;                    // 0..3  (8 edges each)
    const int og = tid & 63;                    // 0..63 (8 outputs each)
    unsigned long long accp[8][4];
#pragma unroll
    for (int a = 0; a < 8; a++)
#pragma unroll
        for (int b = 0; b < 4; b++) accp[a][b] = 0ull;   // (0.f, 0.f)

    for (int k0 = 0; k0 < HID; k0 += KC) {
        __syncthreads();                        // protects sh_w reuse
#pragma unroll
        for (int r = 0; r < 8; r++) {
            int fi = r * 256 + tid;             // float4 index 0..2047
            int kk = fi >> 7;
            int o4 = (fi & 127) << 2;
            int j = k0 + kk;
            const float* sp = (o4 < 256) ? (wl + j * 256 + o4)
                                         : (wr + j * 256 + (o4 - 256));
            float4 vv = *reinterpret_cast<const float4*>(sp);
            *reinterpret_cast<float4*>(&sh_w[kk * 512 + o4]) = vv;
        }
        __syncthreads();
#pragma unroll
        for (int kk = 0; kk < KC; kk++) {
            // w: 8 floats = 4 packed pairs, loaded directly as 2x 16B
            ulonglong2 wq0 = *reinterpret_cast<const ulonglong2*>(&sh_w[kk * 512 + og * 8]);
            ulonglong2 wq1 = *reinterpret_cast<const ulonglong2*>(&sh_w[kk * 512 + og * 8 + 4]);
            unsigned long long wp0 = wq0.x, wp1 = wq0.y, wp2 = wq1.x, wp3 = wq1.y;
            // h: 8 edge values (warp-broadcast)
            float4 h0 = *reinterpret_cast<const float4*>(&sh_h[(k0 + kk) * 32 + eg * 8]);
            float4 h1 = *reinterpret_cast<const float4*>(&sh_h[(k0 + kk) * 32 + eg * 8 + 4]);
            float hv[8] = {h0.x, h0.y, h0.z, h0.w, h1.x, h1.y, h1.z, h1.w};
#pragma unroll
            for (int a = 0; a < 8; a++) {
                unsigned long long hp;
                DUP_F32X2(hp, hv[a]);
                FMA_F32X2(accp[a][0], hp, wp0);
                FMA_F32X2(accp[a][1], hp, wp1);
                FMA_F32X2(accp[a][2], hp, wp2);
                FMA_F32X2(accp[a][3], hp, wp3);
            }
        }
    }

    // unpack to scalar accumulators for the epilogue
    float acc[8][8];
#pragma unroll
    for (int a = 0; a < 8; a++)
#pragma unroll
        for (int b = 0; b < 4; b++)
            UNPACK_F32X2_(acc[a][2 * b], acc[a][2 * b + 1], accp[a][b]);

    // ---- phase D: rt[e][r] = sum_c (right[r*32+c]+br) * t[e][c] ----
    if (og >= 32) {
        int ogr = og - 32;                      // right-half: o = 256 + ogr*8 + i
        int r = ogr >> 2;
        int cb = (ogr & 3) << 3;
#pragma unroll
        for (int a = 0; a < 8; a++) {
            int e = eg * 8 + a;
            float part = 0.f;
#pragma unroll
            for (int i = 0; i < 8; i++)
                part += (acc[a][i] + sh_br[ogr * 8 + i]) * sh_t[e * 33 + cb + i];
            atomicAdd(&sh_rt[e * 8 + r], part);
        }
    }
    __syncthreads();

    // ---- phase E: t2[e][p] = sum_r (left[p*8+r]+bl) * rt[e][r] ----
    if (og < 32) {
#pragma unroll
        for (int a = 0; a < 8; a++) {
            int e = eg * 8 + a;
            float s = 0.f;
#pragma unroll
            for (int r = 0; r < 8; r++)
                s += (acc[a][r] + sh_bl[og * 8 + r]) * sh_rt[e * 8 + r];
            sh_t2[e * 32 + og] = s;
        }
    }
    __syncthreads();

    // ---- phase F: out[e][m][d] = t2[e][2m]*b2[e][0][d] + t2[e][2m+1]*b2[e][1][d] ----
#pragma unroll
    for (int rep = 0; rep < 8; rep++) {
        int p = rep * 256 + tid;                // 0..2047
        int e = p >> 6, j = p & 63;
        int m = j >> 2, d = j & 3;
        float b2a = basis2[(e0 + e) * 8 + d];
        float b2b = basis2[(e0 + e) * 8 + 4 + d];
        float o = sh_t2[e * 32 + 2 * m] * b2a + sh_t2[e * 32 + 2 * m + 1] * b2b;
        sh_out[e * 64 + j] = o;
        if (conv == 1) g_v[(e0 + e) * 64 + j] = o;
    }
    __syncthreads();

    // ---- phase G (K conv only): attention scores + segment max ----
    if (conv == 0 && tid < TE * NH) {
        int e = tid >> 2, hh = tid & 3;
        int dn = __ldg(&dst[e0 + e]);
        const float* qr = g_q + dn * 64 + hh * 16;
        const float* kr = sh_out + e * 64 + hh * 16;
        float s = 0.f;
#pragma unroll
        for (int i = 0; i < 16; i++) s += qr[i] * kr[i];
        s *= 0.25f;                             // / sqrt(HM*DIM=16)
        g_scores[(e0 + e) * NH + hh] = s;
        atomicMaxFloat(&g_m[dn * NH + hh], s);
    }
}

// ---------------- kernel 3: exp + segment sum ----------------
__global__ void exden_kernel(const int* __restrict__ dst) {
    int p = blockIdx.x * blockDim.x + threadIdx.x;
    if (p >= EE * NH) return;
    int e = p >> 2, hh = p & 3;
    int d = __ldg(&dst[e]);
    float ex = expf(g_scores[p] - g_m[d * NH + hh]);
    g_ex[p] = ex;
    atomicAdd(&g_den[d * NH + hh], ex);
}

// ---------------- kernel 4: weighted scatter of V ----------------
__global__ void scatter_kernel(const int* __restrict__ dst, float* __restrict__ dout) {
    int p = blockIdx.x * blockDim.x + threadIdx.x;
    if (p >= EE * 64) return;
    int e = p >> 6, j = p & 63;
    int hh = j >> 4;
    int d = __ldg(&dst[e]);
    float den = fmaxf(g_den[d * NH + hh], 1e-9f);
    float alpha = g_ex[e * NH + hh] / den;
    atomicAdd(&dout[d * 64 + j], alpha * g_v[p]);
}

// ---------------- launch ----------------
extern "C" void kernel_launch(void* const* d_in, const int* in_sizes, int n_in,
                              void* d_out, int out_size) {
    const float* basis1 = (const float*)d_in[0];
    const float* basis2 = (const float*)d_in[1];
    const float* ef     = (const float*)d_in[2];
    const float* f      = (const float*)d_in[3];
    const int*   src    = (const int*)d_in[4];
    const int*   dst    = (const int*)d_in[5];
    const float* q_w    = (const float*)d_in[6];
    const float* q_b    = (const float*)d_in[7];
    const float* k_w1   = (const float*)d_in[8];
    const float* k_b1   = (const float*)d_in[9];
    const float* k_wl   = (const float*)d_in[10];
    const float* k_bl   = (const float*)d_in[11];
    const float* k_wr   = (const float*)d_in[12];
    const float* k_br   = (const float*)d_in[13];
    const float* v_w1   = (const float*)d_in[14];
    const float* v_b1   = (const float*)d_in[15];
    const float* v_wl   = (const float*)d_in[16];
    const float* v_bl   = (const float*)d_in[17];
    const float* v_wr   = (const float*)d_in[18];
    const float* v_br   = (const float*)d_in[19];
    float* dout = (float*)d_out;

    cudaFuncSetAttribute(conv_kernel, cudaFuncAttributeMaxDynamicSharedMemorySize, SMEM_BYTES);

    qinit_kernel<<<(NN * 64 + 255) / 256, 256>>>(f, q_w, q_b, dout);
    conv_kernel<<<dim3(EE / TE, 2), 256, SMEM_BYTES>>>(
        basis1, basis2, ef, f, src, dst,
        k_w1, k_b1, k_wl, k_bl, k_wr, k_br,
        v_w1, v_b1, v_wl, v_bl, v_wr, v_br);
    exden_kernel<<<(EE * NH + 255) / 256, 256>>>(dst);
    scatter_kernel<<<(EE * 64 + 255) / 256, 256>>>(dst, dout);
}

// round 5
// speedup vs baseline: 2.2202x; 2.1801x over previous
#include <cuda_runtime.h>
#include <cuda_bf16.h>
#include <math_constants.h>
#include <cstdint>

#define NN 10000
#define EE 160000
#define EDIM 32
#define HID 128
#define NH 4
#define TM 128            // edges per block

// ---------------- scratch (static device arrays; no allocation) ----------------
__device__ __nv_bfloat16 g_wthi[2 * 512 * 128];  // [conv][n][k] bf16-hi of [wl|wr]^T
__device__ __nv_bfloat16 g_wtlo[2 * 512 * 128];
__device__ float g_bias[2][512];                 // [conv][bl(256)|br(256)]
__device__ float g_q[NN * 64];
__device__ float g_v[EE * 64];
__device__ float g_scores[EE * NH];
__device__ float g_ex[EE * NH];
__device__ float g_m[NN * NH];
__device__ float g_den[NN * NH];

__device__ __forceinline__ void atomicMaxFloat(float* addr, float val) {
    if (val >= 0.f) atomicMax((int*)addr, __float_as_int(val));
    else            atomicMin((unsigned int*)addr, __float_as_uint(val));
}
__device__ __forceinline__ uint32_t smem_to_u32(const void* p) {
    uint32_t a;
    asm("{ .reg .u64 t; cvta.to.shared.u64 t, %1; cvt.u32.u64 %0, t; }" : "=r"(a) : "l"(p));
    return a;
}
__device__ __forceinline__ void ldsm4(uint32_t a, uint32_t* r) {
    asm volatile("ldmatrix.sync.aligned.m8n8.x4.shared.b16 {%0,%1,%2,%3}, [%4];"
                 : "=r"(r[0]), "=r"(r[1]), "=r"(r[2]), "=r"(r[3]) : "r"(a));
}
__device__ __forceinline__ void mma16816(float* c, const uint32_t* a, const uint32_t* b) {
    asm volatile("mma.sync.aligned.m16n8k16.row.col.f32.bf16.bf16.f32 "
                 "{%0,%1,%2,%3}, {%4,%5,%6,%7}, {%8,%9}, {%0,%1,%2,%3};"
                 : "+f"(c[0]), "+f"(c[1]), "+f"(c[2]), "+f"(c[3])
                 : "r"(a[0]), "r"(a[1]), "r"(a[2]), "r"(a[3]), "r"(b[0]), "r"(b[1]));
}
__device__ __forceinline__ void cp16(uint32_t dst, const void* src) {
    asm volatile("cp.async.cg.shared.global [%0], [%1], 16;" :: "r"(dst), "l"(src) : "memory");
}

// ---------------- kernel 0: pre-split weights (bf16 hi/lo, transposed) ----------------
__global__ void presplit_kernel(const float* __restrict__ kwl, const float* __restrict__ kwr,
                                const float* __restrict__ vwl, const float* __restrict__ vwr,
                                const float* __restrict__ kbl, const float* __restrict__ kbr,
                                const float* __restrict__ vbl, const float* __restrict__ vbr) {
    int idx = blockIdx.x * blockDim.x + threadIdx.x;   // 131072
    if (idx < 2 * 512 * 128) {
        int conv = idx >> 16;
        int rem = idx & 65535;
        int n = rem >> 7, k = rem & 127;
        const float* w = conv ? (n < 256 ? vwl : vwr) : (n < 256 ? kwl : kwr);
        float val = w[k * 256 + (n & 255)];
        __nv_bfloat16 hi = __float2bfloat16_rn(val);
        g_wthi[idx] = hi;
        g_wtlo[idx] = __float2bfloat16_rn(val - __bfloat162float(hi));
    }
    if (idx < 1024) {
        int conv = idx >> 9, j = idx & 511;
        const float* s = conv ? (j < 256 ? vbl : vbr) : (j < 256 ? kbl : kbr);
        g_bias[conv][j] = s[j & 255];
    }
}

// ---------------- kernel 1: Q equivariant linear + init ----------------
__global__ void qinit_kernel(const float* __restrict__ f,
                             const float* __restrict__ qw,
                             const float* __restrict__ qb,
                             float* __restrict__ dout) {
    int p = blockIdx.x * blockDim.x + threadIdx.x;
    if (p < NN * 64) {
        int n = p >> 6, j = p & 63;
        int o = j >> 2, d = j & 3;
        int l = (d == 0) ? 0 : 1;
        float acc = (d == 0) ? qb[o] : 0.f;
        const float* wrow = qw + (l * 16 + o) * 16;
        const float* frow = f + n * 64 + d;
#pragma unroll
        for (int m = 0; m < 16; m++) acc += wrow[m] * frow[m * 4];
        g_q[p] = acc;
        dout[p] = 0.f;
    }
    if (p < NN * NH) { g_m[p] = -CUDART_INF_F; g_den[p] = 0.f; }
}

// ---------------- kernel 2: mma.sync fused conv ----------------
// smem byte offsets
#define OFF_AHI 0u
#define OFF_ALO 32768u
#define OFF_W0  65536u      // buffer: hi @+0 (32KB), lo @+32768
#define OFF_W1  131072u
#define OFF_T   196608u     // 128*33*4 = 16896 (t; aliased as t2 in left epilogue)
#define OFF_RT  213504u     // 128*8*4 = 4096
#define OFF_BIAS 217600u    // 512*4
#define SMEM_BYTES 219648u

__device__ __forceinline__ void load_wchunk(uint32_t smem_base, uint32_t bufoff, int conv,
                                            int nbase, int tid) {
#pragma unroll
    for (int ii = 0; ii < 16; ii++) {
        int g = ii * 256 + tid;                 // 0..4095 16B-chunks
        int half = g >> 11;                     // 0 hi, 1 lo
        int rem = g & 2047;
        int r = rem >> 4, q = rem & 15;
        const __nv_bfloat16* src =
            (half ? g_wtlo : g_wthi) + conv * 65536 + (nbase + r) * 128 + q * 8;
        uint32_t dst = smem_base + bufoff + (uint32_t)(half * 32768 + r * 256 + ((q ^ (r & 7)) << 4));
        cp16(dst, src);
    }
    asm volatile("cp.async.commit_group;" ::: "memory");
}

__global__ void __launch_bounds__(256, 1)
conv_mma_kernel(const float* __restrict__ basis1, const float* __restrict__ basis2,
                const float* __restrict__ ef, const float* __restrict__ f,
                const int* __restrict__ src, const int* __restrict__ dst,
                const float* __restrict__ k_w1, const float* __restrict__ k_b1,
                const float* __restrict__ v_w1, const float* __restrict__ v_b1) {
    extern __shared__ char sm[];
    const uint32_t smem_base = smem_to_u32(sm);
    const int tid = threadIdx.x;
    const int lane = tid & 31, wid = tid >> 5;
    const int l4 = lane & 3;
    const int wrow = (wid & 3) * 32;            // e base of warp tile
    const int wcol = (wid >> 2) * 64;           // n base (within chunk)
    const int conv = blockIdx.y;
    const int e0 = blockIdx.x * TM;

    float* sh_ef  = (float*)(sm + OFF_W0);      // aliased: only used pre-GEMM
    float* sh_t   = (float*)(sm + OFF_T);       // later aliased as t2
    float* sh_rt  = (float*)(sm + OFF_RT);
    float* sh_bias= (float*)(sm + OFF_BIAS);

    // ---- prologue: prefetch chunk 0 (nbase 256) into W1 ----
    load_wchunk(smem_base, OFF_W1, conv, 256, tid);

    // ---- stage ef, bias; compute t ----
#pragma unroll
    for (int r = 0; r < 16; r++) {
        int p = r * 256 + tid;                  // 4096
        sh_ef[p] = ef[e0 * EDIM + p];           // [e][i], stride 32, coalesced
    }
    sh_bias[tid] = g_bias[conv][tid];
    sh_bias[256 + tid] = g_bias[conv][256 + tid];
#pragma unroll
    for (int r = 0; r < 16; r++) {
        int p = r * 256 + tid;                  // 4096: t[e][c]
        int e = p >> 5, c = p & 31;
        int m = c >> 1, l = c & 1;
        int sn = __ldg(&src[e0 + e]);
        const float* fr = f + sn * 64 + m * 4;
        const float* b1r = basis1 + (e0 + e) * 8 + l;
        float a = 0.f;
#pragma unroll
        for (int d = 0; d < 4; d++) a += fr[d] * b1r[d * 2];
        sh_t[e * 33 + c] = a;
    }
    __syncthreads();

    // ---- h-phase: h = gelu(ef @ w1 + b1), split bf16 hi/lo into A tiles ----
    {
        const float* w1g = conv ? v_w1 : k_w1;
        const float* hbv = conv ? v_b1 : k_b1;
        const int jj = tid & 63;
        const int j0 = 2 * jj;
        const int eb = tid >> 6;                // 0..3
        float wv0[32], wv1[32];
#pragma unroll
        for (int i = 0; i < 32; i++) {
            wv0[i] = __ldg(&w1g[i * 128 + j0]);
            wv1[i] = __ldg(&w1g[i * 128 + j0 + 1]);
        }
        const float bb0 = __ldg(&hbv[j0]), bb1 = __ldg(&hbv[j0 + 1]);
        const uint32_t kchunk = (uint32_t)(j0 >> 3);
        const uint32_t inb = (uint32_t)((j0 & 7) * 2);
#pragma unroll 4
        for (int rep = 0; rep < 32; rep++) {
            int e = eb * 32 + rep;
            const float* efr = sh_ef + e * 32;
            float a0 = bb0, a1 = bb1;
#pragma unroll
            for (int q = 0; q < 8; q++) {
                float4 v = *reinterpret_cast<const float4*>(efr + q * 4);
#pragma unroll
                for (int u = 0; u < 4; u++) {
                    float ev = (&v.x)[u];
                    a0 += ev * wv0[q * 4 + u];
                    a1 += ev * wv1[q * 4 + u];
                }
            }
            a0 = a0 * normcdff(a0);
            a1 = a1 * normcdff(a1);
            __nv_bfloat162 hp2 = __floats2bfloat162_rn(a0, a1);  // .x = a0 (low)
            float h0f = __bfloat162float(hp2.x), h1f = __bfloat162float(hp2.y);
            __nv_bfloat162 lp2 = __floats2bfloat162_rn(a0 - h0f, a1 - h1f);
            uint32_t off = (uint32_t)(e * 256) + ((kchunk ^ (uint32_t)(e & 7)) << 4) + inb;
            *(uint32_t*)(sm + OFF_AHI + off) = *reinterpret_cast<uint32_t*>(&hp2);
            *(uint32_t*)(sm + OFF_ALO + off) = *reinterpret_cast<uint32_t*>(&lp2);
        }
    }
    __syncthreads();

    // ---- chunk loop: order right,right,left,left ----
    const int a_row_off = ((lane >> 3) & 1) * 8 + (lane & 7);
    const int a_ksel = (lane >> 4) & 1;
    const int b_n_off = ((lane >> 4) & 1) * 8 + (lane & 7);
    const int b_ksel = (lane >> 3) & 1;
    const int cn[4] = {256, 384, 0, 128};

    for (int ci = 0; ci < 4; ci++) {
        asm volatile("cp.async.wait_group 0;" ::: "memory");
        __syncthreads();
        if (ci < 3)
            load_wchunk(smem_base, (ci & 1) ? OFF_W1 : OFF_W0, conv, cn[ci + 1], tid);
        const uint32_t wb = smem_base + (((ci & 1) == 0) ? OFF_W1 : OFF_W0);
        const int nbase = cn[ci];

        float acc[2][8][4];
#pragma unroll
        for (int mt = 0; mt < 2; mt++)
#pragma unroll
            for (int nt = 0; nt < 8; nt++)
#pragma unroll
                for (int u = 0; u < 4; u++) acc[mt][nt][u] = 0.f;

#pragma unroll
        for (int ks = 0; ks < 8; ks++) {
            uint32_t Ahi[2][4], Alo[2][4], Bhi[4][4], Blo[4][4];
#pragma unroll
            for (int mt = 0; mt < 2; mt++) {
                int arow = wrow + mt * 16 + a_row_off;
                int kc = ks * 2 + a_ksel;
                uint32_t ad = smem_base + (uint32_t)(arow * 256 + ((kc ^ (arow & 7)) << 4));
                ldsm4(ad, Ahi[mt]);
                ldsm4(ad + 32768u, Alo[mt]);
            }
#pragma unroll
            for (int np = 0; np < 4; np++) {
                int n = wcol + np * 16 + b_n_off;
                int kc = ks * 2 + b_ksel;
                uint32_t bd = wb + (uint32_t)(n * 256 + ((kc ^ (n & 7)) << 4));
                ldsm4(bd, Bhi[np]);
                ldsm4(bd + 32768u, Blo[np]);
            }
#pragma unroll
            for (int mt = 0; mt < 2; mt++)
#pragma unroll
                for (int np = 0; np < 4; np++) {
                    mma16816(acc[mt][np * 2],     Ahi[mt], &Bhi[np][0]);
                    mma16816(acc[mt][np * 2],     Alo[mt], &Bhi[np][0]);
                    mma16816(acc[mt][np * 2],     Ahi[mt], &Blo[np][0]);
                    mma16816(acc[mt][np * 2 + 1], Ahi[mt], &Bhi[np][2]);
                    mma16816(acc[mt][np * 2 + 1], Alo[mt], &Bhi[np][2]);
                    mma16816(acc[mt][np * 2 + 1], Ahi[mt], &Blo[np][2]);
                }
        }

        // ---- per-chunk epilogue ----
        if (ci < 2) {
            // right: rt[e][r] = sum_c (C+br)[e][r*32+c] * t[e][c]
#pragma unroll
            for (int mt = 0; mt < 2; mt++)
#pragma unroll
                for (int h2 = 0; h2 < 2; h2++) {
                    int e = wrow + mt * 16 + h2 * 8 + (lane >> 2);
#pragma unroll
                    for (int rl = 0; rl < 2; rl++) {
                        float s = 0.f;
#pragma unroll
                        for (int q = 0; q < 4; q++) {
                            int nt = rl * 4 + q;
                            int o = nbase + wcol + nt * 8 + 2 * l4;
                            int c = q * 8 + 2 * l4;
                            s += (acc[mt][nt][h2 * 2] + sh_bias[o]) * sh_t[e * 33 + c]
                               + (acc[mt][nt][h2 * 2 + 1] + sh_bias[o + 1]) * sh_t[e * 33 + c + 1];
                        }
                        s += __shfl_xor_sync(0xFFFFFFFFu, s, 1);
                        s += __shfl_xor_sync(0xFFFFFFFFu, s, 2);
                        if (l4 == 0)
                            sh_rt[e * 8 + ((nbase - 256 + wcol) >> 5) + rl] = s;
                    }
                }
        } else {
            // left: t2[e][p] = sum_r (C+bl)[e][p*8+r] * rt[e][r]
            float* sh_t2 = sh_t;
#pragma unroll
            for (int mt = 0; mt < 2; mt++)
#pragma unroll
                for (int h2 = 0; h2 < 2; h2++) {
                    int e = wrow + mt * 16 + h2 * 8 + (lane >> 2);
                    float r0 = sh_rt[e * 8 + 2 * l4];
                    float r1 = sh_rt[e * 8 + 2 * l4 + 1];
#pragma unroll
                    for (int nt = 0; nt < 8; nt++) {
                        int o = nbase + wcol + nt * 8 + 2 * l4;
                        float s = (acc[mt][nt][h2 * 2] + sh_bias[o]) * r0
                                + (acc[mt][nt][h2 * 2 + 1] + sh_bias[o + 1]) * r1;
                        s += __shfl_xor_sync(0xFFFFFFFFu, s, 1);
                        s += __shfl_xor_sync(0xFFFFFFFFu, s, 2);
                        if (l4 == 0)
                            sh_t2[e * 33 + (nbase >> 3) + (wcol >> 3) + nt] = s;
                    }
                }
        }
    }
    __syncthreads();

    // ---- final: basis2 contraction → V store / K scores ----
    float* sh_t2 = sh_t;
    if (conv == 1) {
#pragma unroll
        for (int rep = 0; rep < 32; rep++) {
            int p = rep * 256 + tid;                 // 8192
            int e = p >> 6, j = p & 63;
            int m = j >> 2, d = j & 3;
            float b2a = basis2[(e0 + e) * 8 + d];
            float b2b = basis2[(e0 + e) * 8 + 4 + d];
            g_v[(e0 + e) * 64 + j] =
                sh_t2[e * 33 + 2 * m] * b2a + sh_t2[e * 33 + 2 * m + 1] * b2b;
        }
    } else {
#pragma unroll
        for (int rep = 0; rep < 2; rep++) {
            int p = rep * 256 + tid;                 // 512
            int e = p >> 2, hh = p & 3;
            int dn = __ldg(&dst[e0 + e]);
            const float* qr = g_q + dn * 64 + hh * 16;
            float s = 0.f;
#pragma unroll
            for (int m = hh * 4; m < hh * 4 + 4; m++) {
                float ta = sh_t2[e * 33 + 2 * m];
                float tb = sh_t2[e * 33 + 2 * m + 1];
#pragma unroll
                for (int d = 0; d < 4; d++) {
                    float kv = ta * basis2[(e0 + e) * 8 + d] + tb * basis2[(e0 + e) * 8 + 4 + d];
                    s += qr[(m - hh * 4) * 4 + d] * kv;
                }
            }
            s *= 0.25f;
            g_scores[(e0 + e) * NH + hh] = s;
            atomicMaxFloat(&g_m[dn * NH + hh], s);
        }
    }
}

// ---------------- kernel 3: exp + segment sum ----------------
__global__ void exden_kernel(const int* __restrict__ dst) {
    int p = blockIdx.x * blockDim.x + threadIdx.x;
    if (p >= EE * NH) return;
    int e = p >> 2, hh = p & 3;
    int d = __ldg(&dst[e]);
    float ex = expf(g_scores[p] - g_m[d * NH + hh]);
    g_ex[p] = ex;
    atomicAdd(&g_den[d * NH + hh], ex);
}

// ---------------- kernel 4: weighted scatter of V ----------------
__global__ void scatter_kernel(const int* __restrict__ dst, float* __restrict__ dout) {
    int p = blockIdx.x * blockDim.x + threadIdx.x;
    if (p >= EE * 64) return;
    int e = p >> 6, j = p & 63;
    int hh = j >> 4;
    int d = __ldg(&dst[e]);
    float den = fmaxf(g_den[d * NH + hh], 1e-9f);
    float alpha = g_ex[e * NH + hh] / den;
    atomicAdd(&dout[d * 64 + j], alpha * g_v[p]);
}

// ---------------- launch ----------------
extern "C" void kernel_launch(void* const* d_in, const int* in_sizes, int n_in,
                              void* d_out, int out_size) {
    const float* basis1 = (const float*)d_in[0];
    const float* basis2 = (const float*)d_in[1];
    const float* ef     = (const float*)d_in[2];
    const float* f      = (const float*)d_in[3];
    const int*   src    = (const int*)d_in[4];
    const int*   dst    = (const int*)d_in[5];
    const float* q_w    = (const float*)d_in[6];
    const float* q_b    = (const float*)d_in[7];
    const float* k_w1   = (const float*)d_in[8];
    const float* k_b1   = (const float*)d_in[9];
    const float* k_wl   = (const float*)d_in[10];
    const float* k_bl   = (const float*)d_in[11];
    const float* k_wr   = (const float*)d_in[12];
    const float* k_br   = (const float*)d_in[13];
    const float* v_w1   = (const float*)d_in[14];
    const float* v_b1   = (const float*)d_in[15];
    const float* v_wl   = (const float*)d_in[16];
    const float* v_bl   = (const float*)d_in[17];
    const float* v_wr   = (const float*)d_in[18];
    const float* v_br   = (const float*)d_in[19];
    float* dout = (float*)d_out;

    cudaFuncSetAttribute(conv_mma_kernel, cudaFuncAttributeMaxDynamicSharedMemorySize, SMEM_BYTES);

    presplit_kernel<<<512, 256>>>(k_wl, k_wr, v_wl, v_wr, k_bl, k_br, v_bl, v_br);
    qinit_kernel<<<(NN * 64 + 255) / 256, 256>>>(f, q_w, q_b, dout);
    conv_mma_kernel<<<dim3(EE / TM, 2), 256, SMEM_BYTES>>>(
        basis1, basis2, ef, f, src, dst, k_w1, k_b1, v_w1, v_b1);
    exden_kernel<<<(EE * NH + 255) / 256, 256>>>(dst);
    scatter_kernel<<<(EE * 64 + 255) / 256, 256>>>(dst, dout);
}

// round 6
// speedup vs baseline: 2.3484x; 1.0577x over previous
#include <cuda_runtime.h>
#include <cuda_bf16.h>
#include <math_constants.h>
#include <cstdint>

#define NN 10000
#define EE 160000
#define EDIM 32
#define HID 128
#define NH 4
#define TM 64             // edges per block

// ---------------- scratch (static device arrays; no allocation) ----------------
__device__ __nv_bfloat16 g_wthi[2 * 512 * 128];  // [conv][n][k] bf16-hi of [wl|wr]^T
__device__ __nv_bfloat16 g_wtlo[2 * 512 * 128];
__device__ float g_bias[2][512];                 // [conv][bl(256)|br(256)]
__device__ float g_q[NN * 64];
__device__ float g_v[EE * 64];
__device__ float g_scores[EE * NH];
__device__ float g_ex[EE * NH];
__device__ float g_m[NN * NH];
__device__ float g_den[NN * NH];

__device__ __forceinline__ void atomicMaxFloat(float* addr, float val) {
    if (val >= 0.f) atomicMax((int*)addr, __float_as_int(val));
    else            atomicMin((unsigned int*)addr, __float_as_uint(val));
}
__device__ __forceinline__ uint32_t smem_to_u32(const void* p) {
    uint32_t a;
    asm("{ .reg .u64 t; cvta.to.shared.u64 t, %1; cvt.u32.u64 %0, t; }" : "=r"(a) : "l"(p));
    return a;
}
__device__ __forceinline__ void ldsm4(uint32_t a, uint32_t* r) {
    asm volatile("ldmatrix.sync.aligned.m8n8.x4.shared.b16 {%0,%1,%2,%3}, [%4];"
                 : "=r"(r[0]), "=r"(r[1]), "=r"(r[2]), "=r"(r[3]) : "r"(a));
}
__device__ __forceinline__ void mma16816(float* c, const uint32_t* a, const uint32_t* b) {
    asm volatile("mma.sync.aligned.m16n8k16.row.col.f32.bf16.bf16.f32 "
                 "{%0,%1,%2,%3}, {%4,%5,%6,%7}, {%8,%9}, {%0,%1,%2,%3};"
                 : "+f"(c[0]), "+f"(c[1]), "+f"(c[2]), "+f"(c[3])
                 : "r"(a[0]), "r"(a[1]), "r"(a[2]), "r"(a[3]), "r"(b[0]), "r"(b[1]));
}
__device__ __forceinline__ void cp16(uint32_t dst, const void* src) {
    asm volatile("cp.async.cg.shared.global [%0], [%1], 16;" :: "r"(dst), "l"(src) : "memory");
}

// ---------------- kernel 0: pre-split weights (bf16 hi/lo, transposed) ----------------
__global__ void presplit_kernel(const float* __restrict__ kwl, const float* __restrict__ kwr,
                                const float* __restrict__ vwl, const float* __restrict__ vwr,
                                const float* __restrict__ kbl, const float* __restrict__ kbr,
                                const float* __restrict__ vbl, const float* __restrict__ vbr) {
    int idx = blockIdx.x * blockDim.x + threadIdx.x;   // 131072
    if (idx < 2 * 512 * 128) {
        int conv = idx >> 16;
        int rem = idx & 65535;
        int n = rem >> 7, k = rem & 127;
        const float* w = conv ? (n < 256 ? vwl : vwr) : (n < 256 ? kwl : kwr);
        float val = w[k * 256 + (n & 255)];
        __nv_bfloat16 hi = __float2bfloat16_rn(val);
        g_wthi[idx] = hi;
        g_wtlo[idx] = __float2bfloat16_rn(val - __bfloat162float(hi));
    }
    if (idx < 1024) {
        int conv = idx >> 9, j = idx & 511;
        const float* s = conv ? (j < 256 ? vbl : vbr) : (j < 256 ? kbl : kbr);
        g_bias[conv][j] = s[j & 255];
    }
}

// ---------------- kernel 1: Q equivariant linear + init ----------------
__global__ void qinit_kernel(const float* __restrict__ f,
                             const float* __restrict__ qw,
                             const float* __restrict__ qb,
                             float* __restrict__ dout) {
    int p = blockIdx.x * blockDim.x + threadIdx.x;
    if (p < NN * 64) {
        int n = p >> 6, j = p & 63;
        int o = j >> 2, d = j & 3;
        int l = (d == 0) ? 0 : 1;
        float acc = (d == 0) ? qb[o] : 0.f;
        const float* wrow = qw + (l * 16 + o) * 16;
        const float* frow = f + n * 64 + d;
#pragma unroll
        for (int m = 0; m < 16; m++) acc += wrow[m] * frow[m * 4];
        g_q[p] = acc;
        dout[p] = 0.f;
    }
    if (p < NN * NH) { g_m[p] = -CUDART_INF_F; g_den[p] = 0.f; }
}

// ---------------- kernel 2: mma.sync fused conv (occ 2) ----------------
// smem byte offsets
#define OFF_AHI 0u          // 16384
#define OFF_ALO 16384u      // 16384
#define OFF_W0  32768u      // 32768 (hi 16K @+0, lo 16K @+16384)
#define OFF_W1  65536u      // 32768 (also stages ef 8KB pre-loop)
#define OFF_T   98304u      // 64*33*4 = 8448 (t; aliased as t2)
#define OFF_RT  106752u     // 64*8*4 = 2048
#define OFF_BIAS 108800u    // 512*4
#define SMEM_BYTES 110848u

__device__ __forceinline__ void load_wchunk(uint32_t smem_base, uint32_t bufoff, int conv,
                                            int nbase, int tid) {
#pragma unroll
    for (int ii = 0; ii < 8; ii++) {
        int g = ii * 256 + tid;                 // 0..2047 16B-chunks
        int half = g >> 10;                     // 0 hi, 1 lo
        int rem = g & 1023;
        int r = rem >> 4, q = rem & 15;
        const __nv_bfloat16* src =
            (half ? g_wtlo : g_wthi) + conv * 65536 + (nbase + r) * 128 + q * 8;
        uint32_t dst = smem_base + bufoff + (uint32_t)(half * 16384 + r * 256 + ((q ^ (r & 7)) << 4));
        cp16(dst, src);
    }
    asm volatile("cp.async.commit_group;" ::: "memory");
}

__global__ void __launch_bounds__(256, 2)
conv_mma_kernel(const float* __restrict__ basis1, const float* __restrict__ basis2,
                const float* __restrict__ ef, const float* __restrict__ f,
                const int* __restrict__ src, const int* __restrict__ dst,
                const float* __restrict__ k_w1, const float* __restrict__ k_b1,
                const float* __restrict__ v_w1, const float* __restrict__ v_b1) {
    extern __shared__ char sm[];
    const uint32_t smem_base = smem_to_u32(sm);
    const int tid = threadIdx.x;
    const int lane = tid & 31, wid = tid >> 5;
    const int l4 = lane & 3;
    const int wrow = (wid & 1) * 32;            // e base of warp tile
    const int wcol = (wid >> 1) * 16;           // n base within 64-col chunk
    const int conv = blockIdx.y;
    const int e0 = blockIdx.x * TM;

    float* sh_ef  = (float*)(sm + OFF_W1);      // aliased: only used pre-loop
    float* sh_t   = (float*)(sm + OFF_T);       // later aliased as t2
    float* sh_rt  = (float*)(sm + OFF_RT);
    float* sh_bias= (float*)(sm + OFF_BIAS);

    // ---- prefetch chunk 0 (nbase 256) into W0 ----
    load_wchunk(smem_base, OFF_W0, conv, 256, tid);

    // ---- stage ef (into W1 region), bias; zero rt; compute t ----
#pragma unroll
    for (int r = 0; r < 2; r++) {
        int idx = r * 256 + tid;                // 512 float4 = 2048 floats
        ((float4*)sh_ef)[idx] = ((const float4*)(ef + (size_t)e0 * EDIM))[idx];
    }
    sh_bias[tid] = g_bias[conv][tid];
    sh_bias[256 + tid] = g_bias[conv][256 + tid];
    sh_rt[tid] = 0.f;
    sh_rt[256 + tid] = 0.f;
#pragma unroll
    for (int r = 0; r < 8; r++) {
        int p = r * 256 + tid;                  // 2048: t[e][c]
        int e = p >> 5, c = p & 31;
        int m = c >> 1, l = c & 1;
        int sn = __ldg(&src[e0 + e]);
        const float* fr = f + sn * 64 + m * 4;
        const float* b1r = basis1 + (e0 + e) * 8 + l;
        float a = 0.f;
#pragma unroll
        for (int d = 0; d < 4; d++) a += fr[d] * b1r[d * 2];
        sh_t[e * 33 + c] = a;
    }
    __syncthreads();

    // ---- h-phase: h = gelu(ef @ w1 + b1), split bf16 hi/lo into A tiles ----
    {
        const float* w1g = conv ? v_w1 : k_w1;
        const float* hbv = conv ? v_b1 : k_b1;
        const int j0 = 2 * (tid & 63);
        const int eb = tid >> 6;                // 0..3, 16 edges each
        float wv0[32], wv1[32];
#pragma unroll
        for (int i = 0; i < 32; i++) {
            wv0[i] = __ldg(&w1g[i * 128 + j0]);
            wv1[i] = __ldg(&w1g[i * 128 + j0 + 1]);
        }
        const float bb0 = __ldg(&hbv[j0]), bb1 = __ldg(&hbv[j0 + 1]);
        const uint32_t kchunk = (uint32_t)(j0 >> 3);
        const uint32_t inb = (uint32_t)((j0 & 7) * 2);
#pragma unroll 4
        for (int rep = 0; rep < 16; rep++) {
            int e = eb * 16 + rep;
            const float* efr = sh_ef + e * 32;
            float a0 = bb0, a1 = bb1;
#pragma unroll
            for (int q = 0; q < 8; q++) {
                float4 v = *reinterpret_cast<const float4*>(efr + q * 4);
#pragma unroll
                for (int u = 0; u < 4; u++) {
                    float ev = (&v.x)[u];
                    a0 += ev * wv0[q * 4 + u];
                    a1 += ev * wv1[q * 4 + u];
                }
            }
            a0 = a0 * normcdff(a0);
            a1 = a1 * normcdff(a1);
            __nv_bfloat162 hp2 = __floats2bfloat162_rn(a0, a1);
            float h0f = __bfloat162float(hp2.x), h1f = __bfloat162float(hp2.y);
            __nv_bfloat162 lp2 = __floats2bfloat162_rn(a0 - h0f, a1 - h1f);
            uint32_t off = (uint32_t)(e * 256) + ((kchunk ^ (uint32_t)(e & 7)) << 4) + inb;
            *(uint32_t*)(sm + OFF_AHI + off) = *reinterpret_cast<uint32_t*>(&hp2);
            *(uint32_t*)(sm + OFF_ALO + off) = *reinterpret_cast<uint32_t*>(&lp2);
        }
    }
    __syncthreads();

    // ---- prefetch chunk 1 (nbase 320) into W1 (ef no longer needed) ----
    load_wchunk(smem_base, OFF_W1, conv, 320, tid);

    // ---- chunk loop: right chunks (cols 256..511) then left (0..255) ----
    const int a_row_off = ((lane >> 3) & 1) * 8 + (lane & 7);
    const int a_ksel = (lane >> 4) & 1;
    const int b_n_off = ((lane >> 4) & 1) * 8 + (lane & 7);
    const int b_ksel = (lane >> 3) & 1;
    const int cn[8] = {256, 320, 384, 448, 0, 64, 128, 192};
    float* sh_t2 = sh_t;

    for (int ci = 0; ci < 8; ci++) {
        if (ci == 7) asm volatile("cp.async.wait_group 0;" ::: "memory");
        else         asm volatile("cp.async.wait_group 1;" ::: "memory");
        __syncthreads();
        const uint32_t wb = smem_base + ((ci & 1) ? OFF_W1 : OFF_W0);

        float acc[2][2][4];
#pragma unroll
        for (int mt = 0; mt < 2; mt++)
#pragma unroll
            for (int nt = 0; nt < 2; nt++)
#pragma unroll
                for (int u = 0; u < 4; u++) acc[mt][nt][u] = 0.f;

#pragma unroll
        for (int ks = 0; ks < 8; ks++) {
            uint32_t Ahi[2][4], Alo[2][4], Bhi[4], Blo[4];
#pragma unroll
            for (int mt = 0; mt < 2; mt++) {
                int arow = wrow + mt * 16 + a_row_off;
                int kc = ks * 2 + a_ksel;
                uint32_t ad = smem_base + (uint32_t)(arow * 256 + ((kc ^ (arow & 7)) << 4));
                ldsm4(ad, Ahi[mt]);
                ldsm4(ad + 16384u, Alo[mt]);
            }
            {
                int n = wcol + b_n_off;
                int kc = ks * 2 + b_ksel;
                uint32_t bd = wb + (uint32_t)(n * 256 + ((kc ^ (n & 7)) << 4));
                ldsm4(bd, Bhi);
                ldsm4(bd + 16384u, Blo);
            }
#pragma unroll
            for (int mt = 0; mt < 2; mt++) {
                mma16816(acc[mt][0], Ahi[mt], &Bhi[0]);
                mma16816(acc[mt][0], Alo[mt], &Bhi[0]);
                mma16816(acc[mt][0], Ahi[mt], &Blo[0]);
                mma16816(acc[mt][1], Ahi[mt], &Bhi[2]);
                mma16816(acc[mt][1], Alo[mt], &Bhi[2]);
                mma16816(acc[mt][1], Ahi[mt], &Blo[2]);
            }
        }

        // ---- per-chunk epilogue ----
        if (ci < 4) {
            // right: rt[e][r] += sum over this warp's 16 cols of (C+br)*t
            const int r = ci * 2 + (wcol >> 5);
#pragma unroll
            for (int mt = 0; mt < 2; mt++)
#pragma unroll
                for (int h2 = 0; h2 < 2; h2++) {
                    int e = wrow + mt * 16 + h2 * 8 + (lane >> 2);
                    float s = 0.f;
#pragma unroll
                    for (int nt = 0; nt < 2; nt++) {
                        int o = 256 + ci * 64 + wcol + nt * 8 + 2 * l4;
                        int c = (ci * 64 + wcol + nt * 8 + 2 * l4) & 31;
                        s += (acc[mt][nt][h2 * 2] + sh_bias[o]) * sh_t[e * 33 + c]
                           + (acc[mt][nt][h2 * 2 + 1] + sh_bias[o + 1]) * sh_t[e * 33 + c + 1];
                    }
                    s += __shfl_xor_sync(0xFFFFFFFFu, s, 1);
                    s += __shfl_xor_sync(0xFFFFFFFFu, s, 2);
                    if (l4 == 0) atomicAdd(&sh_rt[e * 8 + r], s);
                }
        } else {
            // left: t2[e][p] = sum_r (C+bl)[e][p*8+r] * rt[e][r]
            const int cli = ci - 4;
#pragma unroll
            for (int mt = 0; mt < 2; mt++)
#pragma unroll
                for (int h2 = 0; h2 < 2; h2++) {
                    int e = wrow + mt * 16 + h2 * 8 + (lane >> 2);
                    float r0 = sh_rt[e * 8 + 2 * l4];
                    float r1 = sh_rt[e * 8 + 2 * l4 + 1];
#pragma unroll
                    for (int nt = 0; nt < 2; nt++) {
                        int o = cli * 64 + wcol + nt * 8 + 2 * l4;
                        float s = (acc[mt][nt][h2 * 2] + sh_bias[o]) * r0
                                + (acc[mt][nt][h2 * 2 + 1] + sh_bias[o + 1]) * r1;
                        s += __shfl_xor_sync(0xFFFFFFFFu, s, 1);
                        s += __shfl_xor_sync(0xFFFFFFFFu, s, 2);
                        if (l4 == 0)
                            sh_t2[e * 33 + cli * 8 + (wcol >> 3) + nt] = s;
                    }
                }
        }
        __syncthreads();
        if (ci < 6)
            load_wchunk(smem_base, (ci & 1) ? OFF_W1 : OFF_W0, conv, cn[ci + 2], tid);
    }
    __syncthreads();

    // ---- final: basis2 contraction → V store / K scores ----
    if (conv == 1) {
#pragma unroll
        for (int rep = 0; rep < 16; rep++) {
            int p = rep * 256 + tid;                 // 4096
            int e = p >> 6, j = p & 63;
            int m = j >> 2, d = j & 3;
            float b2a = basis2[(e0 + e) * 8 + d];
            float b2b = basis2[(e0 + e) * 8 + 4 + d];
            g_v[(e0 + e) * 64 + j] =
                sh_t2[e * 33 + 2 * m] * b2a + sh_t2[e * 33 + 2 * m + 1] * b2b;
        }
    } else {
        int e = tid >> 2, hh = tid & 3;              // 256 = 64*4
        int dn = __ldg(&dst[e0 + e]);
        const float* qr = g_q + dn * 64 + hh * 16;
        float s = 0.f;
#pragma unroll
        for (int m = hh * 4; m < hh * 4 + 4; m++) {
            float ta = sh_t2[e * 33 + 2 * m];
            float tb = sh_t2[e * 33 + 2 * m + 1];
#pragma unroll
            for (int d = 0; d < 4; d++) {
                float kv = ta * basis2[(e0 + e) * 8 + d] + tb * basis2[(e0 + e) * 8 + 4 + d];
                s += qr[(m - hh * 4) * 4 + d] * kv;
            }
        }
        s *= 0.25f;
        g_scores[(e0 + e) * NH + hh] = s;
        atomicMaxFloat(&g_m[dn * NH + hh], s);
    }
}

// ---------------- kernel 3: exp + segment sum ----------------
__global__ void exden_kernel(const int* __restrict__ dst) {
    int p = blockIdx.x * blockDim.x + threadIdx.x;
    if (p >= EE * NH) return;
    int e = p >> 2, hh = p & 3;
    int d = __ldg(&dst[e]);
    float ex = expf(g_scores[p] - g_m[d * NH + hh]);
    g_ex[p] = ex;
    atomicAdd(&g_den[d * NH + hh], ex);
}

// ---------------- kernel 4: weighted scatter of V ----------------
__global__ void scatter_kernel(const int* __restrict__ dst, float* __restrict__ dout) {
    int p = blockIdx.x * blockDim.x + threadIdx.x;
    if (p >= EE * 64) return;
    int e = p >> 6, j = p & 63;
    int hh = j >> 4;
    int d = __ldg(&dst[e]);
    float den = fmaxf(g_den[d * NH + hh], 1e-9f);
    float alpha = g_ex[e * NH + hh] / den;
    atomicAdd(&dout[d * 64 + j], alpha * g_v[p]);
}

// ---------------- launch ----------------
extern "C" void kernel_launch(void* const* d_in, const int* in_sizes, int n_in,
                              void* d_out, int out_size) {
    const float* basis1 = (const float*)d_in[0];
    const float* basis2 = (const float*)d_in[1];
    const float* ef     = (const float*)d_in[2];
    const float* f      = (const float*)d_in[3];
    const int*   src    = (const int*)d_in[4];
    const int*   dst    = (const int*)d_in[5];
    const float* q_w    = (const float*)d_in[6];
    const float* q_b    = (const float*)d_in[7];
    const float* k_w1   = (const float*)d_in[8];
    const float* k_b1   = (const float*)d_in[9];
    const float* k_wl   = (const float*)d_in[10];
    const float* k_bl   = (const float*)d_in[11];
    const float* k_wr   = (const float*)d_in[12];
    const float* k_br   = (const float*)d_in[13];
    const float* v_w1   = (const float*)d_in[14];
    const float* v_b1   = (const float*)d_in[15];
    const float* v_wl   = (const float*)d_in[16];
    const float* v_bl   = (const float*)d_in[17];
    const float* v_wr   = (const float*)d_in[18];
    const float* v_br   = (const float*)d_in[19];
    float* dout = (float*)d_out;

    cudaFuncSetAttribute(conv_mma_kernel, cudaFuncAttributeMaxDynamicSharedMemorySize, SMEM_BYTES);

    presplit_kernel<<<512, 256>>>(k_wl, k_wr, v_wl, v_wr, k_bl, k_br, v_bl, v_br);
    qinit_kernel<<<(NN * 64 + 255) / 256, 256>>>(f, q_w, q_b, dout);
    conv_mma_kernel<<<dim3(EE / TM, 2), 256, SMEM_BYTES>>>(
        basis1, basis2, ef, f, src, dst, k_w1, k_b1, v_w1, v_b1);
    exden_kernel<<<(EE * NH + 255) / 256, 256>>>(dst);
    scatter_kernel<<<(EE * 64 + 255) / 256, 256>>>(dst, dout);
}

// round 7
// speedup vs baseline: 2.5553x; 1.0881x over previous
#include <cuda_runtime.h>
#include <cuda_bf16.h>
#include <math_constants.h>
#include <cstdint>

#define NN 10000
#define EE 160000
#define EDIM 32
#define HID 128
#define NH 4
#define TM 64             // edges per block

// ---------------- scratch (static device arrays; no allocation) ----------------
__device__ __nv_bfloat16 g_wthi[2 * 512 * 128];  // [conv][n][k] bf16-hi of [wl|wr]^T
__device__ __nv_bfloat16 g_wtlo[2 * 512 * 128];
__device__ __nv_bfloat16 g_w1hi[2 * 128 * 32];   // [conv][j][i] bf16-hi of w1^T
__device__ __nv_bfloat16 g_w1lo[2 * 128 * 32];
__device__ float g_bias[2][512];                 // [conv][bl(256)|br(256)]
__device__ float g_q[NN * 64];
__device__ float g_v[EE * 64];
__device__ float g_scores[EE * NH];
__device__ float g_ex[EE * NH];
__device__ float g_m[NN * NH];
__device__ float g_den[NN * NH];

__device__ __forceinline__ void atomicMaxFloat(float* addr, float val) {
    if (val >= 0.f) atomicMax((int*)addr, __float_as_int(val));
    else            atomicMin((unsigned int*)addr, __float_as_uint(val));
}
__device__ __forceinline__ uint32_t smem_to_u32(const void* p) {
    uint32_t a;
    asm("{ .reg .u64 t; cvta.to.shared.u64 t, %1; cvt.u32.u64 %0, t; }" : "=r"(a) : "l"(p));
    return a;
}
__device__ __forceinline__ void ldsm4(uint32_t a, uint32_t* r) {
    asm volatile("ldmatrix.sync.aligned.m8n8.x4.shared.b16 {%0,%1,%2,%3}, [%4];"
                 : "=r"(r[0]), "=r"(r[1]), "=r"(r[2]), "=r"(r[3]) : "r"(a));
}
__device__ __forceinline__ void mma16816(float* c, const uint32_t* a, const uint32_t* b) {
    asm volatile("mma.sync.aligned.m16n8k16.row.col.f32.bf16.bf16.f32 "
                 "{%0,%1,%2,%3}, {%4,%5,%6,%7}, {%8,%9}, {%0,%1,%2,%3};"
                 : "+f"(c[0]), "+f"(c[1]), "+f"(c[2]), "+f"(c[3])
                 : "r"(a[0]), "r"(a[1]), "r"(a[2]), "r"(a[3]), "r"(b[0]), "r"(b[1]));
}
__device__ __forceinline__ void cp16(uint32_t dst, const void* src) {
    asm volatile("cp.async.cg.shared.global [%0], [%1], 16;" :: "r"(dst), "l"(src) : "memory");
}

// ---------------- kernel 0: pre-split weights (bf16 hi/lo, transposed) ----------------
__global__ void presplit_kernel(const float* __restrict__ kwl, const float* __restrict__ kwr,
                                const float* __restrict__ vwl, const float* __restrict__ vwr,
                                const float* __restrict__ kbl, const float* __restrict__ kbr,
                                const float* __restrict__ vbl, const float* __restrict__ vbr,
                                const float* __restrict__ kw1, const float* __restrict__ vw1) {
    int idx = blockIdx.x * blockDim.x + threadIdx.x;   // 131072
    if (idx < 2 * 512 * 128) {
        int conv = idx >> 16;
        int rem = idx & 65535;
        int n = rem >> 7, k = rem & 127;
        const float* w = conv ? (n < 256 ? vwl : vwr) : (n < 256 ? kwl : kwr);
        float val = w[k * 256 + (n & 255)];
        __nv_bfloat16 hi = __float2bfloat16_rn(val);
        g_wthi[idx] = hi;
        g_wtlo[idx] = __float2bfloat16_rn(val - __bfloat162float(hi));
    }
    if (idx < 2 * 128 * 32) {                          // w1^T split
        int conv = idx >> 12;
        int rem = idx & 4095;
        int j = rem >> 5, i = rem & 31;
        float val = (conv ? vw1 : kw1)[i * 128 + j];
        __nv_bfloat16 hi = __float2bfloat16_rn(val);
        g_w1hi[idx] = hi;
        g_w1lo[idx] = __float2bfloat16_rn(val - __bfloat162float(hi));
    }
    if (idx < 1024) {
        int conv = idx >> 9, j = idx & 511;
        const float* s = conv ? (j < 256 ? vbl : vbr) : (j < 256 ? kbl : kbr);
        g_bias[conv][j] = s[j & 255];
    }
}

// ---------------- kernel 1: Q equivariant linear + init ----------------
__global__ void qinit_kernel(const float* __restrict__ f,
                             const float* __restrict__ qw,
                             const float* __restrict__ qb,
                             float* __restrict__ dout) {
    int p = blockIdx.x * blockDim.x + threadIdx.x;
    if (p < NN * 64) {
        int n = p >> 6, j = p & 63;
        int o = j >> 2, d = j & 3;
        int l = (d == 0) ? 0 : 1;
        float acc = (d == 0) ? qb[o] : 0.f;
        const float* wrow = qw + (l * 16 + o) * 16;
        const float* frow = f + n * 64 + d;
#pragma unroll
        for (int m = 0; m < 16; m++) acc += wrow[m] * frow[m * 4];
        g_q[p] = acc;
        dout[p] = 0.f;
    }
    if (p < NN * NH) { g_m[p] = -CUDART_INF_F; g_den[p] = 0.f; }
}

// ---------------- kernel 2: mma.sync fused conv (occ 2, tensor h-MLP) ----------------
// smem byte offsets
#define OFF_AHI 0u          // 16384 (64 x 256B)
#define OFF_ALO 16384u      // 16384
#define OFF_W0  32768u      // 32768 (hi 16K @+0, lo 16K @+16384)
#define OFF_W1  65536u      // 32768; pre-loop: ef-hi 8K | ef-lo 8K | w1t-hi 8K | w1t-lo 8K
#define OFF_T   98304u      // 64*33*4 = 8448 (t; aliased as t2)
#define OFF_RT  106752u     // 64*8*4 = 2048
#define OFF_BIAS 108800u    // 512*4
#define SMEM_BYTES 110848u

#define OFF_EFHI (OFF_W1)
#define OFF_EFLO (OFF_W1 + 8192u)
#define OFF_W1T  (OFF_W1 + 16384u)   // hi 8K, lo at +8192

__device__ __forceinline__ void load_wchunk(uint32_t smem_base, uint32_t bufoff, int conv,
                                            int nbase, int tid) {
#pragma unroll
    for (int ii = 0; ii < 8; ii++) {
        int g = ii * 256 + tid;                 // 0..2047 16B-chunks
        int half = g >> 10;                     // 0 hi, 1 lo
        int rem = g & 1023;
        int r = rem >> 4, q = rem & 15;
        const __nv_bfloat16* src =
            (half ? g_wtlo : g_wthi) + conv * 65536 + (nbase + r) * 128 + q * 8;
        uint32_t dst = smem_base + bufoff + (uint32_t)(half * 16384 + r * 256 + ((q ^ (r & 7)) << 4));
        cp16(dst, src);
    }
    asm volatile("cp.async.commit_group;" ::: "memory");
}

__global__ void __launch_bounds__(256, 2)
conv_mma_kernel(const float* __restrict__ basis1, const float* __restrict__ basis2,
                const float* __restrict__ ef, const float* __restrict__ f,
                const int* __restrict__ src, const int* __restrict__ dst,
                const float* __restrict__ k_b1, const float* __restrict__ v_b1) {
    extern __shared__ char sm[];
    const uint32_t smem_base = smem_to_u32(sm);
    const int tid = threadIdx.x;
    const int lane = tid & 31, wid = tid >> 5;
    const int l4 = lane & 3;
    const int wrow = (wid & 1) * 32;            // e base of warp tile (main loop)
    const int wcol = (wid >> 1) * 16;           // n base within 64-col chunk
    const int conv = blockIdx.y;
    const int e0 = blockIdx.x * TM;

    float* sh_t   = (float*)(sm + OFF_T);       // later aliased as t2
    float* sh_rt  = (float*)(sm + OFF_RT);
    float* sh_bias= (float*)(sm + OFF_BIAS);

    // ---- prefetch chunk 0 (nbase 256) into W0; w1t tiles into W1 upper ----
    load_wchunk(smem_base, OFF_W0, conv, 256, tid);
#pragma unroll
    for (int r = 0; r < 4; r++) {
        int g = r * 256 + tid;                  // 1024: (half, n, q)
        int half = g >> 9;
        int rem = g & 511;
        int n = rem >> 2, q = rem & 3;
        const __nv_bfloat16* srcp =
            (half ? g_w1lo : g_w1hi) + conv * 4096 + n * 32 + q * 8;
        uint32_t dstp = smem_base + OFF_W1T + (uint32_t)(half * 8192 + n * 64 + ((q ^ (n & 3)) << 4));
        cp16(dstp, srcp);
    }
    asm volatile("cp.async.commit_group;" ::: "memory");

    // ---- stage ef (fp32 -> bf16 hi/lo tiles), bias; zero rt; compute t ----
#pragma unroll
    for (int r = 0; r < 2; r++) {
        int idx = r * 256 + tid;                // 512 float4s
        int e = idx >> 3, i0 = (idx & 7) * 4;
        float4 v = ((const float4*)(ef + (size_t)e0 * EDIM))[idx];
        __nv_bfloat162 h01 = __floats2bfloat162_rn(v.x, v.y);
        __nv_bfloat162 h23 = __floats2bfloat162_rn(v.z, v.w);
        __nv_bfloat162 l01 = __floats2bfloat162_rn(v.x - __bfloat162float(h01.x),
                                                   v.y - __bfloat162float(h01.y));
        __nv_bfloat162 l23 = __floats2bfloat162_rn(v.z - __bfloat162float(h23.x),
                                                   v.w - __bfloat162float(h23.y));
        int q = i0 >> 3;
        uint32_t base = (uint32_t)(e * 128 + ((q ^ (e & 7)) << 4) + (i0 & 7) * 2);
        *(uint32_t*)(sm + OFF_EFHI + base)     = *reinterpret_cast<uint32_t*>(&h01);
        *(uint32_t*)(sm + OFF_EFHI + base + 4) = *reinterpret_cast<uint32_t*>(&h23);
        *(uint32_t*)(sm + OFF_EFLO + base)     = *reinterpret_cast<uint32_t*>(&l01);
        *(uint32_t*)(sm + OFF_EFLO + base + 4) = *reinterpret_cast<uint32_t*>(&l23);
    }
    sh_bias[tid] = g_bias[conv][tid];
    sh_bias[256 + tid] = g_bias[conv][256 + tid];
    sh_rt[tid] = 0.f;
    sh_rt[256 + tid] = 0.f;
#pragma unroll
    for (int r = 0; r < 8; r++) {
        int p = r * 256 + tid;                  // 2048: t[e][c]
        int e = p >> 5, c = p & 31;
        int m = c >> 1, l = c & 1;
        int sn = __ldg(&src[e0 + e]);
        const float* fr = f + sn * 64 + m * 4;
        const float* b1r = basis1 + (e0 + e) * 8 + l;
        float a = 0.f;
#pragma unroll
        for (int d = 0; d < 4; d++) a += fr[d] * b1r[d * 2];
        sh_t[e * 33 + c] = a;
    }
    asm volatile("cp.async.wait_group 1;" ::: "memory");   // w1t in (chunk0 may still fly? no: group order)
    asm volatile("cp.async.wait_group 0;" ::: "memory");   // both chunk0 + w1t resident
    __syncthreads();

    // ---- h-phase on tensor cores: h = gelu(ef @ w1 + b1), split into A tiles ----
    const int a_row_off = ((lane >> 3) & 1) * 8 + (lane & 7);
    const int a_ksel = (lane >> 4) & 1;
    const int b_n_off = ((lane >> 4) & 1) * 8 + (lane & 7);
    const int b_ksel = (lane >> 3) & 1;
    {
        const float* hbv = conv ? v_b1 : k_b1;
        const int wn = wid * 16;                 // j base (0..112)
        float bj[2][2];
#pragma unroll
        for (int nt = 0; nt < 2; nt++) {
            int j0 = wn + nt * 8 + 2 * l4;
            bj[nt][0] = __ldg(&hbv[j0]);
            bj[nt][1] = __ldg(&hbv[j0 + 1]);
        }
        uint32_t Bh[2][4], Bl[2][4];
#pragma unroll
        for (int kc = 0; kc < 2; kc++) {
            int n = wn + b_n_off;
            int c = kc * 2 + b_ksel;
            uint32_t bd = smem_base + OFF_W1T + (uint32_t)(n * 64 + ((c ^ (n & 3)) << 4));
            ldsm4(bd, Bh[kc]);
            ldsm4(bd + 8192u, Bl[kc]);
        }
        float hacc[4][2][4];
#pragma unroll
        for (int mt = 0; mt < 4; mt++)
#pragma unroll
            for (int nt = 0; nt < 2; nt++)
#pragma unroll
                for (int u = 0; u < 4; u++) hacc[mt][nt][u] = 0.f;
#pragma unroll
        for (int mt = 0; mt < 4; mt++)
#pragma unroll
            for (int kc = 0; kc < 2; kc++) {
                int arow = mt * 16 + a_row_off;
                int c = kc * 2 + a_ksel;
                uint32_t ad = smem_base + OFF_EFHI + (uint32_t)(arow * 128 + ((c ^ (arow & 7)) << 4));
                uint32_t Ah[4], Al[4];
                ldsm4(ad, Ah);
                ldsm4(ad + 8192u, Al);
#pragma unroll
                for (int nt = 0; nt < 2; nt++) {
                    mma16816(hacc[mt][nt], Ah, &Bh[kc][nt * 2]);
                    mma16816(hacc[mt][nt], Al, &Bh[kc][nt * 2]);
                    mma16816(hacc[mt][nt], Ah, &Bl[kc][nt * 2]);
                }
            }
        // gelu + split + store to A tiles
#pragma unroll
        for (int mt = 0; mt < 4; mt++)
#pragma unroll
            for (int nt = 0; nt < 2; nt++) {
                int j0 = wn + nt * 8 + 2 * l4;
                int jc = j0 >> 3;
#pragma unroll
                for (int hrow = 0; hrow < 2; hrow++) {
                    int e = mt * 16 + hrow * 8 + (lane >> 2);
                    float v0 = hacc[mt][nt][hrow * 2]     + bj[nt][0];
                    float v1 = hacc[mt][nt][hrow * 2 + 1] + bj[nt][1];
                    v0 = v0 * normcdff(v0);
                    v1 = v1 * normcdff(v1);
                    __nv_bfloat162 hp = __floats2bfloat162_rn(v0, v1);
                    __nv_bfloat162 lp = __floats2bfloat162_rn(v0 - __bfloat162float(hp.x),
                                                              v1 - __bfloat162float(hp.y));
                    uint32_t addr = (uint32_t)(e * 256 + ((jc ^ (e & 7)) << 4) + (j0 & 7) * 2);
                    *(uint32_t*)(sm + OFF_AHI + addr) = *reinterpret_cast<uint32_t*>(&hp);
                    *(uint32_t*)(sm + OFF_ALO + addr) = *reinterpret_cast<uint32_t*>(&lp);
                }
            }
    }
    __syncthreads();

    // ---- prefetch chunk 1 (nbase 320) into W1 (ef/w1t no longer needed) ----
    load_wchunk(smem_base, OFF_W1, conv, 320, tid);

    // ---- chunk loop: right chunks (cols 256..511) then left (0..255) ----
    const int cn[8] = {256, 320, 384, 448, 0, 64, 128, 192};
    float* sh_t2 = sh_t;

    for (int ci = 0; ci < 8; ci++) {
        if (ci == 7) asm volatile("cp.async.wait_group 0;" ::: "memory");
        else         asm volatile("cp.async.wait_group 1;" ::: "memory");
        __syncthreads();
        const uint32_t wb = smem_base + ((ci & 1) ? OFF_W1 : OFF_W0);

        float acc[2][2][4];
#pragma unroll
        for (int mt = 0; mt < 2; mt++)
#pragma unroll
            for (int nt = 0; nt < 2; nt++)
#pragma unroll
                for (int u = 0; u < 4; u++) acc[mt][nt][u] = 0.f;

#pragma unroll
        for (int ks = 0; ks < 8; ks++) {
            uint32_t Ahi[2][4], Alo[2][4], Bhi[4], Blo[4];
#pragma unroll
            for (int mt = 0; mt < 2; mt++) {
                int arow = wrow + mt * 16 + a_row_off;
                int kc = ks * 2 + a_ksel;
                uint32_t ad = smem_base + (uint32_t)(arow * 256 + ((kc ^ (arow & 7)) << 4));
                ldsm4(ad, Ahi[mt]);
                ldsm4(ad + 16384u, Alo[mt]);
            }
            {
                int n = wcol + b_n_off;
                int kc = ks * 2 + b_ksel;
                uint32_t bd = wb + (uint32_t)(n * 256 + ((kc ^ (n & 7)) << 4));
                ldsm4(bd, Bhi);
                ldsm4(bd + 16384u, Blo);
            }
#pragma unroll
            for (int mt = 0; mt < 2; mt++) {
                mma16816(acc[mt][0], Ahi[mt], &Bhi[0]);
                mma16816(acc[mt][0], Alo[mt], &Bhi[0]);
                mma16816(acc[mt][0], Ahi[mt], &Blo[0]);
                mma16816(acc[mt][1], Ahi[mt], &Bhi[2]);
                mma16816(acc[mt][1], Alo[mt], &Bhi[2]);
                mma16816(acc[mt][1], Ahi[mt], &Blo[2]);
            }
        }

        // ---- per-chunk epilogue ----
        if (ci < 4) {
            const int r = ci * 2 + (wcol >> 5);
#pragma unroll
            for (int mt = 0; mt < 2; mt++)
#pragma unroll
                for (int h2 = 0; h2 < 2; h2++) {
                    int e = wrow + mt * 16 + h2 * 8 + (lane >> 2);
                    float s = 0.f;
#pragma unroll
                    for (int nt = 0; nt < 2; nt++) {
                        int o = 256 + ci * 64 + wcol + nt * 8 + 2 * l4;
                        int c = (ci * 64 + wcol + nt * 8 + 2 * l4) & 31;
                        s += (acc[mt][nt][h2 * 2] + sh_bias[o]) * sh_t[e * 33 + c]
                           + (acc[mt][nt][h2 * 2 + 1] + sh_bias[o + 1]) * sh_t[e * 33 + c + 1];
                    }
                    s += __shfl_xor_sync(0xFFFFFFFFu, s, 1);
                    s += __shfl_xor_sync(0xFFFFFFFFu, s, 2);
                    if (l4 == 0) atomicAdd(&sh_rt[e * 8 + r], s);
                }
        } else {
            const int cli = ci - 4;
#pragma unroll
            for (int mt = 0; mt < 2; mt++)
#pragma unroll
                for (int h2 = 0; h2 < 2; h2++) {
                    int e = wrow + mt * 16 + h2 * 8 + (lane >> 2);
                    float r0 = sh_rt[e * 8 + 2 * l4];
                    float r1 = sh_rt[e * 8 + 2 * l4 + 1];
#pragma unroll
                    for (int nt = 0; nt < 2; nt++) {
                        int o = cli * 64 + wcol + nt * 8 + 2 * l4;
                        float s = (acc[mt][nt][h2 * 2] + sh_bias[o]) * r0
                                + (acc[mt][nt][h2 * 2 + 1] + sh_bias[o + 1]) * r1;
                        s += __shfl_xor_sync(0xFFFFFFFFu, s, 1);
                        s += __shfl_xor_sync(0xFFFFFFFFu, s, 2);
                        if (l4 == 0)
                            sh_t2[e * 33 + cli * 8 + (wcol >> 3) + nt] = s;
                    }
                }
        }
        __syncthreads();
        if (ci < 6)
            load_wchunk(smem_base, (ci & 1) ? OFF_W1 : OFF_W0, conv, cn[ci + 2], tid);
    }
    __syncthreads();

    // ---- final: basis2 contraction → V store / K scores ----
    if (conv == 1) {
#pragma unroll
        for (int rep = 0; rep < 16; rep++) {
            int p = rep * 256 + tid;                 // 4096
            int e = p >> 6, j = p & 63;
            int m = j >> 2, d = j & 3;
            float b2a = basis2[(e0 + e) * 8 + d];
            float b2b = basis2[(e0 + e) * 8 + 4 + d];
            g_v[(e0 + e) * 64 + j] =
                sh_t2[e * 33 + 2 * m] * b2a + sh_t2[e * 33 + 2 * m + 1] * b2b;
        }
    } else {
        int e = tid >> 2, hh = tid & 3;              // 256 = 64*4
        int dn = __ldg(&dst[e0 + e]);
        const float* qr = g_q + dn * 64 + hh * 16;
        float s = 0.f;
#pragma unroll
        for (int m = hh * 4; m < hh * 4 + 4; m++) {
            float ta = sh_t2[e * 33 + 2 * m];
            float tb = sh_t2[e * 33 + 2 * m + 1];
#pragma unroll
            for (int d = 0; d < 4; d++) {
                float kv = ta * basis2[(e0 + e) * 8 + d] + tb * basis2[(e0 + e) * 8 + 4 + d];
                s += qr[(m - hh * 4) * 4 + d] * kv;
            }
        }
        s *= 0.25f;
        g_scores[(e0 + e) * NH + hh] = s;
        atomicMaxFloat(&g_m[dn * NH + hh], s);
    }
}

// ---------------- kernel 3: exp + segment sum ----------------
__global__ void exden_kernel(const int* __restrict__ dst) {
    int p = blockIdx.x * blockDim.x + threadIdx.x;
    if (p >= EE * NH) return;
    int e = p >> 2, hh = p & 3;
    int d = __ldg(&dst[e]);
    float ex = expf(g_scores[p] - g_m[d * NH + hh]);
    g_ex[p] = ex;
    atomicAdd(&g_den[d * NH + hh], ex);
}

// ---------------- kernel 4: weighted scatter of V (vectorized red) ----------------
__global__ void scatter_kernel(const int* __restrict__ dst, float* __restrict__ dout) {
    int p = blockIdx.x * blockDim.x + threadIdx.x;   // EE*4 (edge, head)
    if (p >= EE * NH) return;
    int e = p >> 2, hh = p & 3;
    int d = __ldg(&dst[e]);
    float den = fmaxf(g_den[d * NH + hh], 1e-9f);
    float alpha = g_ex[p] / den;
    const float4* vp = (const float4*)(g_v + (size_t)e * 64 + hh * 16);
    float* op = dout + (size_t)d * 64 + hh * 16;
#pragma unroll
    for (int q = 0; q < 4; q++) {
        float4 v = vp[q];
        asm volatile("red.global.add.v4.f32 [%0], {%1, %2, %3, %4};"
                     :: "l"(op + q * 4),
                        "f"(v.x * alpha), "f"(v.y * alpha),
                        "f"(v.z * alpha), "f"(v.w * alpha)
                     : "memory");
    }
}

// ---------------- launch ----------------
extern "C" void kernel_launch(void* const* d_in, const int* in_sizes, int n_in,
                              void* d_out, int out_size) {
    const float* basis1 = (const float*)d_in[0];
    const float* basis2 = (const float*)d_in[1];
    const float* ef     = (const float*)d_in[2];
    const float* f      = (const float*)d_in[3];
    const int*   src    = (const int*)d_in[4];
    const int*   dst    = (const int*)d_in[5];
    const float* q_w    = (const float*)d_in[6];
    const float* q_b    = (const float*)d_in[7];
    const float* k_w1   = (const float*)d_in[8];
    const float* k_b1   = (const float*)d_in[9];
    const float* k_wl   = (const float*)d_in[10];
    const float* k_bl   = (const float*)d_in[11];
    const float* k_wr   = (const float*)d_in[12];
    const float* k_br   = (const float*)d_in[13];
    const float* v_w1   = (const float*)d_in[14];
    const float* v_b1   = (const float*)d_in[15];
    const float* v_wl   = (const float*)d_in[16];
    const float* v_bl   = (const float*)d_in[17];
    const float* v_wr   = (const float*)d_in[18];
    const float* v_br   = (const float*)d_in[19];
    float* dout = (float*)d_out;

    cudaFuncSetAttribute(conv_mma_kernel, cudaFuncAttributeMaxDynamicSharedMemorySize, SMEM_BYTES);

    presplit_kernel<<<512, 256>>>(k_wl, k_wr, v_wl, v_wr, k_bl, k_br, v_bl, v_br, k_w1, v_w1);
    qinit_kernel<<<(NN * 64 + 255) / 256, 256>>>(f, q_w, q_b, dout);
    conv_mma_kernel<<<dim3(EE / TM, 2), 256, SMEM_BYTES>>>(
        basis1, basis2, ef, f, src, dst, k_b1, v_b1);
    exden_kernel<<<(EE * NH + 255) / 256, 256>>>(dst);
    scatter_kernel<<<(EE * NH + 255) / 256, 256>>>(dst, dout);
}

// round 8
// speedup vs baseline: 3.0184x; 1.1812x over previous
#include <cuda_runtime.h>
#include <cuda_fp16.h>
#include <math_constants.h>
#include <cstdint>

#define NN 10000
#define EE 160000
#define EDIM 32
#define HID 128
#define NH 4
#define TM 64             // edges per block

// ---------------- scratch (static device arrays; no allocation) ----------------
__device__ __half g_wthi[2 * 512 * 128];  // [conv][n][k] fp16-hi of [wl|wr]^T
__device__ __half g_wtlo[2 * 512 * 128];
__device__ __half g_w1hi[2 * 128 * 32];   // [conv][j][i] fp16-hi of w1^T
__device__ __half g_w1lo[2 * 128 * 32];
__device__ float g_bias[2][512];          // [conv][bl(256)|br(256)]
__device__ float g_q[NN * 64];
__device__ float g_v[EE * 64];
__device__ float g_scores[EE * NH];
__device__ float g_ex[EE * NH];
__device__ float g_m[NN * NH];
__device__ float g_den[NN * NH];

__device__ __forceinline__ void atomicMaxFloat(float* addr, float val) {
    if (val >= 0.f) atomicMax((int*)addr, __float_as_int(val));
    else            atomicMin((unsigned int*)addr, __float_as_uint(val));
}
__device__ __forceinline__ uint32_t smem_to_u32(const void* p) {
    uint32_t a;
    asm("{ .reg .u64 t; cvta.to.shared.u64 t, %1; cvt.u32.u64 %0, t; }" : "=r"(a) : "l"(p));
    return a;
}
__device__ __forceinline__ void ldsm4(uint32_t a, uint32_t* r) {
    asm volatile("ldmatrix.sync.aligned.m8n8.x4.shared.b16 {%0,%1,%2,%3}, [%4];"
                 : "=r"(r[0]), "=r"(r[1]), "=r"(r[2]), "=r"(r[3]) : "r"(a));
}
__device__ __forceinline__ void mma16816(float* c, const uint32_t* a, const uint32_t* b) {
    asm volatile("mma.sync.aligned.m16n8k16.row.col.f32.f16.f16.f32 "
                 "{%0,%1,%2,%3}, {%4,%5,%6,%7}, {%8,%9}, {%0,%1,%2,%3};"
                 : "+f"(c[0]), "+f"(c[1]), "+f"(c[2]), "+f"(c[3])
                 : "r"(a[0]), "r"(a[1]), "r"(a[2]), "r"(a[3]), "r"(b[0]), "r"(b[1]));
}
__device__ __forceinline__ void cp16(uint32_t dst, const void* src) {
    asm volatile("cp.async.cg.shared.global [%0], [%1], 16;" :: "r"(dst), "l"(src) : "memory");
}

// ---------------- kernel 0: pre-split weights (fp16 hi/lo, transposed) ----------------
__global__ void presplit_kernel(const float* __restrict__ kwl, const float* __restrict__ kwr,
                                const float* __restrict__ vwl, const float* __restrict__ vwr,
                                const float* __restrict__ kbl, const float* __restrict__ kbr,
                                const float* __restrict__ vbl, const float* __restrict__ vbr,
                                const float* __restrict__ kw1, const float* __restrict__ vw1) {
    int idx = blockIdx.x * blockDim.x + threadIdx.x;   // 131072
    if (idx < 2 * 512 * 128) {
        int conv = idx >> 16;
        int rem = idx & 65535;
        int n = rem >> 7, k = rem & 127;
        const float* w = conv ? (n < 256 ? vwl : vwr) : (n < 256 ? kwl : kwr);
        float val = w[k * 256 + (n & 255)];
        __half hi = __float2half_rn(val);
        g_wthi[idx] = hi;
        g_wtlo[idx] = __float2half_rn(val - __half2float(hi));
    }
    if (idx < 2 * 128 * 32) {                          // w1^T split
        int conv = idx >> 12;
        int rem = idx & 4095;
        int j = rem >> 5, i = rem & 31;
        float val = (conv ? vw1 : kw1)[i * 128 + j];
        __half hi = __float2half_rn(val);
        g_w1hi[idx] = hi;
        g_w1lo[idx] = __float2half_rn(val - __half2float(hi));
    }
    if (idx < 1024) {
        int conv = idx >> 9, j = idx & 511;
        const float* s = conv ? (j < 256 ? vbl : vbr) : (j < 256 ? kbl : kbr);
        g_bias[conv][j] = s[j & 255];
    }
}

// ---------------- kernel 1: Q equivariant linear + init ----------------
__global__ void qinit_kernel(const float* __restrict__ f,
                             const float* __restrict__ qw,
                             const float* __restrict__ qb,
                             float* __restrict__ dout) {
    int p = blockIdx.x * blockDim.x + threadIdx.x;
    if (p < NN * 64) {
        int n = p >> 6, j = p & 63;
        int o = j >> 2, d = j & 3;
        int l = (d == 0) ? 0 : 1;
        float acc = (d == 0) ? qb[o] : 0.f;
        const float* wrow = qw + (l * 16 + o) * 16;
        const float* frow = f + n * 64 + d;
#pragma unroll
        for (int m = 0; m < 16; m++) acc += wrow[m] * frow[m * 4];
        g_q[p] = acc;
        dout[p] = 0.f;
    }
    if (p < NN * NH) { g_m[p] = -CUDART_INF_F; g_den[p] = 0.f; }
}

// ---------------- kernel 2: mma.sync fused conv (occ 2, fp16 2-pass) ----------------
// smem byte offsets
#define OFF_A   0u          // 16384 (64 x 256B) single fp16 A tile
#define OFF_W0  16384u      // 32768 (hi 16K @+0, lo 16K @+16384)
#define OFF_W1  49152u      // 32768; pre-loop: ef 8K | w1t-hi 8K | w1t-lo 8K
#define OFF_T   81920u      // 64*33*4 = 8448 (t; aliased as t2)
#define OFF_RT  90368u      // 64*8*4 = 2048
#define OFF_BIAS 92416u     // 512*4
#define SMEM_BYTES 94464u

#define OFF_EF  (OFF_W1)
#define OFF_W1T (OFF_W1 + 8192u)   // hi 8K, lo at +8192

__device__ __forceinline__ void load_wchunk(uint32_t smem_base, uint32_t bufoff, int conv,
                                            int nbase, int tid) {
#pragma unroll
    for (int ii = 0; ii < 8; ii++) {
        int g = ii * 256 + tid;                 // 0..2047 16B-chunks
        int half_ = g >> 10;                    // 0 hi, 1 lo
        int rem = g & 1023;
        int r = rem >> 4, q = rem & 15;
        const __half* src =
            (half_ ? g_wtlo : g_wthi) + conv * 65536 + (nbase + r) * 128 + q * 8;
        uint32_t dst = smem_base + bufoff + (uint32_t)(half_ * 16384 + r * 256 + ((q ^ (r & 7)) << 4));
        cp16(dst, src);
    }
    asm volatile("cp.async.commit_group;" ::: "memory");
}

__global__ void __launch_bounds__(256, 2)
conv_mma_kernel(const float* __restrict__ basis1, const float* __restrict__ basis2,
                const float* __restrict__ ef, const float* __restrict__ f,
                const int* __restrict__ src, const int* __restrict__ dst,
                const float* __restrict__ k_b1, const float* __restrict__ v_b1) {
    extern __shared__ char sm[];
    const uint32_t smem_base = smem_to_u32(sm);
    const int tid = threadIdx.x;
    const int lane = tid & 31, wid = tid >> 5;
    const int l4 = lane & 3;
    const int wrow = (wid & 1) * 32;            // e base of warp tile (main loop)
    const int wcol = (wid >> 1) * 16;           // n base within 64-col chunk
    const int conv = blockIdx.y;
    const int e0 = blockIdx.x * TM;

    float* sh_t   = (float*)(sm + OFF_T);       // later aliased as t2
    float* sh_rt  = (float*)(sm + OFF_RT);
    float* sh_bias= (float*)(sm + OFF_BIAS);

    // ---- prefetch chunk 0 (nbase 256) into W0; w1t tiles into W1 upper ----
    load_wchunk(smem_base, OFF_W0, conv, 256, tid);
#pragma unroll
    for (int r = 0; r < 4; r++) {
        int g = r * 256 + tid;                  // 1024: (half, n, q)
        int half_ = g >> 9;
        int rem = g & 511;
        int n = rem >> 2, q = rem & 3;
        const __half* srcp =
            (half_ ? g_w1lo : g_w1hi) + conv * 4096 + n * 32 + q * 8;
        uint32_t dstp = smem_base + OFF_W1T + (uint32_t)(half_ * 8192 + n * 64 + ((q ^ (n & 3)) << 4));
        cp16(dstp, srcp);
    }
    asm volatile("cp.async.commit_group;" ::: "memory");

    // ---- stage ef (fp32 -> fp16 tiles), bias; zero rt; compute t ----
#pragma unroll
    for (int r = 0; r < 2; r++) {
        int idx = r * 256 + tid;                // 512 float4s
        int e = idx >> 3, i0 = (idx & 7) * 4;
        float4 v = ((const float4*)(ef + (size_t)e0 * EDIM))[idx];
        __half2 h01 = __floats2half2_rn(v.x, v.y);
        __half2 h23 = __floats2half2_rn(v.z, v.w);
        int q = i0 >> 3;
        uint32_t base = (uint32_t)(e * 128 + ((q ^ (e & 7)) << 4) + (i0 & 7) * 2);
        *(uint32_t*)(sm + OFF_EF + base)     = *reinterpret_cast<uint32_t*>(&h01);
        *(uint32_t*)(sm + OFF_EF + base + 4) = *reinterpret_cast<uint32_t*>(&h23);
    }
    sh_bias[tid] = g_bias[conv][tid];
    sh_bias[256 + tid] = g_bias[conv][256 + tid];
    sh_rt[tid] = 0.f;
    sh_rt[256 + tid] = 0.f;
#pragma unroll
    for (int r = 0; r < 8; r++) {
        int p = r * 256 + tid;                  // 2048: t[e][c]
        int e = p >> 5, c = p & 31;
        int m = c >> 1, l = c & 1;
        int sn = __ldg(&src[e0 + e]);
        const float* fr = f + sn * 64 + m * 4;
        const float* b1r = basis1 + (e0 + e) * 8 + l;
        float a = 0.f;
#pragma unroll
        for (int d = 0; d < 4; d++) a += fr[d] * b1r[d * 2];
        sh_t[e * 33 + c] = a;
    }
    asm volatile("cp.async.wait_group 0;" ::: "memory");   // chunk0 + w1t resident
    __syncthreads();

    // ---- h-phase on tensor cores: h = gelu(ef @ w1 + b1) -> fp16 A tile ----
    const int a_row_off = ((lane >> 3) & 1) * 8 + (lane & 7);
    const int a_ksel = (lane >> 4) & 1;
    const int b_n_off = ((lane >> 4) & 1) * 8 + (lane & 7);
    const int b_ksel = (lane >> 3) & 1;
    {
        const float* hbv = conv ? v_b1 : k_b1;
        const int wn = wid * 16;                 // j base (0..112)
        float bj[2][2];
#pragma unroll
        for (int nt = 0; nt < 2; nt++) {
            int j0 = wn + nt * 8 + 2 * l4;
            bj[nt][0] = __ldg(&hbv[j0]);
            bj[nt][1] = __ldg(&hbv[j0 + 1]);
        }
        uint32_t Bh[2][4], Bl[2][4];
#pragma unroll
        for (int kc = 0; kc < 2; kc++) {
            int n = wn + b_n_off;
            int c = kc * 2 + b_ksel;
            uint32_t bd = smem_base + OFF_W1T + (uint32_t)(n * 64 + ((c ^ (n & 3)) << 4));
            ldsm4(bd, Bh[kc]);
            ldsm4(bd + 8192u, Bl[kc]);
        }
        float hacc[4][2][4];
#pragma unroll
        for (int mt = 0; mt < 4; mt++)
#pragma unroll
            for (int nt = 0; nt < 2; nt++)
#pragma unroll
                for (int u = 0; u < 4; u++) hacc[mt][nt][u] = 0.f;
#pragma unroll
        for (int mt = 0; mt < 4; mt++)
#pragma unroll
            for (int kc = 0; kc < 2; kc++) {
                int arow = mt * 16 + a_row_off;
                int c = kc * 2 + a_ksel;
                uint32_t ad = smem_base + OFF_EF + (uint32_t)(arow * 128 + ((c ^ (arow & 7)) << 4));
                uint32_t Ah[4];
                ldsm4(ad, Ah);
#pragma unroll
                for (int nt = 0; nt < 2; nt++) {
                    mma16816(hacc[mt][nt], Ah, &Bh[kc][nt * 2]);
                    mma16816(hacc[mt][nt], Ah, &Bl[kc][nt * 2]);
                }
            }
        // gelu + store to fp16 A tile
#pragma unroll
        for (int mt = 0; mt < 4; mt++)
#pragma unroll
            for (int nt = 0; nt < 2; nt++) {
                int j0 = wn + nt * 8 + 2 * l4;
                int jc = j0 >> 3;
#pragma unroll
                for (int hrow = 0; hrow < 2; hrow++) {
                    int e = mt * 16 + hrow * 8 + (lane >> 2);
                    float v0 = hacc[mt][nt][hrow * 2]     + bj[nt][0];
                    float v1 = hacc[mt][nt][hrow * 2 + 1] + bj[nt][1];
                    v0 = v0 * normcdff(v0);
                    v1 = v1 * normcdff(v1);
                    __half2 hp = __floats2half2_rn(v0, v1);
                    uint32_t addr = (uint32_t)(e * 256 + ((jc ^ (e & 7)) << 4) + (j0 & 7) * 2);
                    *(uint32_t*)(sm + OFF_A + addr) = *reinterpret_cast<uint32_t*>(&hp);
                }
            }
    }
    __syncthreads();

    // ---- prefetch chunk 1 (nbase 320) into W1 (ef/w1t no longer needed) ----
    load_wchunk(smem_base, OFF_W1, conv, 320, tid);

    // ---- chunk loop: right chunks (cols 256..511) then left (0..255) ----
    const int cn[8] = {256, 320, 384, 448, 0, 64, 128, 192};
    float* sh_t2 = sh_t;

    for (int ci = 0; ci < 8; ci++) {
        if (ci == 7) asm volatile("cp.async.wait_group 0;" ::: "memory");
        else         asm volatile("cp.async.wait_group 1;" ::: "memory");
        __syncthreads();
        const uint32_t wb = smem_base + ((ci & 1) ? OFF_W1 : OFF_W0);

        float acc[2][2][4];
#pragma unroll
        for (int mt = 0; mt < 2; mt++)
#pragma unroll
            for (int nt = 0; nt < 2; nt++)
#pragma unroll
                for (int u = 0; u < 4; u++) acc[mt][nt][u] = 0.f;

#pragma unroll
        for (int ks = 0; ks < 8; ks++) {
            uint32_t A[2][4], Bhi[4], Blo[4];
#pragma unroll
            for (int mt = 0; mt < 2; mt++) {
                int arow = wrow + mt * 16 + a_row_off;
                int kc = ks * 2 + a_ksel;
                uint32_t ad = smem_base + OFF_A + (uint32_t)(arow * 256 + ((kc ^ (arow & 7)) << 4));
                ldsm4(ad, A[mt]);
            }
            {
                int n = wcol + b_n_off;
                int kc = ks * 2 + b_ksel;
                uint32_t bd = wb + (uint32_t)(n * 256 + ((kc ^ (n & 7)) << 4));
                ldsm4(bd, Bhi);
                ldsm4(bd + 16384u, Blo);
            }
#pragma unroll
            for (int mt = 0; mt < 2; mt++) {
                mma16816(acc[mt][0], A[mt], &Bhi[0]);
                mma16816(acc[mt][0], A[mt], &Blo[0]);
                mma16816(acc[mt][1], A[mt], &Bhi[2]);
                mma16816(acc[mt][1], A[mt], &Blo[2]);
            }
        }

        // ---- per-chunk epilogue ----
        if (ci < 4) {
            const int r = ci * 2 + (wcol >> 5);
#pragma unroll
            for (int mt = 0; mt < 2; mt++)
#pragma unroll
                for (int h2 = 0; h2 < 2; h2++) {
                    int e = wrow + mt * 16 + h2 * 8 + (lane >> 2);
                    float s = 0.f;
#pragma unroll
                    for (int nt = 0; nt < 2; nt++) {
                        int o = 256 + ci * 64 + wcol + nt * 8 + 2 * l4;
                        int c = (ci * 64 + wcol + nt * 8 + 2 * l4) & 31;
                        s += (acc[mt][nt][h2 * 2] + sh_bias[o]) * sh_t[e * 33 + c]
                           + (acc[mt][nt][h2 * 2 + 1] + sh_bias[o + 1]) * sh_t[e * 33 + c + 1];
                    }
                    s += __shfl_xor_sync(0xFFFFFFFFu, s, 1);
                    s += __shfl_xor_sync(0xFFFFFFFFu, s, 2);
                    if (l4 == 0) atomicAdd(&sh_rt[e * 8 + r], s);
                }
        } else {
            const int cli = ci - 4;
#pragma unroll
            for (int mt = 0; mt < 2; mt++)
#pragma unroll
                for (int h2 = 0; h2 < 2; h2++) {
                    int e = wrow + mt * 16 + h2 * 8 + (lane >> 2);
                    float r0 = sh_rt[e * 8 + 2 * l4];
                    float r1 = sh_rt[e * 8 + 2 * l4 + 1];
#pragma unroll
                    for (int nt = 0; nt < 2; nt++) {
                        int o = cli * 64 + wcol + nt * 8 + 2 * l4;
                        float s = (acc[mt][nt][h2 * 2] + sh_bias[o]) * r0
                                + (acc[mt][nt][h2 * 2 + 1] + sh_bias[o + 1]) * r1;
                        s += __shfl_xor_sync(0xFFFFFFFFu, s, 1);
                        s += __shfl_xor_sync(0xFFFFFFFFu, s, 2);
                        if (l4 == 0)
                            sh_t2[e * 33 + cli * 8 + (wcol >> 3) + nt] = s;
                    }
                }
        }
        __syncthreads();
        if (ci < 6)
            load_wchunk(smem_base, (ci & 1) ? OFF_W1 : OFF_W0, conv, cn[ci + 2], tid);
    }
    __syncthreads();

    // ---- final: basis2 contraction → V store / K scores ----
    if (conv == 1) {
#pragma unroll
        for (int rep = 0; rep < 16; rep++) {
            int p = rep * 256 + tid;                 // 4096
            int e = p >> 6, j = p & 63;
            int m = j >> 2, d = j & 3;
            float b2a = basis2[(e0 + e) * 8 + d];
            float b2b = basis2[(e0 + e) * 8 + 4 + d];
            g_v[(e0 + e) * 64 + j] =
                sh_t2[e * 33 + 2 * m] * b2a + sh_t2[e * 33 + 2 * m + 1] * b2b;
        }
    } else {
        int e = tid >> 2, hh = tid & 3;              // 256 = 64*4
        int dn = __ldg(&dst[e0 + e]);
        const float* qr = g_q + dn * 64 + hh * 16;
        float s = 0.f;
#pragma unroll
        for (int m = hh * 4; m < hh * 4 + 4; m++) {
            float ta = sh_t2[e * 33 + 2 * m];
            float tb = sh_t2[e * 33 + 2 * m + 1];
#pragma unroll
            for (int d = 0; d < 4; d++) {
                float kv = ta * basis2[(e0 + e) * 8 + d] + tb * basis2[(e0 + e) * 8 + 4 + d];
                s += qr[(m - hh * 4) * 4 + d] * kv;
            }
        }
        s *= 0.25f;
        g_scores[(e0 + e) * NH + hh] = s;
        atomicMaxFloat(&g_m[dn * NH + hh], s);
    }
}

// ---------------- kernel 3: exp + segment sum ----------------
__global__ void exden_kernel(const int* __restrict__ dst) {
    int p = blockIdx.x * blockDim.x + threadIdx.x;
    if (p >= EE * NH) return;
    int e = p >> 2, hh = p & 3;
    int d = __ldg(&dst[e]);
    float ex = expf(g_scores[p] - g_m[d * NH + hh]);
    g_ex[p] = ex;
    atomicAdd(&g_den[d * NH + hh], ex);
}

// ---------------- kernel 4: weighted scatter of V (vectorized red) ----------------
__global__ void scatter_kernel(const int* __restrict__ dst, float* __restrict__ dout) {
    int p = blockIdx.x * blockDim.x + threadIdx.x;   // EE*4 (edge, head)
    if (p >= EE * NH) return;
    int e = p >> 2, hh = p & 3;
    int d = __ldg(&dst[e]);
    float den = fmaxf(g_den[d * NH + hh], 1e-9f);
    float alpha = g_ex[p] / den;
    const float4* vp = (const float4*)(g_v + (size_t)e * 64 + hh * 16);
    float* op = dout + (size_t)d * 64 + hh * 16;
#pragma unroll
    for (int q = 0; q < 4; q++) {
        float4 v = vp[q];
        asm volatile("red.global.add.v4.f32 [%0], {%1, %2, %3, %4};"
                     :: "l"(op + q * 4),
                        "f"(v.x * alpha), "f"(v.y * alpha),
                        "f"(v.z * alpha), "f"(v.w * alpha)
                     : "memory");
    }
}

// ---------------- launch ----------------
extern "C" void kernel_launch(void* const* d_in, const int* in_sizes, int n_in,
                              void* d_out, int out_size) {
    const float* basis1 = (const float*)d_in[0];
    const float* basis2 = (const float*)d_in[1];
    const float* ef     = (const float*)d_in[2];
    const float* f      = (const float*)d_in[3];
    const int*   src    = (const int*)d_in[4];
    const int*   dst    = (const int*)d_in[5];
    const float* q_w    = (const float*)d_in[6];
    const float* q_b    = (const float*)d_in[7];
    const float* k_w1   = (const float*)d_in[8];
    const float* k_b1   = (const float*)d_in[9];
    const float* k_wl   = (const float*)d_in[10];
    const float* k_bl   = (const float*)d_in[11];
    const float* k_wr   = (const float*)d_in[12];
    const float* k_br   = (const float*)d_in[13];
    const float* v_w1   = (const float*)d_in[14];
    const float* v_b1   = (const float*)d_in[15];
    const float* v_wl   = (const float*)d_in[16];
    const float* v_bl   = (const float*)d_in[17];
    const float* v_wr   = (const float*)d_in[18];
    const float* v_br   = (const float*)d_in[19];
    float* dout = (float*)d_out;

    cudaFuncSetAttribute(conv_mma_kernel, cudaFuncAttributeMaxDynamicSharedMemorySize, SMEM_BYTES);

    presplit_kernel<<<512, 256>>>(k_wl, k_wr, v_wl, v_wr, k_bl, k_br, v_bl, v_br, k_w1, v_w1);
    qinit_kernel<<<(NN * 64 + 255) / 256, 256>>>(f, q_w, q_b, dout);
    conv_mma_kernel<<<dim3(EE / TM, 2), 256, SMEM_BYTES>>>(
        basis1, basis2, ef, f, src, dst, k_b1, v_b1);
    exden_kernel<<<(EE * NH + 255) / 256, 256>>>(dst);
    scatter_kernel<<<(EE * NH + 255) / 256, 256>>>(dst, dout);
}

// round 9
// speedup vs baseline: 3.0839x; 1.0217x over previous
#include <cuda_runtime.h>
#include <cuda_fp16.h>
#include <math_constants.h>
#include <cstdint>

#define NN 10000
#define EE 160000
#define EDIM 32
#define HID 128
#define NH 4
#define TM 64             // edges per block

// ---------------- scratch (static device arrays; no allocation) ----------------
__device__ __half g_wthi[2 * 512 * 128];  // [conv][n][k] fp16-hi of [wl|wr]^T
__device__ __half g_wtlo[2 * 512 * 128];
__device__ __half g_w1hi[2 * 128 * 32];   // [conv][j][i] fp16-hi of w1^T
__device__ __half g_w1lo[2 * 128 * 32];
__device__ float g_bias[2][512];          // [conv][bl(256)|br(256)]
__device__ float g_q[NN * 64];
__device__ float g_ex[EE * NH];
__device__ float g_den[NN * NH];

__device__ __forceinline__ uint32_t smem_to_u32(const void* p) {
    uint32_t a;
    asm("{ .reg .u64 t; cvta.to.shared.u64 t, %1; cvt.u32.u64 %0, t; }" : "=r"(a) : "l"(p));
    return a;
}
__device__ __forceinline__ void ldsm4(uint32_t a, uint32_t* r) {
    asm volatile("ldmatrix.sync.aligned.m8n8.x4.shared.b16 {%0,%1,%2,%3}, [%4];"
                 : "=r"(r[0]), "=r"(r[1]), "=r"(r[2]), "=r"(r[3]) : "r"(a));
}
__device__ __forceinline__ void mma16816(float* c, const uint32_t* a, const uint32_t* b) {
    asm volatile("mma.sync.aligned.m16n8k16.row.col.f32.f16.f16.f32 "
                 "{%0,%1,%2,%3}, {%4,%5,%6,%7}, {%8,%9}, {%0,%1,%2,%3};"
                 : "+f"(c[0]), "+f"(c[1]), "+f"(c[2]), "+f"(c[3])
                 : "r"(a[0]), "r"(a[1]), "r"(a[2]), "r"(a[3]), "r"(b[0]), "r"(b[1]));
}
__device__ __forceinline__ void cp16(uint32_t dst, const void* src) {
    asm volatile("cp.async.cg.shared.global [%0], [%1], 16;" :: "r"(dst), "l"(src) : "memory");
}

// ---------------- kernel 0: pre-split weights (fp16 hi/lo, transposed) ----------------
__global__ void presplit_kernel(const float* __restrict__ kwl, const float* __restrict__ kwr,
                                const float* __restrict__ vwl, const float* __restrict__ vwr,
                                const float* __restrict__ kbl, const float* __restrict__ kbr,
                                const float* __restrict__ vbl, const float* __restrict__ vbr,
                                const float* __restrict__ kw1, const float* __restrict__ vw1) {
    int idx = blockIdx.x * blockDim.x + threadIdx.x;   // 131072
    if (idx < 2 * 512 * 128) {
        int conv = idx >> 16;
        int rem = idx & 65535;
        int n = rem >> 7, k = rem & 127;
        const float* w = conv ? (n < 256 ? vwl : vwr) : (n < 256 ? kwl : kwr);
        float val = w[k * 256 + (n & 255)];
        __half hi = __float2half_rn(val);
        g_wthi[idx] = hi;
        g_wtlo[idx] = __float2half_rn(val - __half2float(hi));
    }
    if (idx < 2 * 128 * 32) {                          // w1^T split
        int conv = idx >> 12;
        int rem = idx & 4095;
        int j = rem >> 5, i = rem & 31;
        float val = (conv ? vw1 : kw1)[i * 128 + j];
        __half hi = __float2half_rn(val);
        g_w1hi[idx] = hi;
        g_w1lo[idx] = __float2half_rn(val - __half2float(hi));
    }
    if (idx < 1024) {
        int conv = idx >> 9, j = idx & 511;
        const float* s = conv ? (j < 256 ? vbl : vbr) : (j < 256 ? kbl : kbr);
        g_bias[conv][j] = s[j & 255];
    }
}

// ---------------- kernel 1: Q equivariant linear + init ----------------
__global__ void qinit_kernel(const float* __restrict__ f,
                             const float* __restrict__ qw,
                             const float* __restrict__ qb,
                             float* __restrict__ dout) {
    int p = blockIdx.x * blockDim.x + threadIdx.x;
    if (p < NN * 64) {
        int n = p >> 6, j = p & 63;
        int o = j >> 2, d = j & 3;
        int l = (d == 0) ? 0 : 1;
        float acc = (d == 0) ? qb[o] : 0.f;
        const float* wrow = qw + (l * 16 + o) * 16;
        const float* frow = f + n * 64 + d;
#pragma unroll
        for (int m = 0; m < 16; m++) acc += wrow[m] * frow[m * 4];
        g_q[p] = acc;
        dout[p] = 0.f;
    }
    if (p < NN * NH) g_den[p] = 0.f;
}

// ---------------- kernel 2: mma.sync fused conv (occ 2, fp16 2-pass) ----------------
// smem byte offsets
#define OFF_A   0u          // 16384 (64 x 256B) single fp16 A tile
#define OFF_W0  16384u      // 32768 (hi 16K @+0, lo 16K @+16384)
#define OFF_W1  49152u      // 32768; pre-loop: ef 8K | w1t-hi 8K | w1t-lo 8K
#define OFF_T   81920u      // 64*33*4 = 8448 (t; aliased as t2)
#define OFF_RT  90368u      // 64*8*4 = 2048
#define OFF_BIAS 92416u     // 512*4 (reused as alpha/dn in V final)
#define SMEM_BYTES 94464u

#define OFF_EF  (OFF_W1)
#define OFF_W1T (OFF_W1 + 8192u)   // hi 8K, lo at +8192

__device__ __forceinline__ void load_wchunk(uint32_t smem_base, uint32_t bufoff, int conv,
                                            int nbase, int tid) {
#pragma unroll
    for (int ii = 0; ii < 8; ii++) {
        int g = ii * 256 + tid;                 // 0..2047 16B-chunks
        int half_ = g >> 10;                    // 0 hi, 1 lo
        int rem = g & 1023;
        int r = rem >> 4, q = rem & 15;
        const __half* src =
            (half_ ? g_wtlo : g_wthi) + conv * 65536 + (nbase + r) * 128 + q * 8;
        uint32_t dst = smem_base + bufoff + (uint32_t)(half_ * 16384 + r * 256 + ((q ^ (r & 7)) << 4));
        cp16(dst, src);
    }
    asm volatile("cp.async.commit_group;" ::: "memory");
}

__global__ void __launch_bounds__(256, 2)
conv_mma_kernel(const float* __restrict__ basis1, const float* __restrict__ basis2,
                const float* __restrict__ ef, const float* __restrict__ f,
                const int* __restrict__ src, const int* __restrict__ dst,
                const float* __restrict__ k_b1, const float* __restrict__ v_b1,
                float* __restrict__ dout, int conv) {
    extern __shared__ char sm[];
    const uint32_t smem_base = smem_to_u32(sm);
    const int tid = threadIdx.x;
    const int lane = tid & 31, wid = tid >> 5;
    const int l4 = lane & 3;
    const int wrow = (wid & 1) * 32;            // e base of warp tile (main loop)
    const int wcol = (wid >> 1) * 16;           // n base within 64-col chunk
    const int e0 = blockIdx.x * TM;

    float* sh_t   = (float*)(sm + OFF_T);       // later aliased as t2
    float* sh_rt  = (float*)(sm + OFF_RT);
    float* sh_bias= (float*)(sm + OFF_BIAS);

    // ---- prefetch chunk 0 (nbase 256) into W0; w1t tiles into W1 upper ----
    load_wchunk(smem_base, OFF_W0, conv, 256, tid);
#pragma unroll
    for (int r = 0; r < 4; r++) {
        int g = r * 256 + tid;                  // 1024: (half, n, q)
        int half_ = g >> 9;
        int rem = g & 511;
        int n = rem >> 2, q = rem & 3;
        const __half* srcp =
            (half_ ? g_w1lo : g_w1hi) + conv * 4096 + n * 32 + q * 8;
        uint32_t dstp = smem_base + OFF_W1T + (uint32_t)(half_ * 8192 + n * 64 + ((q ^ (n & 3)) << 4));
        cp16(dstp, srcp);
    }
    asm volatile("cp.async.commit_group;" ::: "memory");

    // ---- stage ef (fp32 -> fp16 tiles), bias; zero rt; compute t ----
#pragma unroll
    for (int r = 0; r < 2; r++) {
        int idx = r * 256 + tid;                // 512 float4s
        int e = idx >> 3, i0 = (idx & 7) * 4;
        float4 v = ((const float4*)(ef + (size_t)e0 * EDIM))[idx];
        __half2 h01 = __floats2half2_rn(v.x, v.y);
        __half2 h23 = __floats2half2_rn(v.z, v.w);
        int q = i0 >> 3;
        uint32_t base = (uint32_t)(e * 128 + ((q ^ (e & 7)) << 4) + (i0 & 7) * 2);
        *(uint32_t*)(sm + OFF_EF + base)     = *reinterpret_cast<uint32_t*>(&h01);
        *(uint32_t*)(sm + OFF_EF + base + 4) = *reinterpret_cast<uint32_t*>(&h23);
    }
    sh_bias[tid] = g_bias[conv][tid];
    sh_bias[256 + tid] = g_bias[conv][256 + tid];
    sh_rt[tid] = 0.f;
    sh_rt[256 + tid] = 0.f;
#pragma unroll
    for (int r = 0; r < 8; r++) {
        int p = r * 256 + tid;                  // 2048: t[e][c]
        int e = p >> 5, c = p & 31;
        int m = c >> 1, l = c & 1;
        int sn = __ldg(&src[e0 + e]);
        float4 fv = *reinterpret_cast<const float4*>(f + (size_t)sn * 64 + m * 4);
        float4 b1a = *reinterpret_cast<const float4*>(basis1 + (size_t)(e0 + e) * 8);
        float4 b1b = *reinterpret_cast<const float4*>(basis1 + (size_t)(e0 + e) * 8 + 4);
        float a;
        if (l == 0)
            a = fv.x * b1a.x + fv.y * b1a.z + fv.z * b1b.x + fv.w * b1b.z;
        else
            a = fv.x * b1a.y + fv.y * b1a.w + fv.z * b1b.y + fv.w * b1b.w;
        sh_t[e * 33 + c] = a;
    }
    asm volatile("cp.async.wait_group 0;" ::: "memory");   // chunk0 + w1t resident
    __syncthreads();

    // ---- h-phase on tensor cores: h = gelu(ef @ w1 + b1) -> fp16 A tile ----
    const int a_row_off = ((lane >> 3) & 1) * 8 + (lane & 7);
    const int a_ksel = (lane >> 4) & 1;
    const int b_n_off = ((lane >> 4) & 1) * 8 + (lane & 7);
    const int b_ksel = (lane >> 3) & 1;
    {
        const float* hbv = conv ? v_b1 : k_b1;
        const int wn = wid * 16;                 // j base (0..112)
        float bj[2][2];
#pragma unroll
        for (int nt = 0; nt < 2; nt++) {
            int j0 = wn + nt * 8 + 2 * l4;
            bj[nt][0] = __ldg(&hbv[j0]);
            bj[nt][1] = __ldg(&hbv[j0 + 1]);
        }
        uint32_t Bh[2][4], Bl[2][4];
#pragma unroll
        for (int kc = 0; kc < 2; kc++) {
            int n = wn + b_n_off;
            int c = kc * 2 + b_ksel;
            uint32_t bd = smem_base + OFF_W1T + (uint32_t)(n * 64 + ((c ^ (n & 3)) << 4));
            ldsm4(bd, Bh[kc]);
            ldsm4(bd + 8192u, Bl[kc]);
        }
        float hacc[4][2][4];
#pragma unroll
        for (int mt = 0; mt < 4; mt++)
#pragma unroll
            for (int nt = 0; nt < 2; nt++)
#pragma unroll
                for (int u = 0; u < 4; u++) hacc[mt][nt][u] = 0.f;
#pragma unroll
        for (int mt = 0; mt < 4; mt++)
#pragma unroll
            for (int kc = 0; kc < 2; kc++) {
                int arow = mt * 16 + a_row_off;
                int c = kc * 2 + a_ksel;
                uint32_t ad = smem_base + OFF_EF + (uint32_t)(arow * 128 + ((c ^ (arow & 7)) << 4));
                uint32_t Ah[4];
                ldsm4(ad, Ah);
#pragma unroll
                for (int nt = 0; nt < 2; nt++) {
                    mma16816(hacc[mt][nt], Ah, &Bh[kc][nt * 2]);
                    mma16816(hacc[mt][nt], Ah, &Bl[kc][nt * 2]);
                }
            }
        // gelu + store to fp16 A tile
#pragma unroll
        for (int mt = 0; mt < 4; mt++)
#pragma unroll
            for (int nt = 0; nt < 2; nt++) {
                int j0 = wn + nt * 8 + 2 * l4;
                int jc = j0 >> 3;
#pragma unroll
                for (int hrow = 0; hrow < 2; hrow++) {
                    int e = mt * 16 + hrow * 8 + (lane >> 2);
                    float v0 = hacc[mt][nt][hrow * 2]     + bj[nt][0];
                    float v1 = hacc[mt][nt][hrow * 2 + 1] + bj[nt][1];
                    v0 = v0 * normcdff(v0);
                    v1 = v1 * normcdff(v1);
                    __half2 hp = __floats2half2_rn(v0, v1);
                    uint32_t addr = (uint32_t)(e * 256 + ((jc ^ (e & 7)) << 4) + (j0 & 7) * 2);
                    *(uint32_t*)(sm + OFF_A + addr) = *reinterpret_cast<uint32_t*>(&hp);
                }
            }
    }
    __syncthreads();

    // ---- prefetch chunk 1 (nbase 320) into W1 (ef/w1t no longer needed) ----
    load_wchunk(smem_base, OFF_W1, conv, 320, tid);

    // ---- chunk loop: right chunks (cols 256..511) then left (0..255) ----
    const int cn[8] = {256, 320, 384, 448, 0, 64, 128, 192};
    float* sh_t2 = sh_t;

    for (int ci = 0; ci < 8; ci++) {
        if (ci == 7) asm volatile("cp.async.wait_group 0;" ::: "memory");
        else         asm volatile("cp.async.wait_group 1;" ::: "memory");
        __syncthreads();
        const uint32_t wb = smem_base + ((ci & 1) ? OFF_W1 : OFF_W0);

        float acc[2][2][4];
#pragma unroll
        for (int mt = 0; mt < 2; mt++)
#pragma unroll
            for (int nt = 0; nt < 2; nt++)
#pragma unroll
                for (int u = 0; u < 4; u++) acc[mt][nt][u] = 0.f;

#pragma unroll
        for (int ks = 0; ks < 8; ks++) {
            uint32_t A[2][4], Bhi[4], Blo[4];
#pragma unroll
            for (int mt = 0; mt < 2; mt++) {
                int arow = wrow + mt * 16 + a_row_off;
                int kc = ks * 2 + a_ksel;
                uint32_t ad = smem_base + OFF_A + (uint32_t)(arow * 256 + ((kc ^ (arow & 7)) << 4));
                ldsm4(ad, A[mt]);
            }
            {
                int n = wcol + b_n_off;
                int kc = ks * 2 + b_ksel;
                uint32_t bd = wb + (uint32_t)(n * 256 + ((kc ^ (n & 7)) << 4));
                ldsm4(bd, Bhi);
                ldsm4(bd + 16384u, Blo);
            }
#pragma unroll
            for (int mt = 0; mt < 2; mt++) {
                mma16816(acc[mt][0], A[mt], &Bhi[0]);
                mma16816(acc[mt][0], A[mt], &Blo[0]);
                mma16816(acc[mt][1], A[mt], &Bhi[2]);
                mma16816(acc[mt][1], A[mt], &Blo[2]);
            }
        }
        __syncthreads();                        // all warps done reading this W buffer
        if (ci < 6)
            load_wchunk(smem_base, (ci & 1) ? OFF_W1 : OFF_W0, conv, cn[ci + 2], tid);

        // ---- per-chunk epilogue (overlaps with cp.async above) ----
        if (ci < 4) {
            const int r = ci * 2 + (wcol >> 5);
#pragma unroll
            for (int mt = 0; mt < 2; mt++)
#pragma unroll
                for (int h2 = 0; h2 < 2; h2++) {
                    int e = wrow + mt * 16 + h2 * 8 + (lane >> 2);
                    float s = 0.f;
#pragma unroll
                    for (int nt = 0; nt < 2; nt++) {
                        int o = 256 + ci * 64 + wcol + nt * 8 + 2 * l4;
                        int c = (ci * 64 + wcol + nt * 8 + 2 * l4) & 31;
                        s += (acc[mt][nt][h2 * 2] + sh_bias[o]) * sh_t[e * 33 + c]
                           + (acc[mt][nt][h2 * 2 + 1] + sh_bias[o + 1]) * sh_t[e * 33 + c + 1];
                    }
                    s += __shfl_xor_sync(0xFFFFFFFFu, s, 1);
                    s += __shfl_xor_sync(0xFFFFFFFFu, s, 2);
                    if (l4 == 0) atomicAdd(&sh_rt[e * 8 + r], s);
                }
        } else {
            const int cli = ci - 4;
#pragma unroll
            for (int mt = 0; mt < 2; mt++)
#pragma unroll
                for (int h2 = 0; h2 < 2; h2++) {
                    int e = wrow + mt * 16 + h2 * 8 + (lane >> 2);
                    float r0 = sh_rt[e * 8 + 2 * l4];
                    float r1 = sh_rt[e * 8 + 2 * l4 + 1];
#pragma unroll
                    for (int nt = 0; nt < 2; nt++) {
                        int o = cli * 64 + wcol + nt * 8 + 2 * l4;
                        float s = (acc[mt][nt][h2 * 2] + sh_bias[o]) * r0
                                + (acc[mt][nt][h2 * 2 + 1] + sh_bias[o + 1]) * r1;
                        s += __shfl_xor_sync(0xFFFFFFFFu, s, 1);
                        s += __shfl_xor_sync(0xFFFFFFFFu, s, 2);
                        if (l4 == 0)
                            sh_t2[e * 33 + cli * 8 + (wcol >> 3) + nt] = s;
                    }
                }
        }
    }
    __syncthreads();

    // ---- final phase ----
    if (conv == 0) {
        // K: scores -> exp (no max pass; scores are O(1)) -> segment denominator
        int e = tid >> 2, hh = tid & 3;              // 256 = 64*4
        int dn = __ldg(&dst[e0 + e]);
        const float* qr = g_q + dn * 64 + hh * 16;
        float s = 0.f;
#pragma unroll
        for (int m = hh * 4; m < hh * 4 + 4; m++) {
            float ta = sh_t2[e * 33 + 2 * m];
            float tb = sh_t2[e * 33 + 2 * m + 1];
#pragma unroll
            for (int d = 0; d < 4; d++) {
                float kv = ta * basis2[(size_t)(e0 + e) * 8 + d] + tb * basis2[(size_t)(e0 + e) * 8 + 4 + d];
                s += qr[(m - hh * 4) * 4 + d] * kv;
            }
        }
        float ex = expf(s * 0.25f);
        g_ex[(size_t)(e0 + e) * NH + hh] = ex;
        atomicAdd(&g_den[dn * NH + hh], ex);
    } else {
        // V: fused weighted scatter — alpha*v straight to dout via red.v4
        float* sh_alpha = sh_bias;                   // reuse (bias dead)
        int*   sh_dn    = (int*)(sh_bias + 256);
        {
            int e = tid >> 2, hh = tid & 3;
            int dn = __ldg(&dst[e0 + e]);
            if (hh == 0) sh_dn[e] = dn;
            float den = fmaxf(g_den[dn * NH + hh], 1e-9f);
            sh_alpha[tid] = g_ex[(size_t)(e0 + e) * NH + hh] / den;
        }
        __syncthreads();
#pragma unroll
        for (int r = 0; r < 4; r++) {
            int p = r * 256 + tid;                   // 1024 float4 groups
            int e = p >> 4, m = p & 15;
            int hh = m >> 2;
            float4 b2a = *reinterpret_cast<const float4*>(basis2 + (size_t)(e0 + e) * 8);
            float4 b2b = *reinterpret_cast<const float4*>(basis2 + (size_t)(e0 + e) * 8 + 4);
            float ta = sh_t2[e * 33 + 2 * m];
            float tb = sh_t2[e * 33 + 2 * m + 1];
            float al = sh_alpha[e * 4 + hh];
            float* op = dout + (size_t)sh_dn[e] * 64 + m * 4;
            asm volatile("red.global.add.v4.f32 [%0], {%1, %2, %3, %4};"
                         :: "l"(op),
                            "f"(al * (ta * b2a.x + tb * b2b.x)),
                            "f"(al * (ta * b2a.y + tb * b2b.y)),
                            "f"(al * (ta * b2a.z + tb * b2b.z)),
                            "f"(al * (ta * b2a.w + tb * b2b.w))
                         : "memory");
        }
    }
}

// ---------------- launch ----------------
extern "C" void kernel_launch(void* const* d_in, const int* in_sizes, int n_in,
                              void* d_out, int out_size) {
    const float* basis1 = (const float*)d_in[0];
    const float* basis2 = (const float*)d_in[1];
    const float* ef     = (const float*)d_in[2];
    const float* f      = (const float*)d_in[3];
    const int*   src    = (const int*)d_in[4];
    const int*   dst    = (const int*)d_in[5];
    const float* q_w    = (const float*)d_in[6];
    const float* q_b    = (const float*)d_in[7];
    const float* k_w1   = (const float*)d_in[8];
    const float* k_b1   = (const float*)d_in[9];
    const float* k_wl   = (const float*)d_in[10];
    const float* k_bl   = (const float*)d_in[11];
    const float* k_wr   = (const float*)d_in[12];
    const float* k_br   = (const float*)d_in[13];
    const float* v_w1   = (const float*)d_in[14];
    const float* v_b1   = (const float*)d_in[15];
    const float* v_wl   = (const float*)d_in[16];
    const float* v_bl   = (const float*)d_in[17];
    const float* v_wr   = (const float*)d_in[18];
    const float* v_br   = (const float*)d_in[19];
    float* dout = (float*)d_out;

    cudaFuncSetAttribute(conv_mma_kernel, cudaFuncAttributeMaxDynamicSharedMemorySize, SMEM_BYTES);

    presplit_kernel<<<512, 256>>>(k_wl, k_wr, v_wl, v_wr, k_bl, k_br, v_bl, v_br, k_w1, v_w1);
    qinit_kernel<<<(NN * 64 + 255) / 256, 256>>>(f, q_w, q_b, dout);
    conv_mma_kernel<<<EE / TM, 256, SMEM_BYTES>>>(
        basis1, basis2, ef, f, src, dst, k_b1, v_b1, dout, 0);   // K: scores + den
    conv_mma_kernel<<<EE / TM, 256, SMEM_BYTES>>>(
        basis1, basis2, ef, f, src, dst, k_b1, v_b1, dout, 1);   // V: fused scatter
}

// round 11
// speedup vs baseline: 3.1080x; 1.0078x over previous
#include <cuda_runtime.h>
#include <cuda_fp16.h>
#include <math_constants.h>
#include <cstdint>

#define NN 10000
#define EE 160000
#define EDIM 32
#define HID 128
#define NH 4
#define TM 128            // edges per block
#define THREADS 512

// ---------------- scratch (static device arrays; no allocation) ----------------
__device__ __half g_wthi[2 * 512 * 128];  // [conv][n][k] fp16-hi of [wl|wr]^T
__device__ __half g_wtlo[2 * 512 * 128];
__device__ __half g_w1hi[2 * 128 * 32];   // [conv][j][i] fp16-hi of w1^T
__device__ __half g_w1lo[2 * 128 * 32];
__device__ float g_bias[2][512];          // [conv][bl(256)|br(256)]
__device__ float g_q[NN * 64];
__device__ float g_ex[EE * NH];
__device__ float g_den[NN * NH];

__device__ __forceinline__ uint32_t smem_to_u32(const void* p) {
    uint32_t a;
    asm("{ .reg .u64 t; cvta.to.shared.u64 t, %1; cvt.u32.u64 %0, t; }" : "=r"(a) : "l"(p));
    return a;
}
__device__ __forceinline__ void ldsm4(uint32_t a, uint32_t* r) {
    asm volatile("ldmatrix.sync.aligned.m8n8.x4.shared.b16 {%0,%1,%2,%3}, [%4];"
                 : "=r"(r[0]), "=r"(r[1]), "=r"(r[2]), "=r"(r[3]) : "r"(a));
}
__device__ __forceinline__ void mma16816(float* c, const uint32_t* a, const uint32_t* b) {
    asm volatile("mma.sync.aligned.m16n8k16.row.col.f32.f16.f16.f32 "
                 "{%0,%1,%2,%3}, {%4,%5,%6,%7}, {%8,%9}, {%0,%1,%2,%3};"
                 : "+f"(c[0]), "+f"(c[1]), "+f"(c[2]), "+f"(c[3])
                 : "r"(a[0]), "r"(a[1]), "r"(a[2]), "r"(a[3]), "r"(b[0]), "r"(b[1]));
}
__device__ __forceinline__ void cp16(uint32_t dst, const void* src) {
    asm volatile("cp.async.cg.shared.global [%0], [%1], 16;" :: "r"(dst), "l"(src) : "memory");
}

// ---------------- kernel 0: pre-split weights (fp16 hi/lo, transposed) ----------------
__global__ void presplit_kernel(const float* __restrict__ kwl, const float* __restrict__ kwr,
                                const float* __restrict__ vwl, const float* __restrict__ vwr,
                                const float* __restrict__ kbl, const float* __restrict__ kbr,
                                const float* __restrict__ vbl, const float* __restrict__ vbr,
                                const float* __restrict__ kw1, const float* __restrict__ vw1) {
    int idx = blockIdx.x * blockDim.x + threadIdx.x;   // 131072
    if (idx < 2 * 512 * 128) {
        int conv = idx >> 16;
        int rem = idx & 65535;
        int n = rem >> 7, k = rem & 127;
        const float* w = conv ? (n < 256 ? vwl : vwr) : (n < 256 ? kwl : kwr);
        float val = w[k * 256 + (n & 255)];
        __half hi = __float2half_rn(val);
        g_wthi[idx] = hi;
        g_wtlo[idx] = __float2half_rn(val - __half2float(hi));
    }
    if (idx < 2 * 128 * 32) {                          // w1^T split
        int conv = idx >> 12;
        int rem = idx & 4095;
        int j = rem >> 5, i = rem & 31;
        float val = (conv ? vw1 : kw1)[i * 128 + j];
        __half hi = __float2half_rn(val);
        g_w1hi[idx] = hi;
        g_w1lo[idx] = __float2half_rn(val - __half2float(hi));
    }
    if (idx < 1024) {
        int conv = idx >> 9, j = idx & 511;
        const float* s = conv ? (j < 256 ? vbl : vbr) : (j < 256 ? kbl : kbr);
        g_bias[conv][j] = s[j & 255];
    }
}

// ---------------- kernel 1: Q equivariant linear + init ----------------
__global__ void qinit_kernel(const float* __restrict__ f,
                             const float* __restrict__ qw,
                             const float* __restrict__ qb,
                             float* __restrict__ dout) {
    int p = blockIdx.x * blockDim.x + threadIdx.x;
    if (p < NN * 64) {
        int n = p >> 6, j = p & 63;
        int o = j >> 2, d = j & 3;
        int l = (d == 0) ? 0 : 1;
        float acc = (d == 0) ? qb[o] : 0.f;
        const float* wrow = qw + (l * 16 + o) * 16;
        const float* frow = f + n * 64 + d;
#pragma unroll
        for (int m = 0; m < 16; m++) acc += wrow[m] * frow[m * 4];
        g_q[p] = acc;
        dout[p] = 0.f;
    }
    if (p < NN * NH) g_den[p] = 0.f;
}

// ---------------- kernel 2: mma.sync fused conv (TM=128, half-pass) ----------------
// smem byte offsets
#define OFF_A    0u         // 32768: 128e x 128k fp16 (256B rows, swizzled)
#define OFF_W    32768u     // 131072: half W, hi @+0, lo @+65536 (256 n-rows x 256B)
#define OFF_T    163840u    // 128*33*4 = 16896 (t; aliased as t2)
#define OFF_RT   180736u    // 128*8*4 = 4096 (reused as dn[] in V final)
#define OFF_BIAS 184832u    // 512*4 (reused as alpha in V final)
#define OFF_EF   186880u    // 16384: 128e x 128B (fp16 ef rows, swizzled)
#define OFF_W1T  203264u    // 16384: hi 8192 + lo 8192
#define SMEM_BYTES 219648u

__device__ __forceinline__ void load_whalf(uint32_t smem_base, int conv, int nbase, int tid) {
#pragma unroll
    for (int ii = 0; ii < 16; ii++) {
        int g = ii * THREADS + tid;             // 0..8191 16B-chunks
        int half_ = g >> 12;                    // 0 hi, 1 lo
        int rem = g & 4095;
        int n = rem >> 4, q = rem & 15;
        const __half* src =
            (half_ ? g_wtlo : g_wthi) + conv * 65536 + (nbase + n) * 128 + q * 8;
        uint32_t dst = smem_base + OFF_W +
                       (uint32_t)(half_ * 65536 + n * 256 + ((q ^ (n & 7)) << 4));
        cp16(dst, src);
    }
    asm volatile("cp.async.commit_group;" ::: "memory");
}

__global__ void __launch_bounds__(THREADS, 1)
conv_mma_kernel(const float* __restrict__ basis1, const float* __restrict__ basis2,
                const float* __restrict__ ef, const float* __restrict__ f,
                const int* __restrict__ src, const int* __restrict__ dst,
                const float* __restrict__ k_b1, const float* __restrict__ v_b1,
                float* __restrict__ dout, int conv) {
    extern __shared__ char sm[];
    const uint32_t smem_base = smem_to_u32(sm);
    const int tid = threadIdx.x;
    const int lane = tid & 31, wid = tid >> 5;
    const int l4 = lane & 3;
    const int eg = wid >> 3;                    // 0..1: e base = eg*64
    const int ng = wid & 7;                     // 0..7: n base = ng*32
    const int e0 = blockIdx.x * TM;

    float* sh_t   = (float*)(sm + OFF_T);       // later aliased as t2
    float* sh_rt  = (float*)(sm + OFF_RT);
    float* sh_bias= (float*)(sm + OFF_BIAS);

    const int a_row_off = ((lane >> 3) & 1) * 8 + (lane & 7);
    const int a_ksel = (lane >> 4) & 1;
    const int b_n_off = ((lane >> 4) & 1) * 8 + (lane & 7);
    const int b_ksel = (lane >> 3) & 1;

    // ---- prefetch: w1t (group0), right W half (group1) ----
#pragma unroll
    for (int r = 0; r < 2; r++) {
        int g = r * THREADS + tid;              // 1024 chunks total
        int half_ = g >> 9;                     // 0 hi, 1 lo (512 chunks each)
        int rem = g & 511;
        int n = rem >> 2, q = rem & 3;          // n 0..127, q 0..3
        const __half* srcp = (half_ ? g_w1lo : g_w1hi) + conv * 4096 + n * 32 + q * 8;
        uint32_t dstp = smem_base + OFF_W1T +
                        (uint32_t)(half_ * 8192 + n * 64 + ((q ^ (n & 3)) << 4));
        cp16(dstp, srcp);
    }
    asm volatile("cp.async.commit_group;" ::: "memory");
    load_whalf(smem_base, conv, 256, tid);

    // ---- stage ef (fp32 -> fp16 tiles), bias; compute t ----
#pragma unroll
    for (int r = 0; r < 2; r++) {
        int idx = r * THREADS + tid;            // 1024 float4s
        int e = idx >> 3, i0 = (idx & 7) * 4;
        float4 v = ((const float4*)(ef + (size_t)e0 * EDIM))[idx];
        __half2 h01 = __floats2half2_rn(v.x, v.y);
        __half2 h23 = __floats2half2_rn(v.z, v.w);
        int q = i0 >> 3;
        uint32_t base = (uint32_t)(e * 128 + ((q ^ (e & 7)) << 4) + (i0 & 7) * 2);
        *(uint32_t*)(sm + OFF_EF + base)     = *reinterpret_cast<uint32_t*>(&h01);
        *(uint32_t*)(sm + OFF_EF + base + 4) = *reinterpret_cast<uint32_t*>(&h23);
    }
    sh_bias[tid] = g_bias[conv][tid];
#pragma unroll
    for (int r = 0; r < 8; r++) {
        int p = r * THREADS + tid;              // 4096: t[e][c]
        int e = p >> 5, c = p & 31;
        int m = c >> 1, l = c & 1;
        int sn = __ldg(&src[e0 + e]);
        float4 fv = *reinterpret_cast<const float4*>(f + (size_t)sn * 64 + m * 4);
        float4 b1a = *reinterpret_cast<const float4*>(basis1 + (size_t)(e0 + e) * 8);
        float4 b1b = *reinterpret_cast<const float4*>(basis1 + (size_t)(e0 + e) * 8 + 4);
        float a;
        if (l == 0)
            a = fv.x * b1a.x + fv.y * b1a.z + fv.z * b1b.x + fv.w * b1b.z;
        else
            a = fv.x * b1a.y + fv.y * b1a.w + fv.z * b1b.y + fv.w * b1b.w;
        sh_t[e * 33 + c] = a;
    }
    asm volatile("cp.async.wait_group 1;" ::: "memory");   // w1t resident
    __syncthreads();                                       // ef/t visible

    // ---- h-phase on tensor cores: h = gelu(ef @ w1 + b1) -> fp16 A tile ----
    {
        const float* hbv = conv ? v_b1 : k_b1;
        const int wj = (wid & 7) * 16;          // j base
        const int we = (wid >> 3) * 64;         // e base
        float bj[2][2];
#pragma unroll
        for (int nt = 0; nt < 2; nt++) {
            int j0 = wj + nt * 8 + 2 * l4;
            bj[nt][0] = __ldg(&hbv[j0]);
            bj[nt][1] = __ldg(&hbv[j0 + 1]);
        }
        uint32_t Bh[2][4], Bl[2][4];
#pragma unroll
        for (int kc = 0; kc < 2; kc++) {
            int n = wj + b_n_off;
            int c = kc * 2 + b_ksel;
            uint32_t bd = smem_base + OFF_W1T + (uint32_t)(n * 64 + ((c ^ (n & 3)) << 4));
            ldsm4(bd, Bh[kc]);
            ldsm4(bd + 8192u, Bl[kc]);
        }
#pragma unroll
        for (int mt = 0; mt < 4; mt++) {
            float hacc[2][4];
#pragma unroll
            for (int nt = 0; nt < 2; nt++)
#pragma unroll
                for (int u = 0; u < 4; u++) hacc[nt][u] = 0.f;
#pragma unroll
            for (int kc = 0; kc < 2; kc++) {
                int arow = we + mt * 16 + a_row_off;
                int c = kc * 2 + a_ksel;
                uint32_t ad = smem_base + OFF_EF + (uint32_t)(arow * 128 + ((c ^ (arow & 7)) << 4));
                uint32_t Ah[4];
                ldsm4(ad, Ah);
#pragma unroll
                for (int nt = 0; nt < 2; nt++) {
                    mma16816(hacc[nt], Ah, &Bh[kc][nt * 2]);
                    mma16816(hacc[nt], Ah, &Bl[kc][nt * 2]);
                }
            }
#pragma unroll
            for (int nt = 0; nt < 2; nt++) {
                int j0 = wj + nt * 8 + 2 * l4;
                int jc = j0 >> 3;
#pragma unroll
                for (int hrow = 0; hrow < 2; hrow++) {
                    int e = we + mt * 16 + hrow * 8 + (lane >> 2);
                    float v0 = hacc[nt][hrow * 2]     + bj[nt][0];
                    float v1 = hacc[nt][hrow * 2 + 1] + bj[nt][1];
                    v0 = v0 * normcdff(v0);
                    v1 = v1 * normcdff(v1);
                    __half2 hp = __floats2half2_rn(v0, v1);
                    uint32_t addr = (uint32_t)(e * 256 + ((jc ^ (e & 7)) << 4) + (j0 & 7) * 2);
                    *(uint32_t*)(sm + OFF_A + addr) = *reinterpret_cast<uint32_t*>(&hp);
                }
            }
        }
    }
    asm volatile("cp.async.wait_group 0;" ::: "memory");   // right W resident
    __syncthreads();                                       // A tile visible
    float* sh_t2 = sh_t;

    // ================= PASS R (cols 256..511) =================
    {
        float acc[4][4][4];
#pragma unroll
        for (int mt = 0; mt < 4; mt++)
#pragma unroll
            for (int nt = 0; nt < 4; nt++)
#pragma unroll
                for (int u = 0; u < 4; u++) acc[mt][nt][u] = 0.f;
#pragma unroll
        for (int ks = 0; ks < 8; ks++) {
            uint32_t A[4][4];
#pragma unroll
            for (int mt = 0; mt < 4; mt++) {
                int arow = eg * 64 + mt * 16 + a_row_off;
                int kc = ks * 2 + a_ksel;
                ldsm4(smem_base + OFF_A + (uint32_t)(arow * 256 + ((kc ^ (arow & 7)) << 4)), A[mt]);
            }
#pragma unroll
            for (int g2 = 0; g2 < 2; g2++) {
                int n = ng * 32 + g2 * 16 + b_n_off;
                int kc = ks * 2 + b_ksel;
                uint32_t bd = smem_base + OFF_W + (uint32_t)(n * 256 + ((kc ^ (n & 7)) << 4));
                uint32_t Bhi[4], Blo[4];
                ldsm4(bd, Bhi);
                ldsm4(bd + 65536u, Blo);
#pragma unroll
                for (int mt = 0; mt < 4; mt++) {
                    mma16816(acc[mt][g2 * 2],     A[mt], &Bhi[0]);
                    mma16816(acc[mt][g2 * 2],     A[mt], &Blo[0]);
                    mma16816(acc[mt][g2 * 2 + 1], A[mt], &Bhi[2]);
                    mma16816(acc[mt][g2 * 2 + 1], A[mt], &Blo[2]);
                }
            }
        }
        __syncthreads();                        // all warps done reading right W
        load_whalf(smem_base, conv, 0, tid);    // prefetch left half (overlaps epilogue)

        // right epilogue: rt[e][ng] (unique writer per warp — no atomics)
#pragma unroll
        for (int mt = 0; mt < 4; mt++)
#pragma unroll
            for (int h2 = 0; h2 < 2; h2++) {
                int e = eg * 64 + mt * 16 + h2 * 8 + (lane >> 2);
                float s = 0.f;
#pragma unroll
                for (int nt = 0; nt < 4; nt++) {
                    int nc = nt * 8 + 2 * l4;
                    int o = 256 + ng * 32 + nc;
                    s += (acc[mt][nt][h2 * 2] + sh_bias[o]) * sh_t[e * 33 + nc]
                       + (acc[mt][nt][h2 * 2 + 1] + sh_bias[o + 1]) * sh_t[e * 33 + nc + 1];
                }
                s += __shfl_xor_sync(0xFFFFFFFFu, s, 1);
                s += __shfl_xor_sync(0xFFFFFFFFu, s, 2);
                if (l4 == 0) sh_rt[e * 8 + ng] = s;
            }
    }
    asm volatile("cp.async.wait_group 0;" ::: "memory");   // left W resident
    __syncthreads();                                       // rt visible

    // ================= PASS L (cols 0..255) =================
    {
        float acc[4][4][4];
#pragma unroll
        for (int mt = 0; mt < 4; mt++)
#pragma unroll
            for (int nt = 0; nt < 4; nt++)
#pragma unroll
                for (int u = 0; u < 4; u++) acc[mt][nt][u] = 0.f;
#pragma unroll
        for (int ks = 0; ks < 8; ks++) {
            uint32_t A[4][4];
#pragma unroll
            for (int mt = 0; mt < 4; mt++) {
                int arow = eg * 64 + mt * 16 + a_row_off;
                int kc = ks * 2 + a_ksel;
                ldsm4(smem_base + OFF_A + (uint32_t)(arow * 256 + ((kc ^ (arow & 7)) << 4)), A[mt]);
            }
#pragma unroll
            for (int g2 = 0; g2 < 2; g2++) {
                int n = ng * 32 + g2 * 16 + b_n_off;
                int kc = ks * 2 + b_ksel;
                uint32_t bd = smem_base + OFF_W + (uint32_t)(n * 256 + ((kc ^ (n & 7)) << 4));
                uint32_t Bhi[4], Blo[4];
                ldsm4(bd, Bhi);
                ldsm4(bd + 65536u, Blo);
#pragma unroll
                for (int mt = 0; mt < 4; mt++) {
                    mma16816(acc[mt][g2 * 2],     A[mt], &Bhi[0]);
                    mma16816(acc[mt][g2 * 2],     A[mt], &Blo[0]);
                    mma16816(acc[mt][g2 * 2 + 1], A[mt], &Bhi[2]);
                    mma16816(acc[mt][g2 * 2 + 1], A[mt], &Blo[2]);
                }
            }
        }
        // left epilogue: t2[e][ng*4+nt]
#pragma unroll
        for (int mt = 0; mt < 4; mt++)
#pragma unroll
            for (int h2 = 0; h2 < 2; h2++) {
                int e = eg * 64 + mt * 16 + h2 * 8 + (lane >> 2);
                float r0 = sh_rt[e * 8 + 2 * l4];
                float r1 = sh_rt[e * 8 + 2 * l4 + 1];
#pragma unroll
                for (int nt = 0; nt < 4; nt++) {
                    int o = ng * 32 + nt * 8 + 2 * l4;
                    float s = (acc[mt][nt][h2 * 2] + sh_bias[o]) * r0
                            + (acc[mt][nt][h2 * 2 + 1] + sh_bias[o + 1]) * r1;
                    s += __shfl_xor_sync(0xFFFFFFFFu, s, 1);
                    s += __shfl_xor_sync(0xFFFFFFFFu, s, 2);
                    if (l4 == 0)
                        sh_t2[e * 33 + ng * 4 + nt] = s;
                }
            }
    }
    __syncthreads();

    // ---- final phase ----
    if (conv == 0) {
        // K: scores -> exp (no max pass; scores are O(1)) -> segment denominator
        int e = tid >> 2, hh = tid & 3;              // 512 = 128*4
        int dn = __ldg(&dst[e0 + e]);
        const float* qr = g_q + dn * 64 + hh * 16;
        float s = 0.f;
#pragma unroll
        for (int m = hh * 4; m < hh * 4 + 4; m++) {
            float ta = sh_t2[e * 33 + 2 * m];
            float tb = sh_t2[e * 33 + 2 * m + 1];
#pragma unroll
            for (int d = 0; d < 4; d++) {
                float kv = ta * basis2[(size_t)(e0 + e) * 8 + d]
                         + tb * basis2[(size_t)(e0 + e) * 8 + 4 + d];
                s += qr[(m - hh * 4) * 4 + d] * kv;
            }
        }
        float ex = expf(s * 0.25f);
        g_ex[(size_t)(e0 + e) * NH + hh] = ex;
        atomicAdd(&g_den[dn * NH + hh], ex);
    } else {
        // V: fused weighted scatter — alpha*v straight to dout via red.v4
        float* sh_alpha = sh_bias;                   // 512 floats (bias dead)
        int*   sh_dn    = (int*)(sm + OFF_RT);       // 128 ints (rt dead)
        {
            int e = tid >> 2, hh = tid & 3;
            int dn = __ldg(&dst[e0 + e]);
            if (hh == 0) sh_dn[e] = dn;
            float den = fmaxf(g_den[dn * NH + hh], 1e-9f);
            sh_alpha[tid] = g_ex[(size_t)(e0 + e) * NH + hh] / den;
        }
        __syncthreads();
#pragma unroll
        for (int r = 0; r < 4; r++) {
            int p = r * THREADS + tid;               // 2048 float4 groups
            int e = p >> 4, m = p & 15;
            int hh = m >> 2;
            float4 b2a = *reinterpret_cast<const float4*>(basis2 + (size_t)(e0 + e) * 8);
            float4 b2b = *reinterpret_cast<const float4*>(basis2 + (size_t)(e0 + e) * 8 + 4);
            float ta = sh_t2[e * 33 + 2 * m];
            float tb = sh_t2[e * 33 + 2 * m + 1];
            float al = sh_alpha[e * 4 + hh];
            float* op = dout + (size_t)sh_dn[e] * 64 + m * 4;
            asm volatile("red.global.add.v4.f32 [%0], {%1, %2, %3, %4};"
                         :: "l"(op),
                            "f"(al * (ta * b2a.x + tb * b2b.x)),
                            "f"(al * (ta * b2a.y + tb * b2b.y)),
                            "f"(al * (ta * b2a.z + tb * b2b.z)),
                            "f"(al * (ta * b2a.w + tb * b2b.w))
                         : "memory");
        }
    }
}

// ---------------- launch ----------------
extern "C" void kernel_launch(void* const* d_in, const int* in_sizes, int n_in,
                              void* d_out, int out_size) {
    const float* basis1 = (const float*)d_in[0];
    const float* basis2 = (const float*)d_in[1];
    const float* ef     = (const float*)d_in[2];
    const float* f      = (const float*)d_in[3];
    const int*   src    = (const int*)d_in[4];
    const int*   dst    = (const int*)d_in[5];
    const float* q_w    = (const float*)d_in[6];
    const float* q_b    = (const float*)d_in[7];
    const float* k_w1   = (const float*)d_in[8];
    const float* k_b1   = (const float*)d_in[9];
    const float* k_wl   = (const float*)d_in[10];
    const float* k_bl   = (const float*)d_in[11];
    const float* k_wr   = (const float*)d_in[12];
    const float* k_br   = (const float*)d_in[13];
    const float* v_w1   = (const float*)d_in[14];
    const float* v_b1   = (const float*)d_in[15];
    const float* v_wl   = (const float*)d_in[16];
    const float* v_bl   = (const float*)d_in[17];
    const float* v_wr   = (const float*)d_in[18];
    const float* v_br   = (const float*)d_in[19];
    float* dout = (float*)d_out;

    cudaFuncSetAttribute(conv_mma_kernel, cudaFuncAttributeMaxDynamicSharedMemorySize, SMEM_BYTES);

    presplit_kernel<<<512, 256>>>(k_wl, k_wr, v_wl, v_wr, k_bl, k_br, v_bl, v_br, k_w1, v_w1);
    qinit_kernel<<<(NN * 64 + 255) / 256, 256>>>(f, q_w, q_b, dout);
    conv_mma_kernel<<<EE / TM, THREADS, SMEM_BYTES>>>(
        basis1, basis2, ef, f, src, dst, k_b1, v_b1, dout, 0);   // K: scores + den
    conv_mma_kernel<<<EE / TM, THREADS, SMEM_BYTES>>>(
        basis1, basis2, ef, f, src, dst, k_b1, v_b1, dout, 1);   // V: fused scatter
}

// round 12
// speedup vs baseline: 3.4644x; 1.1147x over previous
#include <cuda_runtime.h>
#include <cuda_fp16.h>
#include <math_constants.h>
#include <cstdint>

#define NN 10000
#define EE 160000
#define EDIM 32
#define HID 128
#define NH 4
#define TM 128            // edges per block
#define THREADS 512

// ---------------- scratch (static device arrays; no allocation) ----------------
__device__ __half g_wthi[2 * 512 * 128];  // [conv][n][k] fp16-hi of [wl|wr]^T
__device__ __half g_wtlo[2 * 512 * 128];
__device__ __half g_w1hi[2 * 128 * 32];   // [conv][j][i] fp16-hi of w1^T
__device__ __half g_w1lo[2 * 128 * 32];
__device__ float g_bias[2][512];          // [conv][bl(256)|br(256)]
__device__ float g_q[NN * 64];
__device__ float g_ex[EE * NH];
__device__ float g_den[NN * NH];

__device__ __forceinline__ uint32_t smem_to_u32(const void* p) {
    uint32_t a;
    asm("{ .reg .u64 t; cvta.to.shared.u64 t, %1; cvt.u32.u64 %0, t; }" : "=r"(a) : "l"(p));
    return a;
}
__device__ __forceinline__ void ldsm4(uint32_t a, uint32_t* r) {
    asm volatile("ldmatrix.sync.aligned.m8n8.x4.shared.b16 {%0,%1,%2,%3}, [%4];"
                 : "=r"(r[0]), "=r"(r[1]), "=r"(r[2]), "=r"(r[3]) : "r"(a));
}
__device__ __forceinline__ void mma16816(float* c, const uint32_t* a, const uint32_t* b) {
    asm volatile("mma.sync.aligned.m16n8k16.row.col.f32.f16.f16.f32 "
                 "{%0,%1,%2,%3}, {%4,%5,%6,%7}, {%8,%9}, {%0,%1,%2,%3};"
                 : "+f"(c[0]), "+f"(c[1]), "+f"(c[2]), "+f"(c[3])
                 : "r"(a[0]), "r"(a[1]), "r"(a[2]), "r"(a[3]), "r"(b[0]), "r"(b[1]));
}
__device__ __forceinline__ void cp16(uint32_t dst, const void* src) {
    asm volatile("cp.async.cg.shared.global [%0], [%1], 16;" :: "r"(dst), "l"(src) : "memory");
}

// ---------------- kernel 0: pre-split weights (fp16 hi/lo, transposed) ----------------
__global__ void presplit_kernel(const float* __restrict__ kwl, const float* __restrict__ kwr,
                                const float* __restrict__ vwl, const float* __restrict__ vwr,
                                const float* __restrict__ kbl, const float* __restrict__ kbr,
                                const float* __restrict__ vbl, const float* __restrict__ vbr,
                                const float* __restrict__ kw1, const float* __restrict__ vw1) {
    int idx = blockIdx.x * blockDim.x + threadIdx.x;   // 131072
    if (idx < 2 * 512 * 128) {
        int conv = idx >> 16;
        int rem = idx & 65535;
        int n = rem >> 7, k = rem & 127;
        const float* w = conv ? (n < 256 ? vwl : vwr) : (n < 256 ? kwl : kwr);
        float val = w[k * 256 + (n & 255)];
        __half hi = __float2half_rn(val);
        g_wthi[idx] = hi;
        g_wtlo[idx] = __float2half_rn(val - __half2float(hi));
    }
    if (idx < 2 * 128 * 32) {                          // w1^T split
        int conv = idx >> 12;
        int rem = idx & 4095;
        int j = rem >> 5, i = rem & 31;
        float val = (conv ? vw1 : kw1)[i * 128 + j];
        __half hi = __float2half_rn(val);
        g_w1hi[idx] = hi;
        g_w1lo[idx] = __float2half_rn(val - __half2float(hi));
    }
    if (idx < 1024) {
        int conv = idx >> 9, j = idx & 511;
        const float* s = conv ? (j < 256 ? vbl : vbr) : (j < 256 ? kbl : kbr);
        g_bias[conv][j] = s[j & 255];
    }
}

// ---------------- kernel 1: Q equivariant linear + init ----------------
__global__ void qinit_kernel(const float* __restrict__ f,
                             const float* __restrict__ qw,
                             const float* __restrict__ qb,
                             float* __restrict__ dout) {
    int p = blockIdx.x * blockDim.x + threadIdx.x;
    if (p < NN * 64) {
        int n = p >> 6, j = p & 63;
        int o = j >> 2, d = j & 3;
        int l = (d == 0) ? 0 : 1;
        float acc = (d == 0) ? qb[o] : 0.f;
        const float* wrow = qw + (l * 16 + o) * 16;
        const float* frow = f + n * 64 + d;
#pragma unroll
        for (int m = 0; m < 16; m++) acc += wrow[m] * frow[m * 4];
        g_q[p] = acc;
        dout[p] = 0.f;
    }
    if (p < NN * NH) g_den[p] = 0.f;
}

// ---------------- kernel 2: mma.sync fused conv (TM=128, half-pass) ----------------
// smem byte offsets
#define OFF_A    0u         // 32768: 128e x 128k fp16 (256B rows, swizzled)
#define OFF_W    32768u     // 131072: half W, hi @+0, lo @+65536 (256 n-rows x 256B)
#define OFF_T    163840u    // 128*33*4 = 16896 (t; aliased as t2)
#define OFF_RT   180736u    // 128*8*4 = 4096 (reused as dn[] in V final)
#define OFF_BIAS 184832u    // 512*4 (reused as alpha in V final)
#define OFF_EF   186880u    // 16384: 128e x 128B (fp16 ef rows, swizzled)
#define OFF_W1T  203264u    // 16384: hi 8192 + lo 8192
#define SMEM_BYTES 219648u

// nhalves=2: hi+lo (16KB*... 8192 chunks); nhalves=1: hi only (4096 chunks)
template <int NHALVES>
__device__ __forceinline__ void load_whalf(uint32_t smem_base, int conv, int nbase, int tid) {
#pragma unroll
    for (int ii = 0; ii < 8 * NHALVES; ii++) {
        int g = ii * THREADS + tid;             // 16B-chunks
        int half_ = g >> 12;                    // 0 hi, 1 lo
        int rem = g & 4095;
        int n = rem >> 4, q = rem & 15;
        const __half* src =
            (half_ ? g_wtlo : g_wthi) + conv * 65536 + (nbase + n) * 128 + q * 8;
        uint32_t dst = smem_base + OFF_W +
                       (uint32_t)(half_ * 65536 + n * 256 + ((q ^ (n & 7)) << 4));
        cp16(dst, src);
    }
    asm volatile("cp.async.commit_group;" ::: "memory");
}

__global__ void __launch_bounds__(THREADS, 1)
conv_mma_kernel(const float* __restrict__ basis1, const float* __restrict__ basis2,
                const float* __restrict__ ef, const float* __restrict__ f,
                const int* __restrict__ src, const int* __restrict__ dst,
                const float* __restrict__ k_b1, const float* __restrict__ v_b1,
                float* __restrict__ dout, int conv) {
    extern __shared__ char sm[];
    const uint32_t smem_base = smem_to_u32(sm);
    const int tid = threadIdx.x;
    const int lane = tid & 31, wid = tid >> 5;
    const int l4 = lane & 3;
    const int eg = wid >> 3;                    // 0..1: e base = eg*64
    const int ng = wid & 7;                     // 0..7: n base = ng*32
    const int e0 = blockIdx.x * TM;

    float* sh_t   = (float*)(sm + OFF_T);       // later aliased as t2
    float* sh_rt  = (float*)(sm + OFF_RT);
    float* sh_bias= (float*)(sm + OFF_BIAS);

    const int a_row_off = ((lane >> 3) & 1) * 8 + (lane & 7);
    const int a_ksel = (lane >> 4) & 1;
    const int b_n_off = ((lane >> 4) & 1) * 8 + (lane & 7);
    const int b_ksel = (lane >> 3) & 1;

    // ---- prefetch: w1t (group0), right W half hi+lo (group1) ----
#pragma unroll
    for (int r = 0; r < 2; r++) {
        int g = r * THREADS + tid;              // 1024 chunks total
        int half_ = g >> 9;                     // 0 hi, 1 lo (512 chunks each)
        int rem = g & 511;
        int n = rem >> 2, q = rem & 3;          // n 0..127, q 0..3
        const __half* srcp = (half_ ? g_w1lo : g_w1hi) + conv * 4096 + n * 32 + q * 8;
        uint32_t dstp = smem_base + OFF_W1T +
                        (uint32_t)(half_ * 8192 + n * 64 + ((q ^ (n & 3)) << 4));
        cp16(dstp, srcp);
    }
    asm volatile("cp.async.commit_group;" ::: "memory");
    load_whalf<2>(smem_base, conv, 256, tid);

    // ---- stage ef (fp32 -> fp16 tiles), bias; compute t ----
#pragma unroll
    for (int r = 0; r < 2; r++) {
        int idx = r * THREADS + tid;            // 1024 float4s
        int e = idx >> 3, i0 = (idx & 7) * 4;
        float4 v = ((const float4*)(ef + (size_t)e0 * EDIM))[idx];
        __half2 h01 = __floats2half2_rn(v.x, v.y);
        __half2 h23 = __floats2half2_rn(v.z, v.w);
        int q = i0 >> 3;
        uint32_t base = (uint32_t)(e * 128 + ((q ^ (e & 7)) << 4) + (i0 & 7) * 2);
        *(uint32_t*)(sm + OFF_EF + base)     = *reinterpret_cast<uint32_t*>(&h01);
        *(uint32_t*)(sm + OFF_EF + base + 4) = *reinterpret_cast<uint32_t*>(&h23);
    }
    sh_bias[tid] = g_bias[conv][tid];
#pragma unroll
    for (int r = 0; r < 8; r++) {
        int p = r * THREADS + tid;              // 4096: t[e][c]
        int e = p >> 5, c = p & 31;
        int m = c >> 1, l = c & 1;
        int sn = __ldg(&src[e0 + e]);
        float4 fv = *reinterpret_cast<const float4*>(f + (size_t)sn * 64 + m * 4);
        float4 b1a = *reinterpret_cast<const float4*>(basis1 + (size_t)(e0 + e) * 8);
        float4 b1b = *reinterpret_cast<const float4*>(basis1 + (size_t)(e0 + e) * 8 + 4);
        float a;
        if (l == 0)
            a = fv.x * b1a.x + fv.y * b1a.z + fv.z * b1b.x + fv.w * b1b.z;
        else
            a = fv.x * b1a.y + fv.y * b1a.w + fv.z * b1b.y + fv.w * b1b.w;
        sh_t[e * 33 + c] = a;
    }
    asm volatile("cp.async.wait_group 1;" ::: "memory");   // w1t resident
    __syncthreads();                                       // ef/t visible

    // ---- h-phase on tensor cores: h = gelu(ef @ w1 + b1) -> fp16 A tile ----
    {
        const float* hbv = conv ? v_b1 : k_b1;
        const int wj = (wid & 7) * 16;          // j base
        const int we = (wid >> 3) * 64;         // e base
        float bj[2][2];
#pragma unroll
        for (int nt = 0; nt < 2; nt++) {
            int j0 = wj + nt * 8 + 2 * l4;
            bj[nt][0] = __ldg(&hbv[j0]);
            bj[nt][1] = __ldg(&hbv[j0 + 1]);
        }
        uint32_t Bh[2][4], Bl[2][4];
#pragma unroll
        for (int kc = 0; kc < 2; kc++) {
            int n = wj + b_n_off;
            int c = kc * 2 + b_ksel;
            uint32_t bd = smem_base + OFF_W1T + (uint32_t)(n * 64 + ((c ^ (n & 3)) << 4));
            ldsm4(bd, Bh[kc]);
            ldsm4(bd + 8192u, Bl[kc]);
        }
#pragma unroll
        for (int mt = 0; mt < 4; mt++) {
            float hacc[2][4];
#pragma unroll
            for (int nt = 0; nt < 2; nt++)
#pragma unroll
                for (int u = 0; u < 4; u++) hacc[nt][u] = 0.f;
#pragma unroll
            for (int kc = 0; kc < 2; kc++) {
                int arow = we + mt * 16 + a_row_off;
                int c = kc * 2 + a_ksel;
                uint32_t ad = smem_base + OFF_EF + (uint32_t)(arow * 128 + ((c ^ (arow & 7)) << 4));
                uint32_t Ah[4];
                ldsm4(ad, Ah);
#pragma unroll
                for (int nt = 0; nt < 2; nt++) {
                    mma16816(hacc[nt], Ah, &Bh[kc][nt * 2]);
                    mma16816(hacc[nt], Ah, &Bl[kc][nt * 2]);
                }
            }
#pragma unroll
            for (int nt = 0; nt < 2; nt++) {
                int j0 = wj + nt * 8 + 2 * l4;
                int jc = j0 >> 3;
#pragma unroll
                for (int hrow = 0; hrow < 2; hrow++) {
                    int e = we + mt * 16 + hrow * 8 + (lane >> 2);
                    float v0 = hacc[nt][hrow * 2]     + bj[nt][0];
                    float v1 = hacc[nt][hrow * 2 + 1] + bj[nt][1];
                    v0 = v0 * normcdff(v0);
                    v1 = v1 * normcdff(v1);
                    __half2 hp = __floats2half2_rn(v0, v1);
                    uint32_t addr = (uint32_t)(e * 256 + ((jc ^ (e & 7)) << 4) + (j0 & 7) * 2);
                    *(uint32_t*)(sm + OFF_A + addr) = *reinterpret_cast<uint32_t*>(&hp);
                }
            }
        }
    }
    asm volatile("cp.async.wait_group 0;" ::: "memory");   // right W resident
    __syncthreads();                                       // A tile visible
    float* sh_t2 = sh_t;

    // ================= PASS R (cols 256..511, hi+lo 2-pass) =================
    {
        float acc[4][4][4];
#pragma unroll
        for (int mt = 0; mt < 4; mt++)
#pragma unroll
            for (int nt = 0; nt < 4; nt++)
#pragma unroll
                for (int u = 0; u < 4; u++) acc[mt][nt][u] = 0.f;
#pragma unroll
        for (int ks = 0; ks < 8; ks++) {
            uint32_t A[4][4];
#pragma unroll
            for (int mt = 0; mt < 4; mt++) {
                int arow = eg * 64 + mt * 16 + a_row_off;
                int kc = ks * 2 + a_ksel;
                ldsm4(smem_base + OFF_A + (uint32_t)(arow * 256 + ((kc ^ (arow & 7)) << 4)), A[mt]);
            }
#pragma unroll
            for (int g2 = 0; g2 < 2; g2++) {
                int n = ng * 32 + g2 * 16 + b_n_off;
                int kc = ks * 2 + b_ksel;
                uint32_t bd = smem_base + OFF_W + (uint32_t)(n * 256 + ((kc ^ (n & 7)) << 4));
                uint32_t Bhi[4], Blo[4];
                ldsm4(bd, Bhi);
                ldsm4(bd + 65536u, Blo);
#pragma unroll
                for (int mt = 0; mt < 4; mt++) {
                    mma16816(acc[mt][g2 * 2],     A[mt], &Bhi[0]);
                    mma16816(acc[mt][g2 * 2],     A[mt], &Blo[0]);
                    mma16816(acc[mt][g2 * 2 + 1], A[mt], &Bhi[2]);
                    mma16816(acc[mt][g2 * 2 + 1], A[mt], &Blo[2]);
                }
            }
        }
        __syncthreads();                        // all warps done reading right W
        load_whalf<1>(smem_base, conv, 0, tid); // prefetch left half: HI ONLY

        // right epilogue: rt[e][ng] (unique writer per warp — no atomics)
#pragma unroll
        for (int mt = 0; mt < 4; mt++)
#pragma unroll
            for (int h2 = 0; h2 < 2; h2++) {
                int e = eg * 64 + mt * 16 + h2 * 8 + (lane >> 2);
                float s = 0.f;
#pragma unroll
                for (int nt = 0; nt < 4; nt++) {
                    int nc = nt * 8 + 2 * l4;
                    int o = 256 + ng * 32 + nc;
                    s += (acc[mt][nt][h2 * 2] + sh_bias[o]) * sh_t[e * 33 + nc]
                       + (acc[mt][nt][h2 * 2 + 1] + sh_bias[o + 1]) * sh_t[e * 33 + nc + 1];
                }
                s += __shfl_xor_sync(0xFFFFFFFFu, s, 1);
                s += __shfl_xor_sync(0xFFFFFFFFu, s, 2);
                if (l4 == 0) sh_rt[e * 8 + ng] = s;
            }
    }
    asm volatile("cp.async.wait_group 0;" ::: "memory");   // left W (hi) resident
    __syncthreads();                                       // rt visible

    // ================= PASS L (cols 0..255, hi-only single pass) =================
    {
        float acc[4][4][4];
#pragma unroll
        for (int mt = 0; mt < 4; mt++)
#pragma unroll
            for (int nt = 0; nt < 4; nt++)
#pragma unroll
                for (int u = 0; u < 4; u++) acc[mt][nt][u] = 0.f;
#pragma unroll
        for (int ks = 0; ks < 8; ks++) {
            uint32_t A[4][4];
#pragma unroll
            for (int mt = 0; mt < 4; mt++) {
                int arow = eg * 64 + mt * 16 + a_row_off;
                int kc = ks * 2 + a_ksel;
                ldsm4(smem_base + OFF_A + (uint32_t)(arow * 256 + ((kc ^ (arow & 7)) << 4)), A[mt]);
            }
#pragma unroll
            for (int g2 = 0; g2 < 2; g2++) {
                int n = ng * 32 + g2 * 16 + b_n_off;
                int kc = ks * 2 + b_ksel;
                uint32_t bd = smem_base + OFF_W + (uint32_t)(n * 256 + ((kc ^ (n & 7)) << 4));
                uint32_t Bhi[4];
                ldsm4(bd, Bhi);
#pragma unroll
                for (int mt = 0; mt < 4; mt++) {
                    mma16816(acc[mt][g2 * 2],     A[mt], &Bhi[0]);
                    mma16816(acc[mt][g2 * 2 + 1], A[mt], &Bhi[2]);
                }
            }
        }
        // left epilogue: t2[e][ng*4+nt]
#pragma unroll
        for (int mt = 0; mt < 4; mt++)
#pragma unroll
            for (int h2 = 0; h2 < 2; h2++) {
                int e = eg * 64 + mt * 16 + h2 * 8 + (lane >> 2);
                float r0 = sh_rt[e * 8 + 2 * l4];
                float r1 = sh_rt[e * 8 + 2 * l4 + 1];
#pragma unroll
                for (int nt = 0; nt < 4; nt++) {
                    int o = ng * 32 + nt * 8 + 2 * l4;
                    float s = (acc[mt][nt][h2 * 2] + sh_bias[o]) * r0
                            + (acc[mt][nt][h2 * 2 + 1] + sh_bias[o + 1]) * r1;
                    s += __shfl_xor_sync(0xFFFFFFFFu, s, 1);
                    s += __shfl_xor_sync(0xFFFFFFFFu, s, 2);
                    if (l4 == 0)
                        sh_t2[e * 33 + ng * 4 + nt] = s;
                }
            }
    }
    __syncthreads();

    // ---- final phase ----
    if (conv == 0) {
        // K: scores -> exp (no max pass; scores are O(1)) -> segment denominator
        int e = tid >> 2, hh = tid & 3;              // 512 = 128*4
        int dn = __ldg(&dst[e0 + e]);
        const float* qr = g_q + dn * 64 + hh * 16;
        float s = 0.f;
#pragma unroll
        for (int m = hh * 4; m < hh * 4 + 4; m++) {
            float ta = sh_t2[e * 33 + 2 * m];
            float tb = sh_t2[e * 33 + 2 * m + 1];
#pragma unroll
            for (int d = 0; d < 4; d++) {
                float kv = ta * basis2[(size_t)(e0 + e) * 8 + d]
                         + tb * basis2[(size_t)(e0 + e) * 8 + 4 + d];
                s += qr[(m - hh * 4) * 4 + d] * kv;
            }
        }
        float ex = expf(s * 0.25f);
        g_ex[(size_t)(e0 + e) * NH + hh] = ex;
        atomicAdd(&g_den[dn * NH + hh], ex);
    } else {
        // V: fused weighted scatter — alpha*v straight to dout via red.v4
        float* sh_alpha = sh_bias;                   // 512 floats (bias dead)
        int*   sh_dn    = (int*)(sm + OFF_RT);       // 128 ints (rt dead)
        {
            int e = tid >> 2, hh = tid & 3;
            int dn = __ldg(&dst[e0 + e]);
            if (hh == 0) sh_dn[e] = dn;
            float den = fmaxf(g_den[dn * NH + hh], 1e-9f);
            sh_alpha[tid] = g_ex[(size_t)(e0 + e) * NH + hh] / den;
        }
        __syncthreads();
#pragma unroll
        for (int r = 0; r < 4; r++) {
            int p = r * THREADS + tid;               // 2048 float4 groups
            int e = p >> 4, m = p & 15;
            int hh = m >> 2;
            float4 b2a = *reinterpret_cast<const float4*>(basis2 + (size_t)(e0 + e) * 8);
            float4 b2b = *reinterpret_cast<const float4*>(basis2 + (size_t)(e0 + e) * 8 + 4);
            float ta = sh_t2[e * 33 + 2 * m];
            float tb = sh_t2[e * 33 + 2 * m + 1];
            float al = sh_alpha[e * 4 + hh];
            float* op = dout + (size_t)sh_dn[e] * 64 + m * 4;
            asm volatile("red.global.add.v4.f32 [%0], {%1, %2, %3, %4};"
                         :: "l"(op),
                            "f"(al * (ta * b2a.x + tb * b2b.x)),
                            "f"(al * (ta * b2a.y + tb * b2b.y)),
                            "f"(al * (ta * b2a.z + tb * b2b.z)),
                            "f"(al * (ta * b2a.w + tb * b2b.w))
                         : "memory");
        }
    }
}

// ---------------- launch ----------------
extern "C" void kernel_launch(void* const* d_in, const int* in_sizes, int n_in,
                              void* d_out, int out_size) {
    const float* basis1 = (const float*)d_in[0];
    const float* basis2 = (const float*)d_in[1];
    const float* ef     = (const float*)d_in[2];
    const float* f      = (const float*)d_in[3];
    const int*   src    = (const int*)d_in[4];
    const int*   dst    = (const int*)d_in[5];
    const float* q_w    = (const float*)d_in[6];
    const float* q_b    = (const float*)d_in[7];
    const float* k_w1   = (const float*)d_in[8];
    const float* k_b1   = (const float*)d_in[9];
    const float* k_wl   = (const float*)d_in[10];
    const float* k_bl   = (const float*)d_in[11];
    const float* k_wr   = (const float*)d_in[12];
    const float* k_br   = (const float*)d_in[13];
    const float* v_w1   = (const float*)d_in[14];
    const float* v_b1   = (const float*)d_in[15];
    const float* v_wl   = (const float*)d_in[16];
    const float* v_bl   = (const float*)d_in[17];
    const float* v_wr   = (const float*)d_in[18];
    const float* v_br   = (const float*)d_in[19];
    float* dout = (float*)d_out;

    cudaFuncSetAttribute(conv_mma_kernel, cudaFuncAttributeMaxDynamicSharedMemorySize, SMEM_BYTES);

    presplit_kernel<<<512, 256>>>(k_wl, k_wr, v_wl, v_wr, k_bl, k_br, v_bl, v_br, k_w1, v_w1);
    qinit_kernel<<<(NN * 64 + 255) / 256, 256>>>(f, q_w, q_b, dout);
    conv_mma_kernel<<<EE / TM, THREADS, SMEM_BYTES>>>(
        basis1, basis2, ef, f, src, dst, k_b1, v_b1, dout, 0);   // K: scores + den
    conv_mma_kernel<<<EE / TM, THREADS, SMEM_BYTES>>>(
        basis1, basis2, ef, f, src, dst, k_b1, v_b1, dout, 1);   // V: fused scatter
}

// round 13
// speedup vs baseline: 3.8758x; 1.1188x over previous
#include <cuda_runtime.h>
#include <cuda_fp16.h>
#include <math_constants.h>
#include <cstdint>

#define NN 10000
#define EE 160000
#define EDIM 32
#define HID 128
#define NH 4
#define TM 128            // edges per block
#define THREADS 512

// ---------------- scratch (static device arrays; no allocation) ----------------
__device__ __half g_wthi[2 * 512 * 128];  // [conv][n][k] fp16-hi of [wl|wr]^T
__device__ __half g_w1hi[2 * 128 * 32];   // [conv][j][i] fp16-hi of w1^T
__device__ __half g_w1lo[2 * 128 * 32];
__device__ float g_bias[2][512];          // [conv][bl(256)|br(256)]
__device__ float g_q[NN * 64];
__device__ float g_ex[EE * NH];
__device__ float g_den[NN * NH];

__device__ __forceinline__ uint32_t smem_to_u32(const void* p) {
    uint32_t a;
    asm("{ .reg .u64 t; cvta.to.shared.u64 t, %1; cvt.u32.u64 %0, t; }" : "=r"(a) : "l"(p));
    return a;
}
__device__ __forceinline__ void ldsm4(uint32_t a, uint32_t* r) {
    asm volatile("ldmatrix.sync.aligned.m8n8.x4.shared.b16 {%0,%1,%2,%3}, [%4];"
                 : "=r"(r[0]), "=r"(r[1]), "=r"(r[2]), "=r"(r[3]) : "r"(a));
}
__device__ __forceinline__ void mma16816(float* c, const uint32_t* a, const uint32_t* b) {
    asm volatile("mma.sync.aligned.m16n8k16.row.col.f32.f16.f16.f32 "
                 "{%0,%1,%2,%3}, {%4,%5,%6,%7}, {%8,%9}, {%0,%1,%2,%3};"
                 : "+f"(c[0]), "+f"(c[1]), "+f"(c[2]), "+f"(c[3])
                 : "r"(a[0]), "r"(a[1]), "r"(a[2]), "r"(a[3]), "r"(b[0]), "r"(b[1]));
}
__device__ __forceinline__ void cp16(uint32_t dst, const void* src) {
    asm volatile("cp.async.cg.shared.global [%0], [%1], 16;" :: "r"(dst), "l"(src) : "memory");
}

// ---------------- kernel 0: pre-split weights (fp16, transposed) ----------------
__global__ void presplit_kernel(const float* __restrict__ kwl, const float* __restrict__ kwr,
                                const float* __restrict__ vwl, const float* __restrict__ vwr,
                                const float* __restrict__ kbl, const float* __restrict__ kbr,
                                const float* __restrict__ vbl, const float* __restrict__ vbr,
                                const float* __restrict__ kw1, const float* __restrict__ vw1) {
    int idx = blockIdx.x * blockDim.x + threadIdx.x;   // 131072
    if (idx < 2 * 512 * 128) {
        int conv = idx >> 16;
        int rem = idx & 65535;
        int n = rem >> 7, k = rem & 127;
        const float* w = conv ? (n < 256 ? vwl : vwr) : (n < 256 ? kwl : kwr);
        g_wthi[idx] = __float2half_rn(w[k * 256 + (n & 255)]);
    }
    if (idx < 2 * 128 * 32) {                          // w1^T split (2-pass kept)
        int conv = idx >> 12;
        int rem = idx & 4095;
        int j = rem >> 5, i = rem & 31;
        float val = (conv ? vw1 : kw1)[i * 128 + j];
        __half hi = __float2half_rn(val);
        g_w1hi[idx] = hi;
        g_w1lo[idx] = __float2half_rn(val - __half2float(hi));
    }
    if (idx < 1024) {
        int conv = idx >> 9, j = idx & 511;
        const float* s = conv ? (j < 256 ? vbl : vbr) : (j < 256 ? kbl : kbr);
        g_bias[conv][j] = s[j & 255];
    }
}

// ---------------- kernel 1: Q equivariant linear + init ----------------
__global__ void qinit_kernel(const float* __restrict__ f,
                             const float* __restrict__ qw,
                             const float* __restrict__ qb,
                             float* __restrict__ dout) {
    int p = blockIdx.x * blockDim.x + threadIdx.x;
    if (p < NN * 64) {
        int n = p >> 6, j = p & 63;
        int o = j >> 2, d = j & 3;
        int l = (d == 0) ? 0 : 1;
        float acc = (d == 0) ? qb[o] : 0.f;
        const float* wrow = qw + (l * 16 + o) * 16;
        const float* frow = f + n * 64 + d;
#pragma unroll
        for (int m = 0; m < 16; m++) acc += wrow[m] * frow[m * 4];
        g_q[p] = acc;
        dout[p] = 0.f;
    }
    if (p < NN * NH) g_den[p] = 0.f;
}

// ---------------- kernel 2: mma.sync fused conv (TM=128, full W-hi resident) ----------------
// smem byte offsets
#define OFF_A    0u         // 32768: 128e x 128k fp16 (256B rows, swizzled)
#define OFF_W    32768u     // 131072: FULL W-hi, 512 n-rows x 256B
#define OFF_T    163840u    // 128*33*4 = 16896 (t; aliased as t2)
#define OFF_RT   180736u    // 128*8*4 = 4096 (reused as dn[] in V final)
#define OFF_BIAS 184832u    // 512*4 (reused as alpha in V final)
#define OFF_EF   186880u    // 16384: 128e x 128B (fp16 ef rows, swizzled)
#define OFF_W1T  203264u    // 16384: hi 8192 + lo 8192
#define SMEM_BYTES 219648u

__device__ __forceinline__ void load_w_full(uint32_t smem_base, int conv, int tid) {
#pragma unroll
    for (int ii = 0; ii < 16; ii++) {
        int g = ii * THREADS + tid;             // 0..8191 16B-chunks (512 rows x 16)
        int n = g >> 4, q = g & 15;
        const __half* src = g_wthi + conv * 65536 + n * 128 + q * 8;
        uint32_t dst = smem_base + OFF_W + (uint32_t)(n * 256 + ((q ^ (n & 7)) << 4));
        cp16(dst, src);
    }
    asm volatile("cp.async.commit_group;" ::: "memory");
}

__global__ void __launch_bounds__(THREADS, 1)
conv_mma_kernel(const float* __restrict__ basis1, const float* __restrict__ basis2,
                const float* __restrict__ ef, const float* __restrict__ f,
                const int* __restrict__ src, const int* __restrict__ dst,
                const float* __restrict__ k_b1, const float* __restrict__ v_b1,
                float* __restrict__ dout, int conv) {
    extern __shared__ char sm[];
    const uint32_t smem_base = smem_to_u32(sm);
    const int tid = threadIdx.x;
    const int lane = tid & 31, wid = tid >> 5;
    const int l4 = lane & 3;
    const int eg = wid >> 3;                    // 0..1: e base = eg*64
    const int ng = wid & 7;                     // 0..7: n base = ng*32
    const int e0 = blockIdx.x * TM;

    float* sh_t   = (float*)(sm + OFF_T);       // later aliased as t2
    float* sh_rt  = (float*)(sm + OFF_RT);
    float* sh_bias= (float*)(sm + OFF_BIAS);

    const int a_row_off = ((lane >> 3) & 1) * 8 + (lane & 7);
    const int a_ksel = (lane >> 4) & 1;
    const int b_n_off = ((lane >> 4) & 1) * 8 + (lane & 7);
    const int b_ksel = (lane >> 3) & 1;

    // ---- prefetch: w1t (group0), full W-hi (group1) ----
#pragma unroll
    for (int r = 0; r < 2; r++) {
        int g = r * THREADS + tid;              // 1024 chunks total
        int half_ = g >> 9;                     // 0 hi, 1 lo (512 chunks each)
        int rem = g & 511;
        int n = rem >> 2, q = rem & 3;          // n 0..127, q 0..3
        const __half* srcp = (half_ ? g_w1lo : g_w1hi) + conv * 4096 + n * 32 + q * 8;
        uint32_t dstp = smem_base + OFF_W1T +
                        (uint32_t)(half_ * 8192 + n * 64 + ((q ^ (n & 3)) << 4));
        cp16(dstp, srcp);
    }
    asm volatile("cp.async.commit_group;" ::: "memory");
    load_w_full(smem_base, conv, tid);

    // ---- stage ef (fp32 -> fp16 tiles), bias; compute t ----
#pragma unroll
    for (int r = 0; r < 2; r++) {
        int idx = r * THREADS + tid;            // 1024 float4s
        int e = idx >> 3, i0 = (idx & 7) * 4;
        float4 v = ((const float4*)(ef + (size_t)e0 * EDIM))[idx];
        __half2 h01 = __floats2half2_rn(v.x, v.y);
        __half2 h23 = __floats2half2_rn(v.z, v.w);
        int q = i0 >> 3;
        uint32_t base = (uint32_t)(e * 128 + ((q ^ (e & 7)) << 4) + (i0 & 7) * 2);
        *(uint32_t*)(sm + OFF_EF + base)     = *reinterpret_cast<uint32_t*>(&h01);
        *(uint32_t*)(sm + OFF_EF + base + 4) = *reinterpret_cast<uint32_t*>(&h23);
    }
    sh_bias[tid] = g_bias[conv][tid];
#pragma unroll
    for (int r = 0; r < 8; r++) {
        int p = r * THREADS + tid;              // 4096: t[e][c]
        int e = p >> 5, c = p & 31;
        int m = c >> 1, l = c & 1;
        int sn = __ldg(&src[e0 + e]);
        float4 fv = *reinterpret_cast<const float4*>(f + (size_t)sn * 64 + m * 4);
        float4 b1a = *reinterpret_cast<const float4*>(basis1 + (size_t)(e0 + e) * 8);
        float4 b1b = *reinterpret_cast<const float4*>(basis1 + (size_t)(e0 + e) * 8 + 4);
        float a;
        if (l == 0)
            a = fv.x * b1a.x + fv.y * b1a.z + fv.z * b1b.x + fv.w * b1b.z;
        else
            a = fv.x * b1a.y + fv.y * b1a.w + fv.z * b1b.y + fv.w * b1b.w;
        sh_t[e * 33 + c] = a;
    }
    asm volatile("cp.async.wait_group 1;" ::: "memory");   // w1t resident
    __syncthreads();                                       // ef/t visible

    // ---- h-phase on tensor cores: h = gelu(ef @ w1 + b1) -> fp16 A tile ----
    {
        const float* hbv = conv ? v_b1 : k_b1;
        const int wj = (wid & 7) * 16;          // j base
        const int we = (wid >> 3) * 64;         // e base
        float bj[2][2];
#pragma unroll
        for (int nt = 0; nt < 2; nt++) {
            int j0 = wj + nt * 8 + 2 * l4;
            bj[nt][0] = __ldg(&hbv[j0]);
            bj[nt][1] = __ldg(&hbv[j0 + 1]);
        }
        uint32_t Bh[2][4], Bl[2][4];
#pragma unroll
        for (int kc = 0; kc < 2; kc++) {
            int n = wj + b_n_off;
            int c = kc * 2 + b_ksel;
            uint32_t bd = smem_base + OFF_W1T + (uint32_t)(n * 64 + ((c ^ (n & 3)) << 4));
            ldsm4(bd, Bh[kc]);
            ldsm4(bd + 8192u, Bl[kc]);
        }
#pragma unroll
        for (int mt = 0; mt < 4; mt++) {
            float hacc[2][4];
#pragma unroll
            for (int nt = 0; nt < 2; nt++)
#pragma unroll
                for (int u = 0; u < 4; u++) hacc[nt][u] = 0.f;
#pragma unroll
            for (int kc = 0; kc < 2; kc++) {
                int arow = we + mt * 16 + a_row_off;
                int c = kc * 2 + a_ksel;
                uint32_t ad = smem_base + OFF_EF + (uint32_t)(arow * 128 + ((c ^ (arow & 7)) << 4));
                uint32_t Ah[4];
                ldsm4(ad, Ah);
#pragma unroll
                for (int nt = 0; nt < 2; nt++) {
                    mma16816(hacc[nt], Ah, &Bh[kc][nt * 2]);
                    mma16816(hacc[nt], Ah, &Bl[kc][nt * 2]);
                }
            }
#pragma unroll
            for (int nt = 0; nt < 2; nt++) {
                int j0 = wj + nt * 8 + 2 * l4;
                int jc = j0 >> 3;
#pragma unroll
                for (int hrow = 0; hrow < 2; hrow++) {
                    int e = we + mt * 16 + hrow * 8 + (lane >> 2);
                    float v0 = hacc[nt][hrow * 2]     + bj[nt][0];
                    float v1 = hacc[nt][hrow * 2 + 1] + bj[nt][1];
                    v0 = v0 * normcdff(v0);
                    v1 = v1 * normcdff(v1);
                    __half2 hp = __floats2half2_rn(v0, v1);
                    uint32_t addr = (uint32_t)(e * 256 + ((jc ^ (e & 7)) << 4) + (j0 & 7) * 2);
                    *(uint32_t*)(sm + OFF_A + addr) = *reinterpret_cast<uint32_t*>(&hp);
                }
            }
        }
    }
    asm volatile("cp.async.wait_group 0;" ::: "memory");   // full W-hi resident
    __syncthreads();                                       // A tile visible
    float* sh_t2 = sh_t;

    // ================= PASS R (W rows 256..511) =================
    {
        float acc[4][4][4];
#pragma unroll
        for (int mt = 0; mt < 4; mt++)
#pragma unroll
            for (int nt = 0; nt < 4; nt++)
#pragma unroll
                for (int u = 0; u < 4; u++) acc[mt][nt][u] = 0.f;
#pragma unroll
        for (int ks = 0; ks < 8; ks++) {
            uint32_t A[4][4];
#pragma unroll
            for (int mt = 0; mt < 4; mt++) {
                int arow = eg * 64 + mt * 16 + a_row_off;
                int kc = ks * 2 + a_ksel;
                ldsm4(smem_base + OFF_A + (uint32_t)(arow * 256 + ((kc ^ (arow & 7)) << 4)), A[mt]);
            }
#pragma unroll
            for (int g2 = 0; g2 < 2; g2++) {
                int n = 256 + ng * 32 + g2 * 16 + b_n_off;
                int kc = ks * 2 + b_ksel;
                uint32_t Bhi[4];
                ldsm4(smem_base + OFF_W + (uint32_t)(n * 256 + ((kc ^ (n & 7)) << 4)), Bhi);
#pragma unroll
                for (int mt = 0; mt < 4; mt++) {
                    mma16816(acc[mt][g2 * 2],     A[mt], &Bhi[0]);
                    mma16816(acc[mt][g2 * 2 + 1], A[mt], &Bhi[2]);
                }
            }
        }
        // right epilogue: rt[e][ng] (unique writer per warp — no atomics)
#pragma unroll
        for (int mt = 0; mt < 4; mt++)
#pragma unroll
            for (int h2 = 0; h2 < 2; h2++) {
                int e = eg * 64 + mt * 16 + h2 * 8 + (lane >> 2);
                float s = 0.f;
#pragma unroll
                for (int nt = 0; nt < 4; nt++) {
                    int nc = nt * 8 + 2 * l4;
                    int o = 256 + ng * 32 + nc;
                    s += (acc[mt][nt][h2 * 2] + sh_bias[o]) * sh_t[e * 33 + nc]
                       + (acc[mt][nt][h2 * 2 + 1] + sh_bias[o + 1]) * sh_t[e * 33 + nc + 1];
                }
                s += __shfl_xor_sync(0xFFFFFFFFu, s, 1);
                s += __shfl_xor_sync(0xFFFFFFFFu, s, 2);
                if (l4 == 0) sh_rt[e * 8 + ng] = s;
            }
    }
    __syncthreads();                                       // rt visible

    // ================= PASS L (W rows 0..255) =================
    {
        float acc[4][4][4];
#pragma unroll
        for (int mt = 0; mt < 4; mt++)
#pragma unroll
            for (int nt = 0; nt < 4; nt++)
#pragma unroll
                for (int u = 0; u < 4; u++) acc[mt][nt][u] = 0.f;
#pragma unroll
        for (int ks = 0; ks < 8; ks++) {
            uint32_t A[4][4];
#pragma unroll
            for (int mt = 0; mt < 4; mt++) {
                int arow = eg * 64 + mt * 16 + a_row_off;
                int kc = ks * 2 + a_ksel;
                ldsm4(smem_base + OFF_A + (uint32_t)(arow * 256 + ((kc ^ (arow & 7)) << 4)), A[mt]);
            }
#pragma unroll
            for (int g2 = 0; g2 < 2; g2++) {
                int n = ng * 32 + g2 * 16 + b_n_off;
                int kc = ks * 2 + b_ksel;
                uint32_t Bhi[4];
                ldsm4(smem_base + OFF_W + (uint32_t)(n * 256 + ((kc ^ (n & 7)) << 4)), Bhi);
#pragma unroll
                for (int mt = 0; mt < 4; mt++) {
                    mma16816(acc[mt][g2 * 2],     A[mt], &Bhi[0]);
                    mma16816(acc[mt][g2 * 2 + 1], A[mt], &Bhi[2]);
                }
            }
        }
        // left epilogue: t2[e][ng*4+nt]
#pragma unroll
        for (int mt = 0; mt < 4; mt++)
#pragma unroll
            for (int h2 = 0; h2 < 2; h2++) {
                int e = eg * 64 + mt * 16 + h2 * 8 + (lane >> 2);
                float r0 = sh_rt[e * 8 + 2 * l4];
                float r1 = sh_rt[e * 8 + 2 * l4 + 1];
#pragma unroll
                for (int nt = 0; nt < 4; nt++) {
                    int o = ng * 32 + nt * 8 + 2 * l4;
                    float s = (acc[mt][nt][h2 * 2] + sh_bias[o]) * r0
                            + (acc[mt][nt][h2 * 2 + 1] + sh_bias[o + 1]) * r1;
                    s += __shfl_xor_sync(0xFFFFFFFFu, s, 1);
                    s += __shfl_xor_sync(0xFFFFFFFFu, s, 2);
                    if (l4 == 0)
                        sh_t2[e * 33 + ng * 4 + nt] = s;
                }
            }
    }
    __syncthreads();

    // ---- final phase ----
    if (conv == 0) {
        // K: scores -> exp (no max pass; scores are O(1)) -> segment denominator
        int e = tid >> 2, hh = tid & 3;              // 512 = 128*4
        int dn = __ldg(&dst[e0 + e]);
        const float* qr = g_q + dn * 64 + hh * 16;
        float s = 0.f;
#pragma unroll
        for (int m = hh * 4; m < hh * 4 + 4; m++) {
            float ta = sh_t2[e * 33 + 2 * m];
            float tb = sh_t2[e * 33 + 2 * m + 1];
#pragma unroll
            for (int d = 0; d < 4; d++) {
                float kv = ta * basis2[(size_t)(e0 + e) * 8 + d]
                         + tb * basis2[(size_t)(e0 + e) * 8 + 4 + d];
                s += qr[(m - hh * 4) * 4 + d] * kv;
            }
        }
        float ex = expf(s * 0.25f);
        g_ex[(size_t)(e0 + e) * NH + hh] = ex;
        atomicAdd(&g_den[dn * NH + hh], ex);
    } else {
        // V: fused weighted scatter — alpha*v straight to dout via red.v4
        float* sh_alpha = sh_bias;                   // 512 floats (bias dead)
        int*   sh_dn    = (int*)(sm + OFF_RT);       // 128 ints (rt dead)
        {
            int e = tid >> 2, hh = tid & 3;
            int dn = __ldg(&dst[e0 + e]);
            if (hh == 0) sh_dn[e] = dn;
            float den = fmaxf(g_den[dn * NH + hh], 1e-9f);
            sh_alpha[tid] = g_ex[(size_t)(e0 + e) * NH + hh] / den;
        }
        __syncthreads();
#pragma unroll
        for (int r = 0; r < 4; r++) {
            int p = r * THREADS + tid;               // 2048 float4 groups
            int e = p >> 4, m = p & 15;
            int hh = m >> 2;
            float4 b2a = *reinterpret_cast<const float4*>(basis2 + (size_t)(e0 + e) * 8);
            float4 b2b = *reinterpret_cast<const float4*>(basis2 + (size_t)(e0 + e) * 8 + 4);
            float ta = sh_t2[e * 33 + 2 * m];
            float tb = sh_t2[e * 33 + 2 * m + 1];
            float al = sh_alpha[e * 4 + hh];
            float* op = dout + (size_t)sh_dn[e] * 64 + m * 4;
            asm volatile("red.global.add.v4.f32 [%0], {%1, %2, %3, %4};"
                         :: "l"(op),
                            "f"(al * (ta * b2a.x + tb * b2b.x)),
                            "f"(al * (ta * b2a.y + tb * b2b.y)),
                            "f"(al * (ta * b2a.z + tb * b2b.z)),
                            "f"(al * (ta * b2a.w + tb * b2b.w))
                         : "memory");
        }
    }
}

// ---------------- launch ----------------
extern "C" void kernel_launch(void* const* d_in, const int* in_sizes, int n_in,
                              void* d_out, int out_size) {
    const float* basis1 = (const float*)d_in[0];
    const float* basis2 = (const float*)d_in[1];
    const float* ef     = (const float*)d_in[2];
    const float* f      = (const float*)d_in[3];
    const int*   src    = (const int*)d_in[4];
    const int*   dst    = (const int*)d_in[5];
    const float* q_w    = (const float*)d_in[6];
    const float* q_b    = (const float*)d_in[7];
    const float* k_w1   = (const float*)d_in[8];
    const float* k_b1   = (const float*)d_in[9];
    const float* k_wl   = (const float*)d_in[10];
    const float* k_bl   = (const float*)d_in[11];
    const float* k_wr   = (const float*)d_in[12];
    const float* k_br   = (const float*)d_in[13];
    const float* v_w1   = (const float*)d_in[14];
    const float* v_b1   = (const float*)d_in[15];
    const float* v_wl   = (const float*)d_in[16];
    const float* v_bl   = (const float*)d_in[17];
    const float* v_wr   = (const float*)d_in[18];
    const float* v_br   = (const float*)d_in[19];
    float* dout = (float*)d_out;

    cudaFuncSetAttribute(conv_mma_kernel, cudaFuncAttributeMaxDynamicSharedMemorySize, SMEM_BYTES);

    presplit_kernel<<<512, 256>>>(k_wl, k_wr, v_wl, v_wr, k_bl, k_br, v_bl, v_br, k_w1, v_w1);
    qinit_kernel<<<(NN * 64 + 255) / 256, 256>>>(f, q_w, q_b, dout);
    conv_mma_kernel<<<EE / TM, THREADS, SMEM_BYTES>>>(
        basis1, basis2, ef, f, src, dst, k_b1, v_b1, dout, 0);   // K: scores + den
    conv_mma_kernel<<<EE / TM, THREADS, SMEM_BYTES>>>(
        basis1, basis2, ef, f, src, dst, k_b1, v_b1, dout, 1);   // V: fused scatter
}

// round 14
// speedup vs baseline: 4.7494x; 1.2254x over previous
#include <cuda_runtime.h>
#include <cuda_fp16.h>
#include <math_constants.h>
#include <cstdint>

#define NN 10000
#define EE 160000
#define EDIM 32
#define HID 128
#define NH 4
#define TM 64             // edges per block
#define THREADS 256

// ---------------- scratch (static device arrays; no allocation) ----------------
__device__ __half g_wthi[2 * 512 * 128];  // [conv][n][k] fp16-hi of [wl|wr]^T
__device__ __half g_w1hi[2 * 128 * 32];   // [conv][j][i] fp16-hi of w1^T
__device__ float g_bias[2][512];          // [conv][bl(256)|br(256)]
__device__ float g_q[NN * 64];
__device__ float g_ex[EE * NH];
__device__ float g_den[NN * NH];

__device__ __forceinline__ uint32_t smem_to_u32(const void* p) {
    uint32_t a;
    asm("{ .reg .u64 t; cvta.to.shared.u64 t, %1; cvt.u32.u64 %0, t; }" : "=r"(a) : "l"(p));
    return a;
}
__device__ __forceinline__ void ldsm4(uint32_t a, uint32_t* r) {
    asm volatile("ldmatrix.sync.aligned.m8n8.x4.shared.b16 {%0,%1,%2,%3}, [%4];"
                 : "=r"(r[0]), "=r"(r[1]), "=r"(r[2]), "=r"(r[3]) : "r"(a));
}
__device__ __forceinline__ void mma16816(float* c, const uint32_t* a, const uint32_t* b) {
    asm volatile("mma.sync.aligned.m16n8k16.row.col.f32.f16.f16.f32 "
                 "{%0,%1,%2,%3}, {%4,%5,%6,%7}, {%8,%9}, {%0,%1,%2,%3};"
                 : "+f"(c[0]), "+f"(c[1]), "+f"(c[2]), "+f"(c[3])
                 : "r"(a[0]), "r"(a[1]), "r"(a[2]), "r"(a[3]), "r"(b[0]), "r"(b[1]));
}
__device__ __forceinline__ void cp16(uint32_t dst, const void* src) {
    asm volatile("cp.async.cg.shared.global [%0], [%1], 16;" :: "r"(dst), "l"(src) : "memory");
}

// ---------------- kernel 0: pre-convert weights (fp16, transposed) ----------------
__global__ void presplit_kernel(const float* __restrict__ kwl, const float* __restrict__ kwr,
                                const float* __restrict__ vwl, const float* __restrict__ vwr,
                                const float* __restrict__ kbl, const float* __restrict__ kbr,
                                const float* __restrict__ vbl, const float* __restrict__ vbr,
                                const float* __restrict__ kw1, const float* __restrict__ vw1) {
    int idx = blockIdx.x * blockDim.x + threadIdx.x;   // 131072
    if (idx < 2 * 512 * 128) {
        int conv = idx >> 16;
        int rem = idx & 65535;
        int n = rem >> 7, k = rem & 127;
        const float* w = conv ? (n < 256 ? vwl : vwr) : (n < 256 ? kwl : kwr);
        g_wthi[idx] = __float2half_rn(w[k * 256 + (n & 255)]);
    }
    if (idx < 2 * 128 * 32) {                          // w1^T (hi only)
        int conv = idx >> 12;
        int rem = idx & 4095;
        int j = rem >> 5, i = rem & 31;
        g_w1hi[idx] = __float2half_rn((conv ? vw1 : kw1)[i * 128 + j]);
    }
    if (idx < 1024) {
        int conv = idx >> 9, j = idx & 511;
        const float* s = conv ? (j < 256 ? vbl : vbr) : (j < 256 ? kbl : kbr);
        g_bias[conv][j] = s[j & 255];
    }
}

// ---------------- kernel 1: Q equivariant linear + init ----------------
__global__ void qinit_kernel(const float* __restrict__ f,
                             const float* __restrict__ qw,
                             const float* __restrict__ qb,
                             float* __restrict__ dout) {
    int p = blockIdx.x * blockDim.x + threadIdx.x;
    if (p < NN * 64) {
        int n = p >> 6, j = p & 63;
        int o = j >> 2, d = j & 3;
        int l = (d == 0) ? 0 : 1;
        float acc = (d == 0) ? qb[o] : 0.f;
        const float* wrow = qw + (l * 16 + o) * 16;
        const float* frow = f + n * 64 + d;
#pragma unroll
        for (int m = 0; m < 16; m++) acc += wrow[m] * frow[m * 4];
        g_q[p] = acc;
        dout[p] = 0.f;
    }
    if (p < NN * NH) g_den[p] = 0.f;
}

// ---------------- kernel 2: mma.sync fused conv (TM=64, occ 2) ----------------
// smem byte offsets
#define OFF_A    0u         // 16384: 64e x 128k fp16 (256B rows, swizzled)
#define OFF_W    16384u     // 65536: one W half (256 n-rows x 256B)
#define OFF_T    81920u     // 64*33*4 = 8448 (t; aliased as t2)
#define OFF_RT   90368u     // 64*8*4 = 2048 (reused as dn[] in V final)
#define OFF_BIAS 92416u     // 512*4 (reused as alpha in V final)
#define OFF_EF   94464u     // 8192: 64e x 128B (fp16 ef rows, swizzled)
#define OFF_W1T  102656u    // 8192: w1t hi
#define SMEM_BYTES 110848u

__device__ __forceinline__ void load_whalf(uint32_t smem_base, int conv, int nbase, int tid) {
#pragma unroll
    for (int ii = 0; ii < 16; ii++) {
        int g = ii * THREADS + tid;             // 0..4095 16B-chunks (256 rows x 16)
        int n = g >> 4, q = g & 15;
        const __half* src = g_wthi + conv * 65536 + (nbase + n) * 128 + q * 8;
        uint32_t dst = smem_base + OFF_W + (uint32_t)(n * 256 + ((q ^ (n & 7)) << 4));
        cp16(dst, src);
    }
    asm volatile("cp.async.commit_group;" ::: "memory");
}

__global__ void __launch_bounds__(THREADS, 2)
conv_mma_kernel(const float* __restrict__ basis1, const float* __restrict__ basis2,
                const float* __restrict__ ef, const float* __restrict__ f,
                const int* __restrict__ src, const int* __restrict__ dst,
                const float* __restrict__ k_b1, const float* __restrict__ v_b1,
                float* __restrict__ dout, int conv) {
    extern __shared__ char sm[];
    const uint32_t smem_base = smem_to_u32(sm);
    const int tid = threadIdx.x;
    const int lane = tid & 31, wid = tid >> 5;
    const int l4 = lane & 3;
    const int ng = wid;                         // 0..7: n base = ng*32 (all warps share e 0..63)
    const int e0 = blockIdx.x * TM;

    float* sh_t   = (float*)(sm + OFF_T);       // later aliased as t2
    float* sh_rt  = (float*)(sm + OFF_RT);
    float* sh_bias= (float*)(sm + OFF_BIAS);

    const int a_row_off = ((lane >> 3) & 1) * 8 + (lane & 7);
    const int a_ksel = (lane >> 4) & 1;
    const int b_n_off = ((lane >> 4) & 1) * 8 + (lane & 7);
    const int b_ksel = (lane >> 3) & 1;

    // ---- prefetch: w1t hi (group0), right W half (group1) ----
#pragma unroll
    for (int r = 0; r < 2; r++) {
        int g = r * THREADS + tid;              // 512 chunks (128 rows x 4)
        int n = g >> 2, q = g & 3;
        const __half* srcp = g_w1hi + conv * 4096 + n * 32 + q * 8;
        uint32_t dstp = smem_base + OFF_W1T + (uint32_t)(n * 64 + ((q ^ (n & 3)) << 4));
        cp16(dstp, srcp);
    }
    asm volatile("cp.async.commit_group;" ::: "memory");
    load_whalf(smem_base, conv, 256, tid);

    // ---- stage ef (fp32 -> fp16 tile), bias; compute t ----
#pragma unroll
    for (int r = 0; r < 2; r++) {
        int idx = r * THREADS + tid;            // 512 float4s (64e x 8)
        int e = idx >> 3, i0 = (idx & 7) * 4;
        float4 v = ((const float4*)(ef + (size_t)e0 * EDIM))[idx];
        __half2 h01 = __floats2half2_rn(v.x, v.y);
        __half2 h23 = __floats2half2_rn(v.z, v.w);
        int q = i0 >> 3;
        uint32_t base = (uint32_t)(e * 128 + ((q ^ (e & 7)) << 4) + (i0 & 7) * 2);
        *(uint32_t*)(sm + OFF_EF + base)     = *reinterpret_cast<uint32_t*>(&h01);
        *(uint32_t*)(sm + OFF_EF + base + 4) = *reinterpret_cast<uint32_t*>(&h23);
    }
    sh_bias[tid] = g_bias[conv][tid];
    sh_bias[256 + tid] = g_bias[conv][256 + tid];
#pragma unroll
    for (int r = 0; r < 8; r++) {
        int p = r * THREADS + tid;              // 2048: t[e][c]
        int e = p >> 5, c = p & 31;
        int m = c >> 1, l = c & 1;
        int sn = __ldg(&src[e0 + e]);
        float4 fv = *reinterpret_cast<const float4*>(f + (size_t)sn * 64 + m * 4);
        float4 b1a = *reinterpret_cast<const float4*>(basis1 + (size_t)(e0 + e) * 8);
        float4 b1b = *reinterpret_cast<const float4*>(basis1 + (size_t)(e0 + e) * 8 + 4);
        float a;
        if (l == 0)
            a = fv.x * b1a.x + fv.y * b1a.z + fv.z * b1b.x + fv.w * b1b.z;
        else
            a = fv.x * b1a.y + fv.y * b1a.w + fv.z * b1b.y + fv.w * b1b.w;
        sh_t[e * 33 + c] = a;
    }
    asm volatile("cp.async.wait_group 1;" ::: "memory");   // w1t resident
    __syncthreads();                                       // ef/t visible

    // ---- h-phase on tensor cores: h = gelu(ef @ w1hi + b1) -> fp16 A tile ----
    {
        const float* hbv = conv ? v_b1 : k_b1;
        const int wj = wid * 16;                // j base 0..112
        float bj[2][2];
#pragma unroll
        for (int nt = 0; nt < 2; nt++) {
            int j0 = wj + nt * 8 + 2 * l4;
            bj[nt][0] = __ldg(&hbv[j0]);
            bj[nt][1] = __ldg(&hbv[j0 + 1]);
        }
        uint32_t Bh[2][4];
#pragma unroll
        for (int kc = 0; kc < 2; kc++) {
            int n = wj + b_n_off;
            int c = kc * 2 + b_ksel;
            uint32_t bd = smem_base + OFF_W1T + (uint32_t)(n * 64 + ((c ^ (n & 3)) << 4));
            ldsm4(bd, Bh[kc]);
        }
#pragma unroll
        for (int mt = 0; mt < 4; mt++) {
            float hacc[2][4];
#pragma unroll
            for (int nt = 0; nt < 2; nt++)
#pragma unroll
                for (int u = 0; u < 4; u++) hacc[nt][u] = 0.f;
#pragma unroll
            for (int kc = 0; kc < 2; kc++) {
                int arow = mt * 16 + a_row_off;
                int c = kc * 2 + a_ksel;
                uint32_t ad = smem_base + OFF_EF + (uint32_t)(arow * 128 + ((c ^ (arow & 7)) << 4));
                uint32_t Ah[4];
                ldsm4(ad, Ah);
#pragma unroll
                for (int nt = 0; nt < 2; nt++)
                    mma16816(hacc[nt], Ah, &Bh[kc][nt * 2]);
            }
#pragma unroll
            for (int nt = 0; nt < 2; nt++) {
                int j0 = wj + nt * 8 + 2 * l4;
                int jc = j0 >> 3;
#pragma unroll
                for (int hrow = 0; hrow < 2; hrow++) {
                    int e = mt * 16 + hrow * 8 + (lane >> 2);
                    float v0 = hacc[nt][hrow * 2]     + bj[nt][0];
                    float v1 = hacc[nt][hrow * 2 + 1] + bj[nt][1];
                    v0 = v0 * normcdff(v0);
                    v1 = v1 * normcdff(v1);
                    __half2 hp = __floats2half2_rn(v0, v1);
                    uint32_t addr = (uint32_t)(e * 256 + ((jc ^ (e & 7)) << 4) + (j0 & 7) * 2);
                    *(uint32_t*)(sm + OFF_A + addr) = *reinterpret_cast<uint32_t*>(&hp);
                }
            }
        }
    }
    asm volatile("cp.async.wait_group 0;" ::: "memory");   // right W half resident
    __syncthreads();                                       // A tile visible
    float* sh_t2 = sh_t;

    // ================= PASS R (W rows 256..511, buffer rows 0..255) =================
    {
        float acc[4][4][4];
#pragma unroll
        for (int mt = 0; mt < 4; mt++)
#pragma unroll
            for (int nt = 0; nt < 4; nt++)
#pragma unroll
                for (int u = 0; u < 4; u++) acc[mt][nt][u] = 0.f;
#pragma unroll
        for (int ks = 0; ks < 8; ks++) {
            uint32_t A[4][4];
#pragma unroll
            for (int mt = 0; mt < 4; mt++) {
                int arow = mt * 16 + a_row_off;
                int kc = ks * 2 + a_ksel;
                ldsm4(smem_base + OFF_A + (uint32_t)(arow * 256 + ((kc ^ (arow & 7)) << 4)), A[mt]);
            }
#pragma unroll
            for (int g2 = 0; g2 < 2; g2++) {
                int n = ng * 32 + g2 * 16 + b_n_off;     // buffer-local row
                int kc = ks * 2 + b_ksel;
                uint32_t Bhi[4];
                ldsm4(smem_base + OFF_W + (uint32_t)(n * 256 + ((kc ^ (n & 7)) << 4)), Bhi);
#pragma unroll
                for (int mt = 0; mt < 4; mt++) {
                    mma16816(acc[mt][g2 * 2],     A[mt], &Bhi[0]);
                    mma16816(acc[mt][g2 * 2 + 1], A[mt], &Bhi[2]);
                }
            }
        }
        __syncthreads();                        // all warps done reading right W
        load_whalf(smem_base, conv, 0, tid);    // prefetch left half (hidden by co-block)

        // right epilogue: rt[e][ng] (unique writer per warp — no atomics)
#pragma unroll
        for (int mt = 0; mt < 4; mt++)
#pragma unroll
            for (int h2 = 0; h2 < 2; h2++) {
                int e = mt * 16 + h2 * 8 + (lane >> 2);
                float s = 0.f;
#pragma unroll
                for (int nt = 0; nt < 4; nt++) {
                    int nc = nt * 8 + 2 * l4;
                    int o = 256 + ng * 32 + nc;
                    s += (acc[mt][nt][h2 * 2] + sh_bias[o]) * sh_t[e * 33 + nc]
                       + (acc[mt][nt][h2 * 2 + 1] + sh_bias[o + 1]) * sh_t[e * 33 + nc + 1];
                }
                s += __shfl_xor_sync(0xFFFFFFFFu, s, 1);
                s += __shfl_xor_sync(0xFFFFFFFFu, s, 2);
                if (l4 == 0) sh_rt[e * 8 + ng] = s;
            }
    }
    asm volatile("cp.async.wait_group 0;" ::: "memory");   // left W half resident
    __syncthreads();                                       // rt visible

    // ================= PASS L (W rows 0..255) =================
    {
        float acc[4][4][4];
#pragma unroll
        for (int mt = 0; mt < 4; mt++)
#pragma unroll
            for (int nt = 0; nt < 4; nt++)
#pragma unroll
                for (int u = 0; u < 4; u++) acc[mt][nt][u] = 0.f;
#pragma unroll
        for (int ks = 0; ks < 8; ks++) {
            uint32_t A[4][4];
#pragma unroll
            for (int mt = 0; mt < 4; mt++) {
                int arow = mt * 16 + a_row_off;
                int kc = ks * 2 + a_ksel;
                ldsm4(smem_base + OFF_A + (uint32_t)(arow * 256 + ((kc ^ (arow & 7)) << 4)), A[mt]);
            }
#pragma unroll
            for (int g2 = 0; g2 < 2; g2++) {
                int n = ng * 32 + g2 * 16 + b_n_off;
                int kc = ks * 2 + b_ksel;
                uint32_t Bhi[4];
                ldsm4(smem_base + OFF_W + (uint32_t)(n * 256 + ((kc ^ (n & 7)) << 4)), Bhi);
#pragma unroll
                for (int mt = 0; mt < 4; mt++) {
                    mma16816(acc[mt][g2 * 2],     A[mt], &Bhi[0]);
                    mma16816(acc[mt][g2 * 2 + 1], A[mt], &Bhi[2]);
                }
            }
        }
        // left epilogue: t2[e][ng*4+nt]
#pragma unroll
        for (int mt = 0; mt < 4; mt++)
#pragma unroll
            for (int h2 = 0; h2 < 2; h2++) {
                int e = mt * 16 + h2 * 8 + (lane >> 2);
                float r0 = sh_rt[e * 8 + 2 * l4];
                float r1 = sh_rt[e * 8 + 2 * l4 + 1];
#pragma unroll
                for (int nt = 0; nt < 4; nt++) {
                    int o = ng * 32 + nt * 8 + 2 * l4;
                    float s = (acc[mt][nt][h2 * 2] + sh_bias[o]) * r0
                            + (acc[mt][nt][h2 * 2 + 1] + sh_bias[o + 1]) * r1;
                    s += __shfl_xor_sync(0xFFFFFFFFu, s, 1);
                    s += __shfl_xor_sync(0xFFFFFFFFu, s, 2);
                    if (l4 == 0)
                        sh_t2[e * 33 + ng * 4 + nt] = s;
                }
            }
    }
    __syncthreads();

    // ---- final phase ----
    if (conv == 0) {
        // K: scores -> exp (no max pass; scores are O(1)) -> segment denominator
        int e = tid >> 2, hh = tid & 3;              // 256 = 64*4
        int dn = __ldg(&dst[e0 + e]);
        const float* qr = g_q + dn * 64 + hh * 16;
        float s = 0.f;
#pragma unroll
        for (int m = hh * 4; m < hh * 4 + 4; m++) {
            float ta = sh_t2[e * 33 + 2 * m];
            float tb = sh_t2[e * 33 + 2 * m + 1];
#pragma unroll
            for (int d = 0; d < 4; d++) {
                float kv = ta * basis2[(size_t)(e0 + e) * 8 + d]
                         + tb * basis2[(size_t)(e0 + e) * 8 + 4 + d];
                s += qr[(m - hh * 4) * 4 + d] * kv;
            }
        }
        float ex = expf(s * 0.25f);
        g_ex[(size_t)(e0 + e) * NH + hh] = ex;
        atomicAdd(&g_den[dn * NH + hh], ex);
    } else {
        // V: fused weighted scatter — alpha*v straight to dout via red.v4
        float* sh_alpha = sh_bias;                   // 256 floats (bias dead)
        int*   sh_dn    = (int*)(sm + OFF_RT);       // 64 ints (rt dead)
        {
            int e = tid >> 2, hh = tid & 3;
            int dn = __ldg(&dst[e0 + e]);
            if (hh == 0) sh_dn[e] = dn;
            float den = fmaxf(g_den[dn * NH + hh], 1e-9f);
            sh_alpha[tid] = g_ex[(size_t)(e0 + e) * NH + hh] / den;
        }
        __syncthreads();
#pragma unroll
        for (int r = 0; r < 4; r++) {
            int p = r * THREADS + tid;               // 1024 float4 groups
            int e = p >> 4, m = p & 15;
            int hh = m >> 2;
            float4 b2a = *reinterpret_cast<const float4*>(basis2 + (size_t)(e0 + e) * 8);
            float4 b2b = *reinterpret_cast<const float4*>(basis2 + (size_t)(e0 + e) * 8 + 4);
            float ta = sh_t2[e * 33 + 2 * m];
            float tb = sh_t2[e * 33 + 2 * m + 1];
            float al = sh_alpha[e * 4 + hh];
            float* op = dout + (size_t)sh_dn[e] * 64 + m * 4;
            asm volatile("red.global.add.v4.f32 [%0], {%1, %2, %3, %4};"
                         :: "l"(op),
                            "f"(al * (ta * b2a.x + tb * b2b.x)),
                            "f"(al * (ta * b2a.y + tb * b2b.y)),
                            "f"(al * (ta * b2a.z + tb * b2b.z)),
                            "f"(al * (ta * b2a.w + tb * b2b.w))
                         : "memory");
        }
    }
}

// ---------------- launch ----------------
extern "C" void kernel_launch(void* const* d_in, const int* in_sizes, int n_in,
                              void* d_out, int out_size) {
    const float* basis1 = (const float*)d_in[0];
    const float* basis2 = (const float*)d_in[1];
    const float* ef     = (const float*)d_in[2];
    const float* f      = (const float*)d_in[3];
    const int*   src    = (const int*)d_in[4];
    const int*   dst    = (const int*)d_in[5];
    const float* q_w    = (const float*)d_in[6];
    const float* q_b    = (const float*)d_in[7];
    const float* k_w1   = (const float*)d_in[8];
    const float* k_b1   = (const float*)d_in[9];
    const float* k_wl   = (const float*)d_in[10];
    const float* k_bl   = (const float*)d_in[11];
    const float* k_wr   = (const float*)d_in[12];
    const float* k_br   = (const float*)d_in[13];
    const float* v_w1   = (const float*)d_in[14];
    const float* v_b1   = (const float*)d_in[15];
    const float* v_wl   = (const float*)d_in[16];
    const float* v_bl   = (const float*)d_in[17];
    const float* v_wr   = (const float*)d_in[18];
    const float* v_br   = (const float*)d_in[19];
    float* dout = (float*)d_out;

    cudaFuncSetAttribute(conv_mma_kernel, cudaFuncAttributeMaxDynamicSharedMemorySize, SMEM_BYTES);

    presplit_kernel<<<512, 256>>>(k_wl, k_wr, v_wl, v_wr, k_bl, k_br, v_bl, v_br, k_w1, v_w1);
    qinit_kernel<<<(NN * 64 + 255) / 256, 256>>>(f, q_w, q_b, dout);
    conv_mma_kernel<<<EE / TM, THREADS, SMEM_BYTES>>>(
        basis1, basis2, ef, f, src, dst, k_b1, v_b1, dout, 0);   // K: scores + den
    conv_mma_kernel<<<EE / TM, THREADS, SMEM_BYTES>>>(
        basis1, basis2, ef, f, src, dst, k_b1, v_b1, dout, 1);   // V: fused scatter
}